// round 1
// baseline (speedup 1.0000x reference)
#include <cuda_runtime.h>
#include <cuda_bf16.h>
#include <cstdint>

#define BB 2
#define SS 2048
#define DD 1024
#define HH 16
#define HD 64

// Scratch (no allocation allowed) — [B,H,S,HD] for q/k/v, [B,S,D] for ctx
__device__ float g_q[BB*HH*SS*HD];
__device__ float g_k[BB*HH*SS*HD];
__device__ float g_v[BB*HH*SS*HD];
__device__ float g_ctx[BB*SS*DD];

// ---------------------------------------------------------------------------
// Tiled fp32 GEMM: Y[M,N] = X[M,K] @ W[K,N]
// MODE 0: write to head-major layout [B,H,S,HD] (for Q/K/V projections)
// MODE 1: write plain [M,N] + bias     (for output projection)
// M = B*S = 4096, N = K = D = 1024. All divisible by tiles — no bounds checks.
// ---------------------------------------------------------------------------
template<int MODE>
__global__ __launch_bounds__(256)
void gemm_kernel(const float* __restrict__ X, const float* __restrict__ W,
                 float* __restrict__ Y, const float* __restrict__ bias)
{
    const int Kd = DD, Nd = DD;
    __shared__ float sX[64][16];
    __shared__ float sW[16][65];

    const int tid = threadIdx.x;
    const int tx  = tid & 15;        // 0..15 -> 4 output cols each
    const int ty  = tid >> 4;        // 0..15 -> 4 output rows each
    const int m0  = blockIdx.y * 64;
    const int n0  = blockIdx.x * 64;

    float acc[4][4] = {};

    for (int kt = 0; kt < Kd; kt += 16) {
        // load X tile 64x16 (coalesced 16-float rows)
        #pragma unroll
        for (int idx = tid; idx < 64*16; idx += 256) {
            int m = idx >> 4, k = idx & 15;
            sX[m][k] = X[(size_t)(m0 + m) * Kd + kt + k];
        }
        // load W tile 16x64 (coalesced 64-float rows)
        #pragma unroll
        for (int idx = tid; idx < 16*64; idx += 256) {
            int k = idx >> 6, n = idx & 63;
            sW[k][n] = W[(size_t)(kt + k) * Nd + n0 + n];
        }
        __syncthreads();

        #pragma unroll
        for (int k = 0; k < 16; ++k) {
            float a[4], b[4];
            #pragma unroll
            for (int i = 0; i < 4; ++i) a[i] = sX[ty*4 + i][k];
            #pragma unroll
            for (int j = 0; j < 4; ++j) b[j] = sW[k][tx*4 + j];
            #pragma unroll
            for (int i = 0; i < 4; ++i)
                #pragma unroll
                for (int j = 0; j < 4; ++j)
                    acc[i][j] += a[i] * b[j];
        }
        __syncthreads();
    }

    // epilogue
    #pragma unroll
    for (int i = 0; i < 4; ++i) {
        int m = m0 + ty*4 + i;
        #pragma unroll
        for (int j = 0; j < 4; ++j) {
            int n = n0 + tx*4 + j;
            if (MODE == 0) {
                int b = m / SS, s = m % SS;
                int h = n / HD, hd = n % HD;
                Y[(((size_t)b*HH + h)*SS + s)*HD + hd] = acc[i][j];
            } else {
                Y[(size_t)m * DD + n] = acc[i][j] + bias[n];
            }
        }
    }
}

// ---------------------------------------------------------------------------
// Flash attention (causal, online softmax), fp32.
// grid = (S/64, B*H); block = 256 threads; 64 q-rows x 64 k-cols tiles; HD=64.
// Each thread owns a 4x4 microtile of the 64x64 ctx output.
// ---------------------------------------------------------------------------
#define LD 65   // smem row stride (bank-conflict padding)

__global__ __launch_bounds__(256)
void attn_kernel(const float* __restrict__ Q, const float* __restrict__ Kp,
                 const float* __restrict__ Vp, float* __restrict__ ctx)
{
    extern __shared__ float sm[];
    float* sQ = sm;               // 64*LD
    float* sK = sQ + 64*LD;
    float* sV = sK + 64*LD;
    float* sS = sV + 64*LD;
    float* sM = sS + 64*LD;       // 64
    float* sL = sM + 64;          // 64
    float* sA = sM + 128;         // 64

    const int qi  = blockIdx.x;   // q tile (0..31)
    const int bh  = blockIdx.y;   // b*H + h (0..31)
    const int tid = threadIdx.x;
    const int tx  = tid & 15;
    const int ty  = tid >> 4;

    const float* Qb = Q  + (size_t)bh * SS * HD;
    const float* Kb = Kp + (size_t)bh * SS * HD;
    const float* Vb = Vp + (size_t)bh * SS * HD;

    // load Q tile once
    #pragma unroll
    for (int idx = tid; idx < 64*64; idx += 256) {
        int m = idx >> 6, d = idx & 63;
        sQ[m*LD + d] = Qb[(size_t)(qi*64 + m)*HD + d];
    }
    if (tid < 64) { sM[tid] = -1e30f; sL[tid] = 0.0f; }

    float acc[4][4] = {};
    __syncthreads();

    const float scale = 0.125f;   // 1/sqrt(64)

    for (int kt = 0; kt <= qi; ++kt) {
        // load K,V tiles
        #pragma unroll
        for (int idx = tid; idx < 64*64; idx += 256) {
            int n = idx >> 6, d = idx & 63;
            size_t g = (size_t)(kt*64 + n)*HD + d;
            sK[n*LD + d] = Kb[g];
            sV[n*LD + d] = Vb[g];
        }
        __syncthreads();

        // scores: S[m][n] = scale * sum_d Q[m][d] K[n][d]
        float s[4][4] = {};
        #pragma unroll 8
        for (int d = 0; d < 64; ++d) {
            float a[4], b[4];
            #pragma unroll
            for (int i = 0; i < 4; ++i) a[i] = sQ[(ty*4 + i)*LD + d];
            #pragma unroll
            for (int j = 0; j < 4; ++j) b[j] = sK[(tx*4 + j)*LD + d];
            #pragma unroll
            for (int i = 0; i < 4; ++i)
                #pragma unroll
                for (int j = 0; j < 4; ++j)
                    s[i][j] += a[i] * b[j];
        }
        const bool diag = (kt == qi);
        #pragma unroll
        for (int i = 0; i < 4; ++i)
            #pragma unroll
            for (int j = 0; j < 4; ++j) {
                float v = s[i][j] * scale;
                if (diag && (tx*4 + j) > (ty*4 + i)) v = -1e30f;
                sS[(ty*4 + i)*LD + tx*4 + j] = v;
            }
        __syncthreads();

        // per-row online softmax stats (one thread per row)
        if (tid < 64) {
            int r = tid;
            float mx = sM[r];
            float tmax = -1e30f;
            #pragma unroll 8
            for (int n = 0; n < 64; ++n) tmax = fmaxf(tmax, sS[r*LD + n]);
            float nm = fmaxf(mx, tmax);
            float alpha = __expf(mx - nm);
            float rs = 0.0f;
            #pragma unroll 8
            for (int n = 0; n < 64; ++n) {
                float p = __expf(sS[r*LD + n] - nm);
                sS[r*LD + n] = p;
                rs += p;
            }
            sL[r] = sL[r]*alpha + rs;
            sM[r] = nm;
            sA[r] = alpha;
        }
        __syncthreads();

        // acc = acc*alpha + P @ V
        float al[4];
        #pragma unroll
        for (int i = 0; i < 4; ++i) al[i] = sA[ty*4 + i];
        #pragma unroll
        for (int i = 0; i < 4; ++i)
            #pragma unroll
            for (int j = 0; j < 4; ++j)
                acc[i][j] *= al[i];

        #pragma unroll 8
        for (int n = 0; n < 64; ++n) {
            float p[4], v[4];
            #pragma unroll
            for (int i = 0; i < 4; ++i) p[i] = sS[(ty*4 + i)*LD + n];
            #pragma unroll
            for (int j = 0; j < 4; ++j) v[j] = sV[n*LD + tx*4 + j];
            #pragma unroll
            for (int i = 0; i < 4; ++i)
                #pragma unroll
                for (int j = 0; j < 4; ++j)
                    acc[i][j] += p[i] * v[j];
        }
        __syncthreads();
    }

    // write ctx in [B,S,D] layout
    const int b = bh / HH, h = bh % HH;
    #pragma unroll
    for (int i = 0; i < 4; ++i) {
        int m = qi*64 + ty*4 + i;
        float inv = 1.0f / sL[ty*4 + i];
        #pragma unroll
        for (int j = 0; j < 4; ++j) {
            int hd = tx*4 + j;
            ctx[((size_t)b*SS + m)*DD + h*HD + hd] = acc[i][j] * inv;
        }
    }
}

// ---------------------------------------------------------------------------

extern "C" void kernel_launch(void* const* d_in, const int* in_sizes, int n_in,
                              void* d_out, int out_size)
{
    const float* x  = (const float*)d_in[0];
    const float* Wq = (const float*)d_in[1];
    const float* Wk = (const float*)d_in[2];
    const float* Wv = (const float*)d_in[3];
    const float* Wo = (const float*)d_in[4];
    const float* bo = (const float*)d_in[5];
    float* out = (float*)d_out;

    float *q, *k, *v, *ctx;
    cudaGetSymbolAddress((void**)&q,   g_q);
    cudaGetSymbolAddress((void**)&k,   g_k);
    cudaGetSymbolAddress((void**)&v,   g_v);
    cudaGetSymbolAddress((void**)&ctx, g_ctx);

    const int attn_smem = (4*64*LD + 192) * (int)sizeof(float);  // ~67 KB
    cudaFuncSetAttribute(attn_kernel, cudaFuncAttributeMaxDynamicSharedMemorySize,
                         attn_smem);

    dim3 gblk(256);
    dim3 ggrid(DD/64, (BB*SS)/64);   // 16 x 64

    gemm_kernel<0><<<ggrid, gblk>>>(x, Wq, q, nullptr);
    gemm_kernel<0><<<ggrid, gblk>>>(x, Wk, k, nullptr);
    gemm_kernel<0><<<ggrid, gblk>>>(x, Wv, v, nullptr);

    dim3 agrid(SS/64, BB*HH);        // 32 x 32
    attn_kernel<<<agrid, 256, attn_smem>>>(q, k, v, ctx);

    gemm_kernel<1><<<ggrid, gblk>>>(ctx, Wo, out, bo);
}

// round 3
// speedup vs baseline: 1.5723x; 1.5723x over previous
#include <cuda_runtime.h>
#include <cuda_bf16.h>
#include <cstdint>

#define BB 2
#define SS 2048
#define DD 1024
#define HH 16
#define HD 64
#define MM (BB*SS)     // 4096

// ---------------- device scratch (no allocation allowed) -------------------
__device__ float g_q[BB*HH*SS*HD];
__device__ float g_k[BB*HH*SS*HD];
__device__ float g_v[BB*HH*SS*HD];
__device__ float g_ctx[BB*SS*DD];
__device__ __nv_bfloat16 g_ahi[MM*DD];          // split of X or ctx
__device__ __nv_bfloat16 g_alo[MM*DD];
__device__ __nv_bfloat16 g_wthi[4][DD*DD];      // W^T splits (n-major, k contiguous)
__device__ __nv_bfloat16 g_wtlo[4][DD*DD];

// ---------------- prepass: fp32 -> bf16 hi/lo split -------------------------
__global__ __launch_bounds__(256)
void split_kernel(const float4* __restrict__ X, __nv_bfloat16* __restrict__ Hi,
                  __nv_bfloat16* __restrict__ Lo, int n4)
{
    union U { __nv_bfloat16 b[4]; uint64_t u; };
    for (int i = blockIdx.x * blockDim.x + threadIdx.x; i < n4;
         i += gridDim.x * blockDim.x) {
        float4 f = X[i];
        U h, l;
        float vf[4] = {f.x, f.y, f.z, f.w};
        #pragma unroll
        for (int j = 0; j < 4; ++j) {
            __nv_bfloat16 hb = __float2bfloat16(vf[j]);
            h.b[j] = hb;
            l.b[j] = __float2bfloat16(vf[j] - __bfloat162float(hb));
        }
        ((uint64_t*)Hi)[i] = h.u;
        ((uint64_t*)Lo)[i] = l.u;
    }
}

// ---------------- prepass: W[k][n] -> Wt[n][k] hi/lo split -------------------
__global__ __launch_bounds__(256)
void transpose_split_kernel(const float* __restrict__ W,
                            __nv_bfloat16* __restrict__ Th,
                            __nv_bfloat16* __restrict__ Tl)
{
    __shared__ float tile[32][33];
    int tx = threadIdx.x, ty = threadIdx.y;
    int x = blockIdx.x * 32 + tx;
    #pragma unroll
    for (int i = 0; i < 4; ++i) {
        int y = blockIdx.y * 32 + ty + i * 8;
        tile[ty + i * 8][tx] = W[(size_t)y * DD + x];
    }
    __syncthreads();
    int xo = blockIdx.y * 32 + tx;
    #pragma unroll
    for (int i = 0; i < 4; ++i) {
        int yo = blockIdx.x * 32 + ty + i * 8;
        float v = tile[tx][ty + i * 8];
        __nv_bfloat16 hb = __float2bfloat16(v);
        Th[(size_t)yo * DD + xo] = hb;
        Tl[(size_t)yo * DD + xo] = __float2bfloat16(v - __bfloat162float(hb));
    }
}

// ---------------- mma.sync helpers ------------------------------------------
__device__ __forceinline__ uint32_t smem_u32(const void* p) {
    uint32_t a;
    asm("{ .reg .u64 t; cvta.to.shared.u64 t, %1; cvt.u32.u64 %0, t; }"
        : "=r"(a) : "l"(p));
    return a;
}
__device__ __forceinline__ void ldmx4(uint32_t* r, uint32_t addr) {
    asm volatile("ldmatrix.sync.aligned.m8n8.x4.shared.b16 {%0,%1,%2,%3}, [%4];"
                 : "=r"(r[0]), "=r"(r[1]), "=r"(r[2]), "=r"(r[3]) : "r"(addr));
}
__device__ __forceinline__ void mma_bf16(float* c, const uint32_t* a,
                                         uint32_t b0, uint32_t b1) {
    asm volatile(
        "mma.sync.aligned.m16n8k16.row.col.f32.bf16.bf16.f32 "
        "{%0,%1,%2,%3}, {%4,%5,%6,%7}, {%8,%9}, {%0,%1,%2,%3};"
        : "+f"(c[0]), "+f"(c[1]), "+f"(c[2]), "+f"(c[3])
        : "r"(a[0]), "r"(a[1]), "r"(a[2]), "r"(a[3]), "r"(b0), "r"(b1));
}

// ---------------- HMMA GEMM -------------------------------------------------
// C[4096,1024] = Ahi@Bhi^T + Ahi@Blo^T + Alo@Bhi^T   (B stored [N][K])
// CTA 128x128, BK=32, 8 warps (4x2), warp tile 32x64. Double-buffered smem.
// MODE 0: write head-major [B,H,S,HD]. MODE 1: write [M,N]+bias.
#define AST 40                    // smem row stride in bf16 (80B)
#define NTILES 96                 // 3 segments * (1024/32)

template<int MODE>
__global__ __launch_bounds__(256, 2)
void mma_gemm(const __nv_bfloat16* __restrict__ Ahi, const __nv_bfloat16* __restrict__ Alo,
              const __nv_bfloat16* __restrict__ Bhi, const __nv_bfloat16* __restrict__ Blo,
              float* __restrict__ Y, const float* __restrict__ bias)
{
    __shared__ __nv_bfloat16 sA[2][128*AST];
    __shared__ __nv_bfloat16 sB[2][128*AST];

    const int tid  = threadIdx.x;
    const int wid  = tid >> 5;
    const int lane = tid & 31;
    const int m0 = blockIdx.y * 128;
    const int n0 = blockIdx.x * 128;
    const int wm0 = (wid & 3) * 32;
    const int wn0 = (wid >> 2) * 64;

    const uint64_t* As[3] = {(const uint64_t*)Ahi, (const uint64_t*)Ahi, (const uint64_t*)Alo};
    const uint64_t* Bs[3] = {(const uint64_t*)Bhi, (const uint64_t*)Blo, (const uint64_t*)Bhi};

    // per-thread gmem/smem copy mapping: 1024 u64 per operand tile, 4 per thread
    // idx = tid + i*256 ; row = idx>>3 ; c = idx&7  (u64 within 64B row-chunk)
    // smem bf16 offset = row*AST + c*4
    const int ldrow[4] = { (tid + 0*256) >> 3, (tid + 1*256) >> 3,
                           (tid + 2*256) >> 3, (tid + 3*256) >> 3 };
    const int ldc = tid & 7;

    // ldmatrix base addresses (bytes)
    const uint32_t baseA = smem_u32(&sA[0][0]);
    const uint32_t baseB = smem_u32(&sB[0][0]);
    const uint32_t bufStride = 128 * AST * 2;   // bytes per buffer
    uint32_t aoff[2], boff[4];
    #pragma unroll
    for (int mf = 0; mf < 2; ++mf)
        aoff[mf] = ((wm0 + mf*16 + (lane & 15)) * AST + (lane >> 4) * 8) * 2;
    #pragma unroll
    for (int np = 0; np < 4; ++np)
        boff[np] = ((wn0 + np*16 + ((lane >> 4) & 1) * 8 + (lane & 7)) * AST
                    + ((lane >> 3) & 1) * 8) * 2;

    float acc[2][8][4] = {};
    uint64_t ra[4], rb[4];

    auto ldg = [&](int t) {
        const int seg = t >> 5;
        const int kc  = (t & 31) * 8;          // u64 offset within 256-u64 row
        const uint64_t* Ag = As[seg];
        const uint64_t* Bg = Bs[seg];
        #pragma unroll
        for (int i = 0; i < 4; ++i) {
            ra[i] = Ag[(size_t)(m0 + ldrow[i]) * 256 + kc + ldc];
            rb[i] = Bg[(size_t)(n0 + ldrow[i]) * 256 + kc + ldc];
        }
    };
    auto sts = [&](int buf) {
        #pragma unroll
        for (int i = 0; i < 4; ++i) {
            *(uint64_t*)&sA[buf][ldrow[i]*AST + ldc*4] = ra[i];
            *(uint64_t*)&sB[buf][ldrow[i]*AST + ldc*4] = rb[i];
        }
    };
    auto compute = [&](int buf) {
        const uint32_t bA = baseA + buf * bufStride;
        const uint32_t bB = baseB + buf * bufStride;
        #pragma unroll
        for (int ks = 0; ks < 32; ks += 16) {
            uint32_t af[2][4], bf[4][4];
            #pragma unroll
            for (int mf = 0; mf < 2; ++mf) ldmx4(af[mf], bA + aoff[mf] + ks*2);
            #pragma unroll
            for (int np = 0; np < 4; ++np) ldmx4(bf[np], bB + boff[np] + ks*2);
            #pragma unroll
            for (int mf = 0; mf < 2; ++mf)
                #pragma unroll
                for (int np = 0; np < 4; ++np) {
                    mma_bf16(acc[mf][np*2+0], af[mf], bf[np][0], bf[np][1]);
                    mma_bf16(acc[mf][np*2+1], af[mf], bf[np][2], bf[np][3]);
                }
        }
    };

    ldg(0); sts(0);
    __syncthreads();
    for (int t = 0; t < NTILES; ++t) {
        const int buf = t & 1;
        if (t + 1 < NTILES) ldg(t + 1);
        compute(buf);
        if (t + 1 < NTILES) sts(buf ^ 1);
        __syncthreads();
    }

    // ---- epilogue ----
    const int qrow = lane >> 2;           // 0..7
    const int qcol = (lane & 3) * 2;
    #pragma unroll
    for (int mf = 0; mf < 2; ++mf) {
        #pragma unroll
        for (int nf = 0; nf < 8; ++nf) {
            const int n = n0 + wn0 + nf*8 + qcol;
            #pragma unroll
            for (int half = 0; half < 2; ++half) {
                const int m = m0 + wm0 + mf*16 + qrow + half*8;
                const float cx = acc[mf][nf][half*2 + 0];
                const float cy = acc[mf][nf][half*2 + 1];
                if (MODE == 0) {
                    const int b = m >> 11, s = m & (SS - 1);
                    const int h = n >> 6, hd = n & 63;
                    float2* dst = (float2*)(Y + ((((size_t)b*HH + h)*SS + s)*HD + hd));
                    *dst = make_float2(cx, cy);
                } else {
                    float2* dst = (float2*)(Y + (size_t)m * DD + n);
                    *dst = make_float2(cx + bias[n], cy + bias[n + 1]);
                }
            }
        }
    }
}

// ---------------- flash attention (fp32, unchanged) -------------------------
#define LD 65

__global__ __launch_bounds__(256)
void attn_kernel(const float* __restrict__ Q, const float* __restrict__ Kp,
                 const float* __restrict__ Vp, float* __restrict__ ctx)
{
    extern __shared__ float smf[];
    float* sQ = smf;
    float* sK = sQ + 64*LD;
    float* sV = sK + 64*LD;
    float* sS = sV + 64*LD;
    float* sM = sS + 64*LD;
    float* sL = sM + 64;
    float* sA = sM + 128;

    const int qi  = blockIdx.x;
    const int bh  = blockIdx.y;
    const int tid = threadIdx.x;
    const int tx  = tid & 15;
    const int ty  = tid >> 4;

    const float* Qb = Q  + (size_t)bh * SS * HD;
    const float* Kb = Kp + (size_t)bh * SS * HD;
    const float* Vb = Vp + (size_t)bh * SS * HD;

    #pragma unroll
    for (int idx = tid; idx < 64*64; idx += 256) {
        int m = idx >> 6, d = idx & 63;
        sQ[m*LD + d] = Qb[(size_t)(qi*64 + m)*HD + d];
    }
    if (tid < 64) { sM[tid] = -1e30f; sL[tid] = 0.0f; }

    float acc[4][4] = {};
    __syncthreads();

    const float scale = 0.125f;

    for (int kt = 0; kt <= qi; ++kt) {
        #pragma unroll
        for (int idx = tid; idx < 64*64; idx += 256) {
            int n = idx >> 6, d = idx & 63;
            size_t g = (size_t)(kt*64 + n)*HD + d;
            sK[n*LD + d] = Kb[g];
            sV[n*LD + d] = Vb[g];
        }
        __syncthreads();

        float s[4][4] = {};
        #pragma unroll 8
        for (int d = 0; d < 64; ++d) {
            float a[4], b[4];
            #pragma unroll
            for (int i = 0; i < 4; ++i) a[i] = sQ[(ty*4 + i)*LD + d];
            #pragma unroll
            for (int j = 0; j < 4; ++j) b[j] = sK[(tx*4 + j)*LD + d];
            #pragma unroll
            for (int i = 0; i < 4; ++i)
                #pragma unroll
                for (int j = 0; j < 4; ++j)
                    s[i][j] += a[i] * b[j];
        }
        const bool diag = (kt == qi);
        #pragma unroll
        for (int i = 0; i < 4; ++i)
            #pragma unroll
            for (int j = 0; j < 4; ++j) {
                float v = s[i][j] * scale;
                if (diag && (tx*4 + j) > (ty*4 + i)) v = -1e30f;
                sS[(ty*4 + i)*LD + tx*4 + j] = v;
            }
        __syncthreads();

        if (tid < 64) {
            int r = tid;
            float mx = sM[r];
            float tmax = -1e30f;
            #pragma unroll 8
            for (int n = 0; n < 64; ++n) tmax = fmaxf(tmax, sS[r*LD + n]);
            float nm = fmaxf(mx, tmax);
            float alpha = __expf(mx - nm);
            float rs = 0.0f;
            #pragma unroll 8
            for (int n = 0; n < 64; ++n) {
                float p = __expf(sS[r*LD + n] - nm);
                sS[r*LD + n] = p;
                rs += p;
            }
            sL[r] = sL[r]*alpha + rs;
            sM[r] = nm;
            sA[r] = alpha;
        }
        __syncthreads();

        float al[4];
        #pragma unroll
        for (int i = 0; i < 4; ++i) al[i] = sA[ty*4 + i];
        #pragma unroll
        for (int i = 0; i < 4; ++i)
            #pragma unroll
            for (int j = 0; j < 4; ++j)
                acc[i][j] *= al[i];

        #pragma unroll 8
        for (int n = 0; n < 64; ++n) {
            float p[4], v[4];
            #pragma unroll
            for (int i = 0; i < 4; ++i) p[i] = sS[(ty*4 + i)*LD + n];
            #pragma unroll
            for (int j = 0; j < 4; ++j) v[j] = sV[n*LD + tx*4 + j];
            #pragma unroll
            for (int i = 0; i < 4; ++i)
                #pragma unroll
                for (int j = 0; j < 4; ++j)
                    acc[i][j] += p[i] * v[j];
        }
        __syncthreads();
    }

    const int b = bh / HH, h = bh % HH;
    #pragma unroll
    for (int i = 0; i < 4; ++i) {
        int m = qi*64 + ty*4 + i;
        float inv = 1.0f / sL[ty*4 + i];
        #pragma unroll
        for (int j = 0; j < 4; ++j) {
            int hd = tx*4 + j;
            ctx[((size_t)b*SS + m)*DD + h*HD + hd] = acc[i][j] * inv;
        }
    }
}

// ---------------------------------------------------------------------------

extern "C" void kernel_launch(void* const* d_in, const int* in_sizes, int n_in,
                              void* d_out, int out_size)
{
    const float* x  = (const float*)d_in[0];
    const float* Wq = (const float*)d_in[1];
    const float* Wk = (const float*)d_in[2];
    const float* Wv = (const float*)d_in[3];
    const float* Wo = (const float*)d_in[4];
    const float* bo = (const float*)d_in[5];
    float* out = (float*)d_out;

    float *q, *k, *v, *ctx;
    __nv_bfloat16 *ahi, *alo, *wthi, *wtlo;
    cudaGetSymbolAddress((void**)&q,    g_q);
    cudaGetSymbolAddress((void**)&k,    g_k);
    cudaGetSymbolAddress((void**)&v,    g_v);
    cudaGetSymbolAddress((void**)&ctx,  g_ctx);
    cudaGetSymbolAddress((void**)&ahi,  g_ahi);
    cudaGetSymbolAddress((void**)&alo,  g_alo);
    cudaGetSymbolAddress((void**)&wthi, g_wthi);
    cudaGetSymbolAddress((void**)&wtlo, g_wtlo);

    const int attn_smem = (4*64*LD + 192) * (int)sizeof(float);
    cudaFuncSetAttribute(attn_kernel, cudaFuncAttributeMaxDynamicSharedMemorySize, attn_smem);

    // 1. split X into bf16 hi/lo
    split_kernel<<<1024, 256>>>((const float4*)x, ahi, alo, MM*DD/4);

    // 2. transpose+split weights
    const float* Ws[4] = {Wq, Wk, Wv, Wo};
    for (int i = 0; i < 4; ++i)
        transpose_split_kernel<<<dim3(32,32), dim3(32,8)>>>(
            Ws[i], wthi + (size_t)i*DD*DD, wtlo + (size_t)i*DD*DD);

    // 3. Q/K/V projections on tensor cores (HMMA)
    dim3 ggrid(DD/128, MM/128);   // 8 x 32
    mma_gemm<0><<<ggrid, 256>>>(ahi, alo, wthi + 0*(size_t)DD*DD, wtlo + 0*(size_t)DD*DD, q, nullptr);
    mma_gemm<0><<<ggrid, 256>>>(ahi, alo, wthi + 1*(size_t)DD*DD, wtlo + 1*(size_t)DD*DD, k, nullptr);
    mma_gemm<0><<<ggrid, 256>>>(ahi, alo, wthi + 2*(size_t)DD*DD, wtlo + 2*(size_t)DD*DD, v, nullptr);

    // 4. attention
    dim3 agrid(SS/64, BB*HH);
    attn_kernel<<<agrid, 256, attn_smem>>>(q, k, v, ctx);

    // 5. split ctx, output projection + bias
    split_kernel<<<1024, 256>>>((const float4*)ctx, ahi, alo, MM*DD/4);
    mma_gemm<1><<<ggrid, 256>>>(ahi, alo, wthi + 3*(size_t)DD*DD, wtlo + 3*(size_t)DD*DD, out, bo);
}

// round 5
// speedup vs baseline: 2.7931x; 1.7765x over previous
#include <cuda_runtime.h>
#include <cuda_bf16.h>
#include <cstdint>

#define BB 2
#define SS 2048
#define DD 1024
#define HH 16
#define HD 64
#define MM (BB*SS)     // 4096

// ---------------- device scratch (no allocation allowed) -------------------
__device__ float g_ctx[BB*SS*DD];
__device__ __nv_bfloat16 g_ahi[MM*DD];
__device__ __nv_bfloat16 g_alo[MM*DD];
__device__ __nv_bfloat16 g_wthi[4][DD*DD];
__device__ __nv_bfloat16 g_wtlo[4][DD*DD];
// head-major [B*H][S][HD] bf16 hi/lo
__device__ __nv_bfloat16 g_qh[BB*HH*SS*HD];
__device__ __nv_bfloat16 g_ql[BB*HH*SS*HD];
__device__ __nv_bfloat16 g_kh[BB*HH*SS*HD];
__device__ __nv_bfloat16 g_kl[BB*HH*SS*HD];
__device__ __nv_bfloat16 g_vh[BB*HH*SS*HD];
__device__ __nv_bfloat16 g_vl[BB*HH*SS*HD];

// ---------------- prepass: fp32 -> bf16 hi/lo split -------------------------
__global__ __launch_bounds__(256)
void split_kernel(const float4* __restrict__ X, __nv_bfloat16* __restrict__ Hi,
                  __nv_bfloat16* __restrict__ Lo, int n4)
{
    union U { __nv_bfloat16 b[4]; uint64_t u; };
    for (int i = blockIdx.x * blockDim.x + threadIdx.x; i < n4;
         i += gridDim.x * blockDim.x) {
        float4 f = X[i];
        U h, l;
        float vf[4] = {f.x, f.y, f.z, f.w};
        #pragma unroll
        for (int j = 0; j < 4; ++j) {
            __nv_bfloat16 hb = __float2bfloat16(vf[j]);
            h.b[j] = hb;
            l.b[j] = __float2bfloat16(vf[j] - __bfloat162float(hb));
        }
        ((uint64_t*)Hi)[i] = h.u;
        ((uint64_t*)Lo)[i] = l.u;
    }
}

// ---------------- prepass: W[k][n] -> Wt[n][k] hi/lo split -------------------
__global__ __launch_bounds__(256)
void transpose_split_kernel(const float* __restrict__ W,
                            __nv_bfloat16* __restrict__ Th,
                            __nv_bfloat16* __restrict__ Tl)
{
    __shared__ float tile[32][33];
    int tx = threadIdx.x, ty = threadIdx.y;
    int x = blockIdx.x * 32 + tx;
    #pragma unroll
    for (int i = 0; i < 4; ++i) {
        int y = blockIdx.y * 32 + ty + i * 8;
        tile[ty + i * 8][tx] = W[(size_t)y * DD + x];
    }
    __syncthreads();
    int xo = blockIdx.y * 32 + tx;
    #pragma unroll
    for (int i = 0; i < 4; ++i) {
        int yo = blockIdx.x * 32 + ty + i * 8;
        float v = tile[tx][ty + i * 8];
        __nv_bfloat16 hb = __float2bfloat16(v);
        Th[(size_t)yo * DD + xo] = hb;
        Tl[(size_t)yo * DD + xo] = __float2bfloat16(v - __bfloat162float(hb));
    }
}

// ---------------- mma.sync helpers ------------------------------------------
__device__ __forceinline__ uint32_t smem_u32(const void* p) {
    uint32_t a;
    asm("{ .reg .u64 t; cvta.to.shared.u64 t, %1; cvt.u32.u64 %0, t; }"
        : "=r"(a) : "l"(p));
    return a;
}
__device__ __forceinline__ void ldmx4(uint32_t* r, uint32_t addr) {
    asm volatile("ldmatrix.sync.aligned.m8n8.x4.shared.b16 {%0,%1,%2,%3}, [%4];"
                 : "=r"(r[0]), "=r"(r[1]), "=r"(r[2]), "=r"(r[3]) : "r"(addr));
}
__device__ __forceinline__ void ldmx4t(uint32_t* r, uint32_t addr) {
    asm volatile("ldmatrix.sync.aligned.m8n8.x4.trans.shared.b16 {%0,%1,%2,%3}, [%4];"
                 : "=r"(r[0]), "=r"(r[1]), "=r"(r[2]), "=r"(r[3]) : "r"(addr));
}
__device__ __forceinline__ void mma_bf16(float* c, const uint32_t* a,
                                         uint32_t b0, uint32_t b1) {
    asm volatile(
        "mma.sync.aligned.m16n8k16.row.col.f32.bf16.bf16.f32 "
        "{%0,%1,%2,%3}, {%4,%5,%6,%7}, {%8,%9}, {%0,%1,%2,%3};"
        : "+f"(c[0]), "+f"(c[1]), "+f"(c[2]), "+f"(c[3])
        : "r"(a[0]), "r"(a[1]), "r"(a[2]), "r"(a[3]), "r"(b0), "r"(b1));
}
__device__ __forceinline__ float ex2f(float x) {
    float y; asm("ex2.approx.f32 %0, %1;" : "=f"(y) : "f"(x)); return y;
}
__device__ __forceinline__ uint32_t pack2(__nv_bfloat16 a, __nv_bfloat16 b) {
    __nv_bfloat162 t = __halves2bfloat162(a, b);
    return *(uint32_t*)&t;
}
__device__ __forceinline__ uint32_t pack_bf16x2(float a, float b) {
    return pack2(__float2bfloat16(a), __float2bfloat16(b));
}

// ---------------- HMMA GEMM -------------------------------------------------
// C[4096,1024] = Ahi@Bhi^T + Ahi@Blo^T + Alo@Bhi^T   (B stored [N][K])
// CTA 128x128, BK=32, 8 warps (4x2), warp tile 32x64. Double-buffered smem.
// MODE 0: write bf16 hi/lo head-major [B,H,S,HD]. MODE 1: fp32 [M,N]+bias.
#define AST 40
#define NTILES 96

template<int MODE>
__global__ __launch_bounds__(256, 2)
void mma_gemm(const __nv_bfloat16* __restrict__ Ahi, const __nv_bfloat16* __restrict__ Alo,
              const __nv_bfloat16* __restrict__ Bhi, const __nv_bfloat16* __restrict__ Blo,
              __nv_bfloat16* __restrict__ Yh, __nv_bfloat16* __restrict__ Yl,
              float* __restrict__ Yf, const float* __restrict__ bias)
{
    __shared__ __nv_bfloat16 sA[2][128*AST];
    __shared__ __nv_bfloat16 sB[2][128*AST];

    const int tid  = threadIdx.x;
    const int wid  = tid >> 5;
    const int lane = tid & 31;
    const int m0 = blockIdx.y * 128;
    const int n0 = blockIdx.x * 128;
    const int wm0 = (wid & 3) * 32;
    const int wn0 = (wid >> 2) * 64;

    const uint64_t* As[3] = {(const uint64_t*)Ahi, (const uint64_t*)Ahi, (const uint64_t*)Alo};
    const uint64_t* Bs[3] = {(const uint64_t*)Bhi, (const uint64_t*)Blo, (const uint64_t*)Bhi};

    const int ldrow[4] = { (tid + 0*256) >> 3, (tid + 1*256) >> 3,
                           (tid + 2*256) >> 3, (tid + 3*256) >> 3 };
    const int ldc = tid & 7;

    const uint32_t baseA = smem_u32(&sA[0][0]);
    const uint32_t baseB = smem_u32(&sB[0][0]);
    const uint32_t bufStride = 128 * AST * 2;
    uint32_t aoff[2], boff[4];
    #pragma unroll
    for (int mf = 0; mf < 2; ++mf)
        aoff[mf] = ((wm0 + mf*16 + (lane & 15)) * AST + (lane >> 4) * 8) * 2;
    #pragma unroll
    for (int np = 0; np < 4; ++np)
        boff[np] = ((wn0 + np*16 + ((lane >> 4) & 1) * 8 + (lane & 7)) * AST
                    + ((lane >> 3) & 1) * 8) * 2;

    float acc[2][8][4] = {};
    uint64_t ra[4], rb[4];

    auto ldg = [&](int t) {
        const int seg = t >> 5;
        const int kc  = (t & 31) * 8;
        const uint64_t* Ag = As[seg];
        const uint64_t* Bg = Bs[seg];
        #pragma unroll
        for (int i = 0; i < 4; ++i) {
            ra[i] = Ag[(size_t)(m0 + ldrow[i]) * 256 + kc + ldc];
            rb[i] = Bg[(size_t)(n0 + ldrow[i]) * 256 + kc + ldc];
        }
    };
    auto sts = [&](int buf) {
        #pragma unroll
        for (int i = 0; i < 4; ++i) {
            *(uint64_t*)&sA[buf][ldrow[i]*AST + ldc*4] = ra[i];
            *(uint64_t*)&sB[buf][ldrow[i]*AST + ldc*4] = rb[i];
        }
    };
    auto compute = [&](int buf) {
        const uint32_t bA = baseA + buf * bufStride;
        const uint32_t bB = baseB + buf * bufStride;
        #pragma unroll
        for (int ks = 0; ks < 32; ks += 16) {
            uint32_t af[2][4], bf[4][4];
            #pragma unroll
            for (int mf = 0; mf < 2; ++mf) ldmx4(af[mf], bA + aoff[mf] + ks*2);
            #pragma unroll
            for (int np = 0; np < 4; ++np) ldmx4(bf[np], bB + boff[np] + ks*2);
            #pragma unroll
            for (int mf = 0; mf < 2; ++mf)
                #pragma unroll
                for (int np = 0; np < 4; ++np) {
                    mma_bf16(acc[mf][np*2+0], af[mf], bf[np][0], bf[np][1]);
                    mma_bf16(acc[mf][np*2+1], af[mf], bf[np][2], bf[np][3]);
                }
        }
    };

    ldg(0); sts(0);
    __syncthreads();
    for (int t = 0; t < NTILES; ++t) {
        const int buf = t & 1;
        if (t + 1 < NTILES) ldg(t + 1);
        compute(buf);
        if (t + 1 < NTILES) sts(buf ^ 1);
        __syncthreads();
    }

    // ---- epilogue ----
    const int qrow = lane >> 2;
    const int qcol = (lane & 3) * 2;
    #pragma unroll
    for (int mf = 0; mf < 2; ++mf) {
        #pragma unroll
        for (int nf = 0; nf < 8; ++nf) {
            const int n = n0 + wn0 + nf*8 + qcol;
            #pragma unroll
            for (int half = 0; half < 2; ++half) {
                const int m = m0 + wm0 + mf*16 + qrow + half*8;
                const float cx = acc[mf][nf][half*2 + 0];
                const float cy = acc[mf][nf][half*2 + 1];
                if (MODE == 0) {
                    const int b = m >> 11, s = m & (SS - 1);
                    const int h = n >> 6, hd = n & 63;
                    const size_t off = (((size_t)b*HH + h)*SS + s)*HD + hd;
                    __nv_bfloat16 hx = __float2bfloat16(cx);
                    __nv_bfloat16 hy = __float2bfloat16(cy);
                    *(uint32_t*)(Yh + off) = pack2(hx, hy);
                    *(uint32_t*)(Yl + off) = pack_bf16x2(
                        cx - __bfloat162float(hx), cy - __bfloat162float(hy));
                } else {
                    float2* dst = (float2*)(Yf + (size_t)m * DD + n);
                    *dst = make_float2(cx + bias[n], cy + bias[n + 1]);
                }
            }
        }
    }
}

// ---------------- HMMA flash attention --------------------------------------
// CTA: 128 q-rows, 8 warps x 16 rows. kv steps of 64. bf16 hi/lo split mma.
#define KST 72                        // smem row stride (bf16)
#define LOG2E 1.4426950408889634f

__global__ __launch_bounds__(256, 1)
void attn_mma(const __nv_bfloat16* __restrict__ Qh, const __nv_bfloat16* __restrict__ Ql,
              const __nv_bfloat16* __restrict__ Kh, const __nv_bfloat16* __restrict__ Kl,
              const __nv_bfloat16* __restrict__ Vh, const __nv_bfloat16* __restrict__ Vl,
              float* __restrict__ ctx)
{
    __shared__ __attribute__((aligned(16))) __nv_bfloat16 sm[4*64*KST];

    const int qi  = blockIdx.x;          // 0..15
    const int bh  = blockIdx.y;          // 0..31
    const int tid = threadIdx.x;
    const int wid = tid >> 5;
    const int lane = tid & 31;
    const int wrow0 = wid * 16;

    const size_t hbase = (size_t)bh * SS * HD;
    const uint4* Qh4 = (const uint4*)(Qh + hbase + (size_t)qi*128*HD);
    const uint4* Ql4 = (const uint4*)(Ql + hbase + (size_t)qi*128*HD);
    const uint4* Kh4 = (const uint4*)(Kh + hbase);
    const uint4* Kl4 = (const uint4*)(Kl + hbase);
    const uint4* Vh4 = (const uint4*)(Vh + hbase);
    const uint4* Vl4 = (const uint4*)(Vl + hbase);

    // ---- stage Q (128x64 hi + lo) into smem, ldmatrix into registers ----
    {
        const uint4* bufs[2] = {Qh4, Ql4};
        #pragma unroll
        for (int i = 0; i < 8; ++i) {
            int idx = tid + i * 256;            // 0..2047
            int buf = idx >> 10;
            int within = idx & 1023;
            int row = within >> 3, c = within & 7;
            uint4 v = bufs[buf][within];
            *(uint4*)&sm[(buf*128 + row)*KST + c*8] = v;
        }
    }
    __syncthreads();

    uint32_t qhf[4][4], qlf[4][4];
    {
        const uint32_t base = smem_u32(sm);
        const uint32_t roff = ((wrow0 + (lane & 15)) * KST + (lane >> 4) * 8) * 2;
        #pragma unroll
        for (int ks = 0; ks < 4; ++ks) {
            ldmx4(qhf[ks], base + roff + ks * 32);
            ldmx4(qlf[ks], base + roff + 128*KST*2 + ks * 32);
        }
    }
    __syncthreads();

    // ---- per-thread state ----
    float mrow[2] = {-1e30f, -1e30f};
    float lrow[2] = {0.0f, 0.0f};
    float o[8][4] = {};

    const uint32_t sKh = smem_u32(sm);
    const uint32_t sKl = sKh + 64*KST*2;
    const uint32_t sVh = sKh + 128*KST*2;
    const uint32_t sVl = sKh + 192*KST*2;

    // K frag address pieces (non-trans):
    uint32_t kbase[4];
    #pragma unroll
    for (int ng = 0; ng < 4; ++ng) {
        int krow = ng*16 + ((lane >> 4) & 1)*8 + (lane & 7);
        kbase[ng] = (krow * KST + ((lane >> 3) & 1) * 8) * 2;
    }
    // V frag address pieces (trans):
    const uint32_t vrowoff = ((((lane >> 3) & 1)*8 + (lane & 7)) * KST) * 2;
    uint32_t vcol[4];
    #pragma unroll
    for (int ng = 0; ng < 4; ++ng)
        vcol[ng] = (ng*16 + (lane >> 4) * 8) * 2;

    const int wmax = qi*128 + wrow0 + 15;        // max q row this warp owns
    const int nsteps = 2*qi + 2;

    for (int kt = 0; kt < nsteps; ++kt) {
        // ---- load K/V hi/lo tiles (4 x 64x64 bf16) ----
        {
            const uint4* srcs[4] = {Kh4 + kt*512, Kl4 + kt*512, Vh4 + kt*512, Vl4 + kt*512};
            #pragma unroll
            for (int i = 0; i < 8; ++i) {
                int idx = tid + i * 256;
                int tile = idx >> 9;
                int within = idx & 511;
                int row = within >> 3, c = within & 7;
                uint4 v = srcs[tile][within];
                *(uint4*)&sm[(tile*64 + row)*KST + c*8] = v;
            }
        }
        __syncthreads();

        if (kt*64 <= wmax) {
            // ---- scores: 3-pass split QK^T ----
            float s[8][4] = {};
            #pragma unroll
            for (int ks = 0; ks < 4; ++ks) {
                uint32_t khb[4][4], klb[4][4];
                #pragma unroll
                for (int ng = 0; ng < 4; ++ng) {
                    ldmx4(khb[ng], sKh + kbase[ng] + ks*32);
                    ldmx4(klb[ng], sKl + kbase[ng] + ks*32);
                }
                #pragma unroll
                for (int ng = 0; ng < 4; ++ng) {
                    mma_bf16(s[2*ng+0], qhf[ks], khb[ng][0], khb[ng][1]);
                    mma_bf16(s[2*ng+1], qhf[ks], khb[ng][2], khb[ng][3]);
                    mma_bf16(s[2*ng+0], qhf[ks], klb[ng][0], klb[ng][1]);
                    mma_bf16(s[2*ng+1], qhf[ks], klb[ng][2], klb[ng][3]);
                    mma_bf16(s[2*ng+0], qlf[ks], khb[ng][0], khb[ng][1]);
                    mma_bf16(s[2*ng+1], qlf[ks], khb[ng][2], khb[ng][3]);
                }
            }

            // ---- scale + causal mask ----
            const int r0g = qi*128 + wrow0 + (lane >> 2);
            const bool needmask = (kt*64 + 63 > qi*128 + wrow0);
            #pragma unroll
            for (int nf = 0; nf < 8; ++nf) {
                #pragma unroll
                for (int ri = 0; ri < 4; ++ri) {
                    float v = s[nf][ri] * 0.125f;
                    if (needmask) {
                        int col = kt*64 + nf*8 + (lane & 3)*2 + (ri & 1);
                        int rg  = r0g + ((ri >> 1) ? 8 : 0);
                        if (col > rg) v = -1e30f;
                    }
                    s[nf][ri] = v;
                }
            }

            // ---- online softmax ----
            float alpha[2];
            #pragma unroll
            for (int h = 0; h < 2; ++h) {
                float t = -1e30f;
                #pragma unroll
                for (int nf = 0; nf < 8; ++nf)
                    t = fmaxf(t, fmaxf(s[nf][h*2], s[nf][h*2+1]));
                t = fmaxf(t, __shfl_xor_sync(0xffffffffu, t, 1));
                t = fmaxf(t, __shfl_xor_sync(0xffffffffu, t, 2));
                float nm = fmaxf(mrow[h], t);
                alpha[h] = ex2f((mrow[h] - nm) * LOG2E);
                mrow[h] = nm;
            }
            float rs[2] = {0.0f, 0.0f};
            #pragma unroll
            for (int nf = 0; nf < 8; ++nf) {
                #pragma unroll
                for (int ri = 0; ri < 4; ++ri) {
                    int h = ri >> 1;
                    float p = ex2f((s[nf][ri] - mrow[h]) * LOG2E);
                    s[nf][ri] = p;
                    rs[h] += p;
                }
            }
            #pragma unroll
            for (int h = 0; h < 2; ++h) {
                rs[h] += __shfl_xor_sync(0xffffffffu, rs[h], 1);
                rs[h] += __shfl_xor_sync(0xffffffffu, rs[h], 2);
                lrow[h] = lrow[h] * alpha[h] + rs[h];
            }
            #pragma unroll
            for (int nf = 0; nf < 8; ++nf) {
                o[nf][0] *= alpha[0]; o[nf][1] *= alpha[0];
                o[nf][2] *= alpha[1]; o[nf][3] *= alpha[1];
            }

            // ---- P frags (hi/lo) ----
            // A-frag reg order for m16k16: {r,k0-1},{r+8,k0-1},{r,k8-9},{r+8,k8-9}
            // s[nf][0..1] = cols 2j,2j+1 row r ; s[nf][2..3] = row r+8
            uint32_t pah[4][4], pal[4][4];
            #pragma unroll
            for (int ks = 0; ks < 4; ++ks) {
                float a0 = s[2*ks][0],   a1 = s[2*ks][1];      // row r,  k0..1 (frag n=2ks)
                float b0 = s[2*ks][2],   b1 = s[2*ks][3];      // row r+8,k0..1
                float c0 = s[2*ks+1][0], c1 = s[2*ks+1][1];    // row r,  k8..9
                float d0 = s[2*ks+1][2], d1 = s[2*ks+1][3];    // row r+8,k8..9
                __nv_bfloat16 ha0 = __float2bfloat16(a0), ha1 = __float2bfloat16(a1);
                __nv_bfloat16 hb0 = __float2bfloat16(b0), hb1 = __float2bfloat16(b1);
                __nv_bfloat16 hc0 = __float2bfloat16(c0), hc1 = __float2bfloat16(c1);
                __nv_bfloat16 hd0 = __float2bfloat16(d0), hd1 = __float2bfloat16(d1);
                pah[ks][0] = pack2(ha0, ha1);
                pah[ks][1] = pack2(hb0, hb1);
                pah[ks][2] = pack2(hc0, hc1);
                pah[ks][3] = pack2(hd0, hd1);
                pal[ks][0] = pack_bf16x2(a0 - __bfloat162float(ha0), a1 - __bfloat162float(ha1));
                pal[ks][1] = pack_bf16x2(b0 - __bfloat162float(hb0), b1 - __bfloat162float(hb1));
                pal[ks][2] = pack_bf16x2(c0 - __bfloat162float(hc0), c1 - __bfloat162float(hc1));
                pal[ks][3] = pack_bf16x2(d0 - __bfloat162float(hd0), d1 - __bfloat162float(hd1));
            }

            // ---- P@V: 3-pass split ----
            #pragma unroll
            for (int ks = 0; ks < 4; ++ks) {
                const uint32_t vrb = vrowoff + ks*16*KST*2;
                #pragma unroll
                for (int ng = 0; ng < 4; ++ng) {
                    uint32_t vhb[4], vlb[4];
                    ldmx4t(vhb, sVh + vrb + vcol[ng]);
                    ldmx4t(vlb, sVl + vrb + vcol[ng]);
                    mma_bf16(o[2*ng+0], pah[ks], vhb[0], vhb[1]);
                    mma_bf16(o[2*ng+1], pah[ks], vhb[2], vhb[3]);
                    mma_bf16(o[2*ng+0], pah[ks], vlb[0], vlb[1]);
                    mma_bf16(o[2*ng+1], pah[ks], vlb[2], vlb[3]);
                    mma_bf16(o[2*ng+0], pal[ks], vhb[0], vhb[1]);
                    mma_bf16(o[2*ng+1], pal[ks], vhb[2], vhb[3]);
                }
            }
        }
        __syncthreads();
    }

    // ---- epilogue: write ctx [B,S,D] fp32 ----
    const float inv0 = 1.0f / lrow[0];
    const float inv1 = 1.0f / lrow[1];
    const int b = bh >> 4, h = bh & 15;
    const int r0 = qi*128 + wrow0 + (lane >> 2);
    #pragma unroll
    for (int nf = 0; nf < 8; ++nf) {
        const int hd = nf*8 + (lane & 3)*2;
        float2* d0 = (float2*)(ctx + ((size_t)b*SS + r0)*DD + h*HD + hd);
        float2* d1 = (float2*)(ctx + ((size_t)b*SS + r0 + 8)*DD + h*HD + hd);
        *d0 = make_float2(o[nf][0]*inv0, o[nf][1]*inv0);
        *d1 = make_float2(o[nf][2]*inv1, o[nf][3]*inv1);
    }
}

// ---------------------------------------------------------------------------

extern "C" void kernel_launch(void* const* d_in, const int* in_sizes, int n_in,
                              void* d_out, int out_size)
{
    const float* x  = (const float*)d_in[0];
    const float* Wq = (const float*)d_in[1];
    const float* Wk = (const float*)d_in[2];
    const float* Wv = (const float*)d_in[3];
    const float* Wo = (const float*)d_in[4];
    const float* bo = (const float*)d_in[5];
    float* out = (float*)d_out;

    float *ctx;
    __nv_bfloat16 *ahi, *alo, *wthi, *wtlo, *qh, *ql, *kh, *kl, *vh, *vl;
    cudaGetSymbolAddress((void**)&ctx,  g_ctx);
    cudaGetSymbolAddress((void**)&ahi,  g_ahi);
    cudaGetSymbolAddress((void**)&alo,  g_alo);
    cudaGetSymbolAddress((void**)&wthi, g_wthi);
    cudaGetSymbolAddress((void**)&wtlo, g_wtlo);
    cudaGetSymbolAddress((void**)&qh,   g_qh);
    cudaGetSymbolAddress((void**)&ql,   g_ql);
    cudaGetSymbolAddress((void**)&kh,   g_kh);
    cudaGetSymbolAddress((void**)&kl,   g_kl);
    cudaGetSymbolAddress((void**)&vh,   g_vh);
    cudaGetSymbolAddress((void**)&vl,   g_vl);

    // 1. split X into bf16 hi/lo
    split_kernel<<<1024, 256>>>((const float4*)x, ahi, alo, MM*DD/4);

    // 2. transpose+split weights
    const float* Ws[4] = {Wq, Wk, Wv, Wo};
    for (int i = 0; i < 4; ++i)
        transpose_split_kernel<<<dim3(32,32), dim3(32,8)>>>(
            Ws[i], wthi + (size_t)i*DD*DD, wtlo + (size_t)i*DD*DD);

    // 3. Q/K/V projections (HMMA), emitting bf16 hi/lo head-major
    dim3 ggrid(DD/128, MM/128);
    mma_gemm<0><<<ggrid, 256>>>(ahi, alo, wthi + 0*(size_t)DD*DD, wtlo + 0*(size_t)DD*DD, qh, ql, nullptr, nullptr);
    mma_gemm<0><<<ggrid, 256>>>(ahi, alo, wthi + 1*(size_t)DD*DD, wtlo + 1*(size_t)DD*DD, kh, kl, nullptr, nullptr);
    mma_gemm<0><<<ggrid, 256>>>(ahi, alo, wthi + 2*(size_t)DD*DD, wtlo + 2*(size_t)DD*DD, vh, vl, nullptr, nullptr);

    // 4. attention (HMMA flash)
    dim3 agrid(SS/128, BB*HH);
    attn_mma<<<agrid, 256>>>(qh, ql, kh, kl, vh, vl, ctx);

    // 5. split ctx, output projection + bias
    split_kernel<<<1024, 256>>>((const float4*)ctx, ahi, alo, MM*DD/4);
    mma_gemm<1><<<ggrid, 256>>>(ahi, alo, wthi + 3*(size_t)DD*DD, wtlo + 3*(size_t)DD*DD, nullptr, nullptr, out, bo);
}

// round 6
// speedup vs baseline: 2.9367x; 1.0514x over previous
#include <cuda_runtime.h>
#include <cuda_bf16.h>
#include <cstdint>

#define BB 2
#define SS 2048
#define DD 1024
#define HH 16
#define HD 64
#define MM (BB*SS)     // 4096

// ---------------- device scratch (no allocation allowed) -------------------
__device__ float g_ctx[BB*SS*DD];
__device__ __nv_bfloat16 g_ahi[MM*DD];
__device__ __nv_bfloat16 g_alo[MM*DD];
__device__ __nv_bfloat16 g_wthi[4][DD*DD];
__device__ __nv_bfloat16 g_wtlo[4][DD*DD];
__device__ __nv_bfloat16 g_qh[BB*HH*SS*HD];
__device__ __nv_bfloat16 g_ql[BB*HH*SS*HD];
__device__ __nv_bfloat16 g_kh[BB*HH*SS*HD];
__device__ __nv_bfloat16 g_kl[BB*HH*SS*HD];
__device__ __nv_bfloat16 g_vh[BB*HH*SS*HD];
__device__ __nv_bfloat16 g_vl[BB*HH*SS*HD];

// ---------------- prepass: fp32 -> bf16 hi/lo split -------------------------
__global__ __launch_bounds__(256)
void split_kernel(const float4* __restrict__ X, __nv_bfloat16* __restrict__ Hi,
                  __nv_bfloat16* __restrict__ Lo, int n4)
{
    union U { __nv_bfloat16 b[4]; uint64_t u; };
    for (int i = blockIdx.x * blockDim.x + threadIdx.x; i < n4;
         i += gridDim.x * blockDim.x) {
        float4 f = X[i];
        U h, l;
        float vf[4] = {f.x, f.y, f.z, f.w};
        #pragma unroll
        for (int j = 0; j < 4; ++j) {
            __nv_bfloat16 hb = __float2bfloat16(vf[j]);
            h.b[j] = hb;
            l.b[j] = __float2bfloat16(vf[j] - __bfloat162float(hb));
        }
        ((uint64_t*)Hi)[i] = h.u;
        ((uint64_t*)Lo)[i] = l.u;
    }
}

// ---------------- prepass: 4x W[k][n] -> Wt[n][k] hi/lo split ----------------
__global__ __launch_bounds__(256)
void transpose_split_kernel(const float* __restrict__ W0, const float* __restrict__ W1,
                            const float* __restrict__ W2, const float* __restrict__ W3,
                            __nv_bfloat16* __restrict__ Th,
                            __nv_bfloat16* __restrict__ Tl)
{
    __shared__ float tile[32][33];
    const float* Ws[4] = {W0, W1, W2, W3};
    const float* W = Ws[blockIdx.z];
    __nv_bfloat16* th = Th + (size_t)blockIdx.z * DD * DD;
    __nv_bfloat16* tl = Tl + (size_t)blockIdx.z * DD * DD;
    int tx = threadIdx.x, ty = threadIdx.y;
    int x = blockIdx.x * 32 + tx;
    #pragma unroll
    for (int i = 0; i < 4; ++i) {
        int y = blockIdx.y * 32 + ty + i * 8;
        tile[ty + i * 8][tx] = W[(size_t)y * DD + x];
    }
    __syncthreads();
    int xo = blockIdx.y * 32 + tx;
    #pragma unroll
    for (int i = 0; i < 4; ++i) {
        int yo = blockIdx.x * 32 + ty + i * 8;
        float v = tile[tx][ty + i * 8];
        __nv_bfloat16 hb = __float2bfloat16(v);
        th[(size_t)yo * DD + xo] = hb;
        tl[(size_t)yo * DD + xo] = __float2bfloat16(v - __bfloat162float(hb));
    }
}

// ---------------- mma.sync helpers ------------------------------------------
__device__ __forceinline__ uint32_t smem_u32(const void* p) {
    uint32_t a;
    asm("{ .reg .u64 t; cvta.to.shared.u64 t, %1; cvt.u32.u64 %0, t; }"
        : "=r"(a) : "l"(p));
    return a;
}
__device__ __forceinline__ void ldmx4(uint32_t* r, uint32_t addr) {
    asm volatile("ldmatrix.sync.aligned.m8n8.x4.shared.b16 {%0,%1,%2,%3}, [%4];"
                 : "=r"(r[0]), "=r"(r[1]), "=r"(r[2]), "=r"(r[3]) : "r"(addr));
}
__device__ __forceinline__ void ldmx4t(uint32_t* r, uint32_t addr) {
    asm volatile("ldmatrix.sync.aligned.m8n8.x4.trans.shared.b16 {%0,%1,%2,%3}, [%4];"
                 : "=r"(r[0]), "=r"(r[1]), "=r"(r[2]), "=r"(r[3]) : "r"(addr));
}
__device__ __forceinline__ void mma_bf16(float* c, const uint32_t* a,
                                         uint32_t b0, uint32_t b1) {
    asm volatile(
        "mma.sync.aligned.m16n8k16.row.col.f32.bf16.bf16.f32 "
        "{%0,%1,%2,%3}, {%4,%5,%6,%7}, {%8,%9}, {%0,%1,%2,%3};"
        : "+f"(c[0]), "+f"(c[1]), "+f"(c[2]), "+f"(c[3])
        : "r"(a[0]), "r"(a[1]), "r"(a[2]), "r"(a[3]), "r"(b0), "r"(b1));
}
__device__ __forceinline__ float ex2f(float x) {
    float y; asm("ex2.approx.f32 %0, %1;" : "=f"(y) : "f"(x)); return y;
}
__device__ __forceinline__ uint32_t pack2(__nv_bfloat16 a, __nv_bfloat16 b) {
    __nv_bfloat162 t = __halves2bfloat162(a, b);
    return *(uint32_t*)&t;
}
__device__ __forceinline__ uint32_t pack_bf16x2(float a, float b) {
    return pack2(__float2bfloat16(a), __float2bfloat16(b));
}

// ---------------- HMMA GEMM core --------------------------------------------
#define AST 40
#define NTILES 96

struct GemmAcc { float acc[2][8][4]; };

template<typename EPI>
__device__ __forceinline__ void gemm_core(
    const __nv_bfloat16* Ahi, const __nv_bfloat16* Alo,
    const __nv_bfloat16* Bhi, const __nv_bfloat16* Blo,
    int m0, int n0, EPI epi)
{
    __shared__ __nv_bfloat16 sA[2][128*AST];
    __shared__ __nv_bfloat16 sB[2][128*AST];

    const int tid  = threadIdx.x;
    const int wid  = tid >> 5;
    const int lane = tid & 31;
    const int wm0 = (wid & 3) * 32;
    const int wn0 = (wid >> 2) * 64;

    const uint64_t* As[3] = {(const uint64_t*)Ahi, (const uint64_t*)Ahi, (const uint64_t*)Alo};
    const uint64_t* Bs[3] = {(const uint64_t*)Bhi, (const uint64_t*)Blo, (const uint64_t*)Bhi};

    const int ldrow[4] = { (tid + 0*256) >> 3, (tid + 1*256) >> 3,
                           (tid + 2*256) >> 3, (tid + 3*256) >> 3 };
    const int ldc = tid & 7;

    const uint32_t baseA = smem_u32(&sA[0][0]);
    const uint32_t baseB = smem_u32(&sB[0][0]);
    const uint32_t bufStride = 128 * AST * 2;
    uint32_t aoff[2], boff[4];
    #pragma unroll
    for (int mf = 0; mf < 2; ++mf)
        aoff[mf] = ((wm0 + mf*16 + (lane & 15)) * AST + (lane >> 4) * 8) * 2;
    #pragma unroll
    for (int np = 0; np < 4; ++np)
        boff[np] = ((wn0 + np*16 + ((lane >> 4) & 1) * 8 + (lane & 7)) * AST
                    + ((lane >> 3) & 1) * 8) * 2;

    GemmAcc A = {};
    uint64_t ra[4], rb[4];

    auto ldg = [&](int t) {
        const int seg = t >> 5;
        const int kc  = (t & 31) * 8;
        const uint64_t* Ag = As[seg];
        const uint64_t* Bg = Bs[seg];
        #pragma unroll
        for (int i = 0; i < 4; ++i) {
            ra[i] = Ag[(size_t)(m0 + ldrow[i]) * 256 + kc + ldc];
            rb[i] = Bg[(size_t)(n0 + ldrow[i]) * 256 + kc + ldc];
        }
    };
    auto sts = [&](int buf) {
        #pragma unroll
        for (int i = 0; i < 4; ++i) {
            *(uint64_t*)&sA[buf][ldrow[i]*AST + ldc*4] = ra[i];
            *(uint64_t*)&sB[buf][ldrow[i]*AST + ldc*4] = rb[i];
        }
    };
    auto compute = [&](int buf) {
        const uint32_t bA = baseA + buf * bufStride;
        const uint32_t bB = baseB + buf * bufStride;
        #pragma unroll
        for (int ks = 0; ks < 32; ks += 16) {
            uint32_t af[2][4], bf[4][4];
            #pragma unroll
            for (int mf = 0; mf < 2; ++mf) ldmx4(af[mf], bA + aoff[mf] + ks*2);
            #pragma unroll
            for (int np = 0; np < 4; ++np) ldmx4(bf[np], bB + boff[np] + ks*2);
            #pragma unroll
            for (int mf = 0; mf < 2; ++mf)
                #pragma unroll
                for (int np = 0; np < 4; ++np) {
                    mma_bf16(A.acc[mf][np*2+0], af[mf], bf[np][0], bf[np][1]);
                    mma_bf16(A.acc[mf][np*2+1], af[mf], bf[np][2], bf[np][3]);
                }
        }
    };

    ldg(0); sts(0);
    __syncthreads();
    for (int t = 0; t < NTILES; ++t) {
        const int buf = t & 1;
        if (t + 1 < NTILES) ldg(t + 1);
        compute(buf);
        if (t + 1 < NTILES) sts(buf ^ 1);
        __syncthreads();
    }

    const int qrow = lane >> 2;
    const int qcol = (lane & 3) * 2;
    #pragma unroll
    for (int mf = 0; mf < 2; ++mf)
        #pragma unroll
        for (int nf = 0; nf < 8; ++nf)
            #pragma unroll
            for (int half = 0; half < 2; ++half) {
                const int m = m0 + wm0 + mf*16 + qrow + half*8;
                const int n = n0 + wn0 + nf*8 + qcol;
                epi(m, n, A.acc[mf][nf][half*2 + 0], A.acc[mf][nf][half*2 + 1]);
            }
}

// fused QKV projection: grid.x = 24 (gemm = x>>3), grid.y = 32
__global__ __launch_bounds__(256, 2)
void mma_gemm_qkv(const __nv_bfloat16* __restrict__ Ahi, const __nv_bfloat16* __restrict__ Alo,
                  const __nv_bfloat16* __restrict__ Whi, const __nv_bfloat16* __restrict__ Wlo,
                  __nv_bfloat16* __restrict__ qh, __nv_bfloat16* __restrict__ ql,
                  __nv_bfloat16* __restrict__ kh, __nv_bfloat16* __restrict__ kl,
                  __nv_bfloat16* __restrict__ vh, __nv_bfloat16* __restrict__ vl)
{
    const int g  = blockIdx.x >> 3;
    const int n0 = (blockIdx.x & 7) * 128;
    const int m0 = blockIdx.y * 128;
    const __nv_bfloat16* Bhi = Whi + (size_t)g * DD * DD;
    const __nv_bfloat16* Blo = Wlo + (size_t)g * DD * DD;
    __nv_bfloat16* Yh = (g == 0) ? qh : (g == 1) ? kh : vh;
    __nv_bfloat16* Yl = (g == 0) ? ql : (g == 1) ? kl : vl;

    gemm_core(Ahi, Alo, Bhi, Blo, m0, n0,
        [&](int m, int n, float cx, float cy) {
            const int b = m >> 11, s = m & (SS - 1);
            const int h = n >> 6, hd = n & 63;
            const size_t off = (((size_t)b*HH + h)*SS + s)*HD + hd;
            __nv_bfloat16 hx = __float2bfloat16(cx);
            __nv_bfloat16 hy = __float2bfloat16(cy);
            *(uint32_t*)(Yh + off) = pack2(hx, hy);
            *(uint32_t*)(Yl + off) = pack_bf16x2(
                cx - __bfloat162float(hx), cy - __bfloat162float(hy));
        });
}

// output projection + bias
__global__ __launch_bounds__(256, 2)
void mma_gemm_out(const __nv_bfloat16* __restrict__ Ahi, const __nv_bfloat16* __restrict__ Alo,
                  const __nv_bfloat16* __restrict__ Bhi, const __nv_bfloat16* __restrict__ Blo,
                  float* __restrict__ Yf, const float* __restrict__ bias)
{
    const int n0 = blockIdx.x * 128;
    const int m0 = blockIdx.y * 128;
    gemm_core(Ahi, Alo, Bhi, Blo, m0, n0,
        [&](int m, int n, float cx, float cy) {
            float2* dst = (float2*)(Yf + (size_t)m * DD + n);
            *dst = make_float2(cx + bias[n], cy + bias[n + 1]);
        });
}

// ---------------- HMMA flash attention --------------------------------------
// grid (8, 32): CTA processes q-tiles blockIdx.x and 15-blockIdx.x (balance).
// 8 warps x 16 q-rows; kv steps of 64; bf16 hi/lo split mma.
#define KST 72
#define LOG2E 1.4426950408889634f

__global__ __launch_bounds__(256, 2)
void attn_mma(const __nv_bfloat16* __restrict__ Qh, const __nv_bfloat16* __restrict__ Ql,
              const __nv_bfloat16* __restrict__ Kh, const __nv_bfloat16* __restrict__ Kl,
              const __nv_bfloat16* __restrict__ Vh, const __nv_bfloat16* __restrict__ Vl,
              float* __restrict__ ctx)
{
    __shared__ __attribute__((aligned(16))) __nv_bfloat16 sm[4*64*KST];

    const int bh  = blockIdx.y;
    const int tid = threadIdx.x;
    const int wid = tid >> 5;
    const int lane = tid & 31;
    const int wrow0 = wid * 16;

    const size_t hbase = (size_t)bh * SS * HD;
    const uint4* Kh4 = (const uint4*)(Kh + hbase);
    const uint4* Kl4 = (const uint4*)(Kl + hbase);
    const uint4* Vh4 = (const uint4*)(Vh + hbase);
    const uint4* Vl4 = (const uint4*)(Vl + hbase);

    const uint32_t sKh = smem_u32(sm);
    const uint32_t sKl = sKh + 64*KST*2;
    const uint32_t sVh = sKh + 128*KST*2;
    const uint32_t sVl = sKh + 192*KST*2;

    uint32_t kbase[4];
    #pragma unroll
    for (int ng = 0; ng < 4; ++ng) {
        int krow = ng*16 + ((lane >> 4) & 1)*8 + (lane & 7);
        kbase[ng] = (krow * KST + ((lane >> 3) & 1) * 8) * 2;
    }
    const uint32_t vrowoff = ((((lane >> 3) & 1)*8 + (lane & 7)) * KST) * 2;
    uint32_t vcol[4];
    #pragma unroll
    for (int ng = 0; ng < 4; ++ng)
        vcol[ng] = (ng*16 + (lane >> 4) * 8) * 2;

    #pragma unroll 1
    for (int half = 0; half < 2; ++half) {
        const int qi = half ? (15 - blockIdx.x) : blockIdx.x;

        __syncthreads();
        // ---- stage Q (128x64 hi + lo) into smem, ldmatrix into registers ----
        {
            const uint4* Qh4 = (const uint4*)(Qh + hbase + (size_t)qi*128*HD);
            const uint4* Ql4 = (const uint4*)(Ql + hbase + (size_t)qi*128*HD);
            const uint4* bufs[2] = {Qh4, Ql4};
            #pragma unroll
            for (int i = 0; i < 8; ++i) {
                int idx = tid + i * 256;
                int buf = idx >> 10;
                int within = idx & 1023;
                int row = within >> 3, c = within & 7;
                uint4 v = bufs[buf][within];
                *(uint4*)&sm[(buf*128 + row)*KST + c*8] = v;
            }
        }
        __syncthreads();

        uint32_t qhf[4][4], qlf[4][4];
        {
            const uint32_t roff = ((wrow0 + (lane & 15)) * KST + (lane >> 4) * 8) * 2;
            #pragma unroll
            for (int ks = 0; ks < 4; ++ks) {
                ldmx4(qhf[ks], sKh + roff + ks * 32);
                ldmx4(qlf[ks], sKh + roff + 128*KST*2 + ks * 32);
            }
        }
        __syncthreads();

        float mrow[2] = {-1e30f, -1e30f};
        float lrow[2] = {0.0f, 0.0f};
        float o[8][4] = {};

        const int wmax = qi*128 + wrow0 + 15;
        const int nsteps = 2*qi + 2;

        for (int kt = 0; kt < nsteps; ++kt) {
            {
                const uint4* srcs[4] = {Kh4 + kt*512, Kl4 + kt*512, Vh4 + kt*512, Vl4 + kt*512};
                #pragma unroll
                for (int i = 0; i < 8; ++i) {
                    int idx = tid + i * 256;
                    int tile = idx >> 9;
                    int within = idx & 511;
                    int row = within >> 3, c = within & 7;
                    uint4 v = srcs[tile][within];
                    *(uint4*)&sm[(tile*64 + row)*KST + c*8] = v;
                }
            }
            __syncthreads();

            if (kt*64 <= wmax) {
                float s[8][4] = {};
                #pragma unroll
                for (int ks = 0; ks < 4; ++ks) {
                    uint32_t khb[4][4], klb[4][4];
                    #pragma unroll
                    for (int ng = 0; ng < 4; ++ng) {
                        ldmx4(khb[ng], sKh + kbase[ng] + ks*32);
                        ldmx4(klb[ng], sKl + kbase[ng] + ks*32);
                    }
                    #pragma unroll
                    for (int ng = 0; ng < 4; ++ng) {
                        mma_bf16(s[2*ng+0], qhf[ks], khb[ng][0], khb[ng][1]);
                        mma_bf16(s[2*ng+1], qhf[ks], khb[ng][2], khb[ng][3]);
                        mma_bf16(s[2*ng+0], qhf[ks], klb[ng][0], klb[ng][1]);
                        mma_bf16(s[2*ng+1], qhf[ks], klb[ng][2], klb[ng][3]);
                        mma_bf16(s[2*ng+0], qlf[ks], khb[ng][0], khb[ng][1]);
                        mma_bf16(s[2*ng+1], qlf[ks], khb[ng][2], khb[ng][3]);
                    }
                }

                const int r0g = qi*128 + wrow0 + (lane >> 2);
                const bool needmask = (kt*64 + 63 > qi*128 + wrow0);
                #pragma unroll
                for (int nf = 0; nf < 8; ++nf)
                    #pragma unroll
                    for (int ri = 0; ri < 4; ++ri) {
                        float v = s[nf][ri] * 0.125f;
                        if (needmask) {
                            int col = kt*64 + nf*8 + (lane & 3)*2 + (ri & 1);
                            int rg  = r0g + ((ri >> 1) ? 8 : 0);
                            if (col > rg) v = -1e30f;
                        }
                        s[nf][ri] = v;
                    }

                float alpha[2];
                #pragma unroll
                for (int h = 0; h < 2; ++h) {
                    float t = -1e30f;
                    #pragma unroll
                    for (int nf = 0; nf < 8; ++nf)
                        t = fmaxf(t, fmaxf(s[nf][h*2], s[nf][h*2+1]));
                    t = fmaxf(t, __shfl_xor_sync(0xffffffffu, t, 1));
                    t = fmaxf(t, __shfl_xor_sync(0xffffffffu, t, 2));
                    float nm = fmaxf(mrow[h], t);
                    alpha[h] = ex2f((mrow[h] - nm) * LOG2E);
                    mrow[h] = nm;
                }
                float rs[2] = {0.0f, 0.0f};
                #pragma unroll
                for (int nf = 0; nf < 8; ++nf)
                    #pragma unroll
                    for (int ri = 0; ri < 4; ++ri) {
                        int h = ri >> 1;
                        float p = ex2f((s[nf][ri] - mrow[h]) * LOG2E);
                        s[nf][ri] = p;
                        rs[h] += p;
                    }
                #pragma unroll
                for (int h = 0; h < 2; ++h) {
                    rs[h] += __shfl_xor_sync(0xffffffffu, rs[h], 1);
                    rs[h] += __shfl_xor_sync(0xffffffffu, rs[h], 2);
                    lrow[h] = lrow[h] * alpha[h] + rs[h];
                }
                #pragma unroll
                for (int nf = 0; nf < 8; ++nf) {
                    o[nf][0] *= alpha[0]; o[nf][1] *= alpha[0];
                    o[nf][2] *= alpha[1]; o[nf][3] *= alpha[1];
                }

                uint32_t pah[4][4], pal[4][4];
                #pragma unroll
                for (int ks = 0; ks < 4; ++ks) {
                    float a0 = s[2*ks][0],   a1 = s[2*ks][1];
                    float b0 = s[2*ks][2],   b1 = s[2*ks][3];
                    float c0 = s[2*ks+1][0], c1 = s[2*ks+1][1];
                    float d0 = s[2*ks+1][2], d1 = s[2*ks+1][3];
                    __nv_bfloat16 ha0 = __float2bfloat16(a0), ha1 = __float2bfloat16(a1);
                    __nv_bfloat16 hb0 = __float2bfloat16(b0), hb1 = __float2bfloat16(b1);
                    __nv_bfloat16 hc0 = __float2bfloat16(c0), hc1 = __float2bfloat16(c1);
                    __nv_bfloat16 hd0 = __float2bfloat16(d0), hd1 = __float2bfloat16(d1);
                    pah[ks][0] = pack2(ha0, ha1);
                    pah[ks][1] = pack2(hb0, hb1);
                    pah[ks][2] = pack2(hc0, hc1);
                    pah[ks][3] = pack2(hd0, hd1);
                    pal[ks][0] = pack_bf16x2(a0 - __bfloat162float(ha0), a1 - __bfloat162float(ha1));
                    pal[ks][1] = pack_bf16x2(b0 - __bfloat162float(hb0), b1 - __bfloat162float(hb1));
                    pal[ks][2] = pack_bf16x2(c0 - __bfloat162float(hc0), c1 - __bfloat162float(hc1));
                    pal[ks][3] = pack_bf16x2(d0 - __bfloat162float(hd0), d1 - __bfloat162float(hd1));
                }

                #pragma unroll
                for (int ks = 0; ks < 4; ++ks) {
                    const uint32_t vrb = vrowoff + ks*16*KST*2;
                    #pragma unroll
                    for (int ng = 0; ng < 4; ++ng) {
                        uint32_t vhb[4], vlb[4];
                        ldmx4t(vhb, sVh + vrb + vcol[ng]);
                        ldmx4t(vlb, sVl + vrb + vcol[ng]);
                        mma_bf16(o[2*ng+0], pah[ks], vhb[0], vhb[1]);
                        mma_bf16(o[2*ng+1], pah[ks], vhb[2], vhb[3]);
                        mma_bf16(o[2*ng+0], pah[ks], vlb[0], vlb[1]);
                        mma_bf16(o[2*ng+1], pah[ks], vlb[2], vlb[3]);
                        mma_bf16(o[2*ng+0], pal[ks], vhb[0], vhb[1]);
                        mma_bf16(o[2*ng+1], pal[ks], vhb[2], vhb[3]);
                    }
                }
            }
            __syncthreads();
        }

        // ---- epilogue: write ctx [B,S,D] fp32 ----
        const float inv0 = 1.0f / lrow[0];
        const float inv1 = 1.0f / lrow[1];
        const int b = bh >> 4, h = bh & 15;
        const int r0 = qi*128 + wrow0 + (lane >> 2);
        #pragma unroll
        for (int nf = 0; nf < 8; ++nf) {
            const int hd = nf*8 + (lane & 3)*2;
            float2* d0 = (float2*)(ctx + ((size_t)b*SS + r0)*DD + h*HD + hd);
            float2* d1 = (float2*)(ctx + ((size_t)b*SS + r0 + 8)*DD + h*HD + hd);
            *d0 = make_float2(o[nf][0]*inv0, o[nf][1]*inv0);
            *d1 = make_float2(o[nf][2]*inv1, o[nf][3]*inv1);
        }
    }
}

// ---------------------------------------------------------------------------

extern "C" void kernel_launch(void* const* d_in, const int* in_sizes, int n_in,
                              void* d_out, int out_size)
{
    const float* x  = (const float*)d_in[0];
    const float* Wq = (const float*)d_in[1];
    const float* Wk = (const float*)d_in[2];
    const float* Wv = (const float*)d_in[3];
    const float* Wo = (const float*)d_in[4];
    const float* bo = (const float*)d_in[5];
    float* out = (float*)d_out;

    float *ctx;
    __nv_bfloat16 *ahi, *alo, *wthi, *wtlo, *qh, *ql, *kh, *kl, *vh, *vl;
    cudaGetSymbolAddress((void**)&ctx,  g_ctx);
    cudaGetSymbolAddress((void**)&ahi,  g_ahi);
    cudaGetSymbolAddress((void**)&alo,  g_alo);
    cudaGetSymbolAddress((void**)&wthi, g_wthi);
    cudaGetSymbolAddress((void**)&wtlo, g_wtlo);
    cudaGetSymbolAddress((void**)&qh,   g_qh);
    cudaGetSymbolAddress((void**)&ql,   g_ql);
    cudaGetSymbolAddress((void**)&kh,   g_kh);
    cudaGetSymbolAddress((void**)&kl,   g_kl);
    cudaGetSymbolAddress((void**)&vh,   g_vh);
    cudaGetSymbolAddress((void**)&vl,   g_vl);

    // 1. split X into bf16 hi/lo
    split_kernel<<<1024, 256>>>((const float4*)x, ahi, alo, MM*DD/4);

    // 2. transpose+split all 4 weights (one launch)
    transpose_split_kernel<<<dim3(32,32,4), dim3(32,8)>>>(Wq, Wk, Wv, Wo, wthi, wtlo);

    // 3. fused Q/K/V projections (HMMA), emitting bf16 hi/lo head-major
    mma_gemm_qkv<<<dim3(24, 32), 256>>>(ahi, alo, wthi, wtlo, qh, ql, kh, kl, vh, vl);

    // 4. attention (HMMA flash, balanced pairs)
    attn_mma<<<dim3(8, BB*HH), 256>>>(qh, ql, kh, kl, vh, vl, ctx);

    // 5. split ctx, output projection + bias
    split_kernel<<<1024, 256>>>((const float4*)ctx, ahi, alo, MM*DD/4);
    mma_gemm_out<<<dim3(8, 32), 256>>>(ahi, alo, wthi + 3*(size_t)DD*DD, wtlo + 3*(size_t)DD*DD, out, bo);
}

// round 7
// speedup vs baseline: 2.9505x; 1.0047x over previous
#include <cuda_runtime.h>
#include <cuda_bf16.h>
#include <cstdint>

#define BB 2
#define SS 2048
#define DD 1024
#define HH 16
#define HD 64
#define MM (BB*SS)     // 4096

// ---------------- device scratch (no allocation allowed) -------------------
__device__ __nv_bfloat16 g_ahi[MM*DD];
__device__ __nv_bfloat16 g_alo[MM*DD];
__device__ __nv_bfloat16 g_wthi[4][DD*DD];
__device__ __nv_bfloat16 g_wtlo[4][DD*DD];
__device__ __nv_bfloat16 g_qh[BB*HH*SS*HD];
__device__ __nv_bfloat16 g_ql[BB*HH*SS*HD];
__device__ __nv_bfloat16 g_kh[BB*HH*SS*HD];
__device__ __nv_bfloat16 g_kl[BB*HH*SS*HD];
__device__ __nv_bfloat16 g_vh[BB*HH*SS*HD];
__device__ __nv_bfloat16 g_vl[BB*HH*SS*HD];

// ---------------- prepass: fp32 -> bf16 hi/lo split -------------------------
__global__ __launch_bounds__(256)
void split_kernel(const float4* __restrict__ X, __nv_bfloat16* __restrict__ Hi,
                  __nv_bfloat16* __restrict__ Lo, int n4)
{
    union U { __nv_bfloat16 b[4]; uint64_t u; };
    for (int i = blockIdx.x * blockDim.x + threadIdx.x; i < n4;
         i += gridDim.x * blockDim.x) {
        float4 f = X[i];
        U h, l;
        float vf[4] = {f.x, f.y, f.z, f.w};
        #pragma unroll
        for (int j = 0; j < 4; ++j) {
            __nv_bfloat16 hb = __float2bfloat16(vf[j]);
            h.b[j] = hb;
            l.b[j] = __float2bfloat16(vf[j] - __bfloat162float(hb));
        }
        ((uint64_t*)Hi)[i] = h.u;
        ((uint64_t*)Lo)[i] = l.u;
    }
}

// ---------------- prepass: 4x W[k][n] -> Wt[n][k] hi/lo split ----------------
__global__ __launch_bounds__(256)
void transpose_split_kernel(const float* __restrict__ W0, const float* __restrict__ W1,
                            const float* __restrict__ W2, const float* __restrict__ W3,
                            __nv_bfloat16* __restrict__ Th,
                            __nv_bfloat16* __restrict__ Tl)
{
    __shared__ float tile[32][33];
    const float* Ws[4] = {W0, W1, W2, W3};
    const float* W = Ws[blockIdx.z];
    __nv_bfloat16* th = Th + (size_t)blockIdx.z * DD * DD;
    __nv_bfloat16* tl = Tl + (size_t)blockIdx.z * DD * DD;
    int tx = threadIdx.x, ty = threadIdx.y;
    int x = blockIdx.x * 32 + tx;
    #pragma unroll
    for (int i = 0; i < 4; ++i) {
        int y = blockIdx.y * 32 + ty + i * 8;
        tile[ty + i * 8][tx] = W[(size_t)y * DD + x];
    }
    __syncthreads();
    int xo = blockIdx.y * 32 + tx;
    #pragma unroll
    for (int i = 0; i < 4; ++i) {
        int yo = blockIdx.x * 32 + ty + i * 8;
        float v = tile[tx][ty + i * 8];
        __nv_bfloat16 hb = __float2bfloat16(v);
        th[(size_t)yo * DD + xo] = hb;
        tl[(size_t)yo * DD + xo] = __float2bfloat16(v - __bfloat162float(hb));
    }
}

// ---------------- mma.sync / cp.async helpers --------------------------------
__device__ __forceinline__ uint32_t smem_u32(const void* p) {
    uint32_t a;
    asm("{ .reg .u64 t; cvta.to.shared.u64 t, %1; cvt.u32.u64 %0, t; }"
        : "=r"(a) : "l"(p));
    return a;
}
__device__ __forceinline__ void ldmx4(uint32_t* r, uint32_t addr) {
    asm volatile("ldmatrix.sync.aligned.m8n8.x4.shared.b16 {%0,%1,%2,%3}, [%4];"
                 : "=r"(r[0]), "=r"(r[1]), "=r"(r[2]), "=r"(r[3]) : "r"(addr));
}
__device__ __forceinline__ void ldmx4t(uint32_t* r, uint32_t addr) {
    asm volatile("ldmatrix.sync.aligned.m8n8.x4.trans.shared.b16 {%0,%1,%2,%3}, [%4];"
                 : "=r"(r[0]), "=r"(r[1]), "=r"(r[2]), "=r"(r[3]) : "r"(addr));
}
__device__ __forceinline__ void mma_bf16(float* c, const uint32_t* a,
                                         uint32_t b0, uint32_t b1) {
    asm volatile(
        "mma.sync.aligned.m16n8k16.row.col.f32.bf16.bf16.f32 "
        "{%0,%1,%2,%3}, {%4,%5,%6,%7}, {%8,%9}, {%0,%1,%2,%3};"
        : "+f"(c[0]), "+f"(c[1]), "+f"(c[2]), "+f"(c[3])
        : "r"(a[0]), "r"(a[1]), "r"(a[2]), "r"(a[3]), "r"(b0), "r"(b1));
}
__device__ __forceinline__ float ex2f(float x) {
    float y; asm("ex2.approx.f32 %0, %1;" : "=f"(y) : "f"(x)); return y;
}
__device__ __forceinline__ uint32_t pack2(__nv_bfloat16 a, __nv_bfloat16 b) {
    __nv_bfloat162 t = __halves2bfloat162(a, b);
    return *(uint32_t*)&t;
}
__device__ __forceinline__ uint32_t pack_bf16x2(float a, float b) {
    return pack2(__float2bfloat16(a), __float2bfloat16(b));
}
__device__ __forceinline__ void cpa16(uint32_t dst, const void* src) {
    asm volatile("cp.async.cg.shared.global [%0], [%1], 16;" :: "r"(dst), "l"(src));
}
__device__ __forceinline__ void cpa_commit() {
    asm volatile("cp.async.commit_group;" ::: "memory");
}
template<int N> __device__ __forceinline__ void cpa_wait() {
    asm volatile("cp.async.wait_group %0;" :: "n"(N) : "memory");
}

// ---------------- HMMA GEMM core --------------------------------------------
#define AST 40
#define NTILES 96

struct GemmAcc { float acc[2][8][4]; };

template<typename EPI>
__device__ __forceinline__ void gemm_core(
    const __nv_bfloat16* Ahi, const __nv_bfloat16* Alo,
    const __nv_bfloat16* Bhi, const __nv_bfloat16* Blo,
    int m0, int n0, EPI epi)
{
    __shared__ __nv_bfloat16 sA[2][128*AST];
    __shared__ __nv_bfloat16 sB[2][128*AST];

    const int tid  = threadIdx.x;
    const int wid  = tid >> 5;
    const int lane = tid & 31;
    const int wm0 = (wid & 3) * 32;
    const int wn0 = (wid >> 2) * 64;

    const uint64_t* As[3] = {(const uint64_t*)Ahi, (const uint64_t*)Ahi, (const uint64_t*)Alo};
    const uint64_t* Bs[3] = {(const uint64_t*)Bhi, (const uint64_t*)Blo, (const uint64_t*)Bhi};

    const int ldrow[4] = { (tid + 0*256) >> 3, (tid + 1*256) >> 3,
                           (tid + 2*256) >> 3, (tid + 3*256) >> 3 };
    const int ldc = tid & 7;

    const uint32_t baseA = smem_u32(&sA[0][0]);
    const uint32_t baseB = smem_u32(&sB[0][0]);
    const uint32_t bufStride = 128 * AST * 2;
    uint32_t aoff[2], boff[4];
    #pragma unroll
    for (int mf = 0; mf < 2; ++mf)
        aoff[mf] = ((wm0 + mf*16 + (lane & 15)) * AST + (lane >> 4) * 8) * 2;
    #pragma unroll
    for (int np = 0; np < 4; ++np)
        boff[np] = ((wn0 + np*16 + ((lane >> 4) & 1) * 8 + (lane & 7)) * AST
                    + ((lane >> 3) & 1) * 8) * 2;

    GemmAcc A = {};
    uint64_t ra[4], rb[4];

    auto ldg = [&](int t) {
        const int seg = t >> 5;
        const int kc  = (t & 31) * 8;
        const uint64_t* Ag = As[seg];
        const uint64_t* Bg = Bs[seg];
        #pragma unroll
        for (int i = 0; i < 4; ++i) {
            ra[i] = Ag[(size_t)(m0 + ldrow[i]) * 256 + kc + ldc];
            rb[i] = Bg[(size_t)(n0 + ldrow[i]) * 256 + kc + ldc];
        }
    };
    auto sts = [&](int buf) {
        #pragma unroll
        for (int i = 0; i < 4; ++i) {
            *(uint64_t*)&sA[buf][ldrow[i]*AST + ldc*4] = ra[i];
            *(uint64_t*)&sB[buf][ldrow[i]*AST + ldc*4] = rb[i];
        }
    };
    auto compute = [&](int buf) {
        const uint32_t bA = baseA + buf * bufStride;
        const uint32_t bB = baseB + buf * bufStride;
        #pragma unroll
        for (int ks = 0; ks < 32; ks += 16) {
            uint32_t af[2][4], bf[4][4];
            #pragma unroll
            for (int mf = 0; mf < 2; ++mf) ldmx4(af[mf], bA + aoff[mf] + ks*2);
            #pragma unroll
            for (int np = 0; np < 4; ++np) ldmx4(bf[np], bB + boff[np] + ks*2);
            #pragma unroll
            for (int mf = 0; mf < 2; ++mf)
                #pragma unroll
                for (int np = 0; np < 4; ++np) {
                    mma_bf16(A.acc[mf][np*2+0], af[mf], bf[np][0], bf[np][1]);
                    mma_bf16(A.acc[mf][np*2+1], af[mf], bf[np][2], bf[np][3]);
                }
        }
    };

    ldg(0); sts(0);
    __syncthreads();
    for (int t = 0; t < NTILES; ++t) {
        const int buf = t & 1;
        if (t + 1 < NTILES) ldg(t + 1);
        compute(buf);
        if (t + 1 < NTILES) sts(buf ^ 1);
        __syncthreads();
    }

    const int qrow = lane >> 2;
    const int qcol = (lane & 3) * 2;
    #pragma unroll
    for (int mf = 0; mf < 2; ++mf)
        #pragma unroll
        for (int nf = 0; nf < 8; ++nf)
            #pragma unroll
            for (int half = 0; half < 2; ++half) {
                const int m = m0 + wm0 + mf*16 + qrow + half*8;
                const int n = n0 + wn0 + nf*8 + qcol;
                epi(m, n, A.acc[mf][nf][half*2 + 0], A.acc[mf][nf][half*2 + 1]);
            }
}

// fused QKV projection: grid.x = 24 (gemm = x>>3), grid.y = 32
__global__ __launch_bounds__(256, 2)
void mma_gemm_qkv(const __nv_bfloat16* __restrict__ Ahi, const __nv_bfloat16* __restrict__ Alo,
                  const __nv_bfloat16* __restrict__ Whi, const __nv_bfloat16* __restrict__ Wlo,
                  __nv_bfloat16* __restrict__ qh, __nv_bfloat16* __restrict__ ql,
                  __nv_bfloat16* __restrict__ kh, __nv_bfloat16* __restrict__ kl,
                  __nv_bfloat16* __restrict__ vh, __nv_bfloat16* __restrict__ vl)
{
    const int g  = blockIdx.x >> 3;
    const int n0 = (blockIdx.x & 7) * 128;
    const int m0 = blockIdx.y * 128;
    const __nv_bfloat16* Bhi = Whi + (size_t)g * DD * DD;
    const __nv_bfloat16* Blo = Wlo + (size_t)g * DD * DD;
    __nv_bfloat16* Yh = (g == 0) ? qh : (g == 1) ? kh : vh;
    __nv_bfloat16* Yl = (g == 0) ? ql : (g == 1) ? kl : vl;

    gemm_core(Ahi, Alo, Bhi, Blo, m0, n0,
        [&](int m, int n, float cx, float cy) {
            const int b = m >> 11, s = m & (SS - 1);
            const int h = n >> 6, hd = n & 63;
            const size_t off = (((size_t)b*HH + h)*SS + s)*HD + hd;
            __nv_bfloat16 hx = __float2bfloat16(cx);
            __nv_bfloat16 hy = __float2bfloat16(cy);
            *(uint32_t*)(Yh + off) = pack2(hx, hy);
            *(uint32_t*)(Yl + off) = pack_bf16x2(
                cx - __bfloat162float(hx), cy - __bfloat162float(hy));
        });
}

// output projection + bias
__global__ __launch_bounds__(256, 2)
void mma_gemm_out(const __nv_bfloat16* __restrict__ Ahi, const __nv_bfloat16* __restrict__ Alo,
                  const __nv_bfloat16* __restrict__ Bhi, const __nv_bfloat16* __restrict__ Blo,
                  float* __restrict__ Yf, const float* __restrict__ bias)
{
    const int n0 = blockIdx.x * 128;
    const int m0 = blockIdx.y * 128;
    gemm_core(Ahi, Alo, Bhi, Blo, m0, n0,
        [&](int m, int n, float cx, float cy) {
            float2* dst = (float2*)(Yf + (size_t)m * DD + n);
            *dst = make_float2(cx + bias[n], cy + bias[n + 1]);
        });
}

// ---------------- HMMA flash attention --------------------------------------
// grid (8, 32): CTA processes q-tiles blockIdx.x and 15-blockIdx.x (balance).
// cp.async double-buffered K/V (2 stages x 4 tiles of 64x64 bf16).
// Epilogue writes ctx directly as bf16 hi/lo into the out-GEMM A operand.
#define KST 72
#define STAGE (4*64*KST*2)           // 36864 B
#define ATTN_SMEM (2*STAGE)          // 73728 B
#define LOG2E 1.4426950408889634f

__global__ __launch_bounds__(256, 2)
void attn_mma(const __nv_bfloat16* __restrict__ Qh, const __nv_bfloat16* __restrict__ Ql,
              const __nv_bfloat16* __restrict__ Kh, const __nv_bfloat16* __restrict__ Kl,
              const __nv_bfloat16* __restrict__ Vh, const __nv_bfloat16* __restrict__ Vl,
              __nv_bfloat16* __restrict__ Chi, __nv_bfloat16* __restrict__ Clo)
{
    extern __shared__ __align__(16) char dynsm[];
    __nv_bfloat16* sm = (__nv_bfloat16*)dynsm;

    const int bh  = blockIdx.y;
    const int tid = threadIdx.x;
    const int wid = tid >> 5;
    const int lane = tid & 31;
    const int wrow0 = wid * 16;

    const size_t hbase = (size_t)bh * SS * HD;
    const uint4* Kh4 = (const uint4*)(Kh + hbase);
    const uint4* Kl4 = (const uint4*)(Kl + hbase);
    const uint4* Vh4 = (const uint4*)(Vh + hbase);
    const uint4* Vl4 = (const uint4*)(Vl + hbase);

    const uint32_t sbase = smem_u32(sm);

    uint32_t kbase[4];
    #pragma unroll
    for (int ng = 0; ng < 4; ++ng) {
        int krow = ng*16 + ((lane >> 4) & 1)*8 + (lane & 7);
        kbase[ng] = (krow * KST + ((lane >> 3) & 1) * 8) * 2;
    }
    const uint32_t vrowoff = ((((lane >> 3) & 1)*8 + (lane & 7)) * KST) * 2;
    uint32_t vcol[4];
    #pragma unroll
    for (int ng = 0; ng < 4; ++ng)
        vcol[ng] = (ng*16 + (lane >> 4) * 8) * 2;

    // per-thread cp.async slots: idx = tid + i*256, i in 0..7
    // tile = idx>>9 (Kh,Kl,Vh,Vl), within = idx&511, row = within>>3, c = within&7
    uint32_t cpa_dst[8];
    int cpa_src[8];
    #pragma unroll
    for (int i = 0; i < 8; ++i) {
        int idx = tid + i * 256;
        int tile = idx >> 9;
        int within = idx & 511;
        int row = within >> 3, c = within & 7;
        cpa_dst[i] = sbase + ((tile*64 + row)*KST + c*8) * 2;
        cpa_src[i] = within;     // uint4 index within the 64x64 tile
    }

    auto issue = [&](int kt) {
        const uint4* srcs[4] = {Kh4 + kt*512, Kl4 + kt*512, Vh4 + kt*512, Vl4 + kt*512};
        const uint32_t soff = (kt & 1) * STAGE;
        #pragma unroll
        for (int i = 0; i < 8; ++i) {
            int tile = (tid + i*256) >> 9;
            cpa16(cpa_dst[i] + soff, srcs[tile] + cpa_src[i]);
        }
        cpa_commit();
    };

    #pragma unroll 1
    for (int half = 0; half < 2; ++half) {
        const int qi = half ? (15 - blockIdx.x) : blockIdx.x;

        __syncthreads();
        // ---- stage Q (128x64 hi + lo) into stage-0 smem, ldmatrix to regs ----
        {
            const uint4* Qh4 = (const uint4*)(Qh + hbase + (size_t)qi*128*HD);
            const uint4* Ql4 = (const uint4*)(Ql + hbase + (size_t)qi*128*HD);
            const uint4* bufs[2] = {Qh4, Ql4};
            #pragma unroll
            for (int i = 0; i < 8; ++i) {
                int idx = tid + i * 256;
                int buf = idx >> 10;
                int within = idx & 1023;
                int row = within >> 3, c = within & 7;
                uint4 v = bufs[buf][within];
                *(uint4*)&sm[(buf*128 + row)*KST + c*8] = v;
            }
        }
        __syncthreads();

        uint32_t qhf[4][4], qlf[4][4];
        {
            const uint32_t roff = ((wrow0 + (lane & 15)) * KST + (lane >> 4) * 8) * 2;
            #pragma unroll
            for (int ks = 0; ks < 4; ++ks) {
                ldmx4(qhf[ks], sbase + roff + ks * 32);
                ldmx4(qlf[ks], sbase + roff + 128*KST*2 + ks * 32);
            }
        }
        __syncthreads();

        float mrow[2] = {-1e30f, -1e30f};
        float lrow[2] = {0.0f, 0.0f};
        float o[8][4] = {};

        const int wmax = qi*128 + wrow0 + 15;
        const int nsteps = 2*qi + 2;

        issue(0);
        for (int kt = 0; kt < nsteps; ++kt) {
            if (kt + 1 < nsteps) { issue(kt + 1); cpa_wait<1>(); }
            else                 { cpa_wait<0>(); }
            __syncthreads();

            const uint32_t st = sbase + (kt & 1) * STAGE;
            const uint32_t sKh = st;
            const uint32_t sKl = st + 64*KST*2;
            const uint32_t sVh = st + 128*KST*2;
            const uint32_t sVl = st + 192*KST*2;

            if (kt*64 <= wmax) {
                float s[8][4] = {};
                #pragma unroll
                for (int ks = 0; ks < 4; ++ks) {
                    uint32_t khb[4][4], klb[4][4];
                    #pragma unroll
                    for (int ng = 0; ng < 4; ++ng) {
                        ldmx4(khb[ng], sKh + kbase[ng] + ks*32);
                        ldmx4(klb[ng], sKl + kbase[ng] + ks*32);
                    }
                    #pragma unroll
                    for (int ng = 0; ng < 4; ++ng) {
                        mma_bf16(s[2*ng+0], qhf[ks], khb[ng][0], khb[ng][1]);
                        mma_bf16(s[2*ng+1], qhf[ks], khb[ng][2], khb[ng][3]);
                        mma_bf16(s[2*ng+0], qhf[ks], klb[ng][0], klb[ng][1]);
                        mma_bf16(s[2*ng+1], qhf[ks], klb[ng][2], klb[ng][3]);
                        mma_bf16(s[2*ng+0], qlf[ks], khb[ng][0], khb[ng][1]);
                        mma_bf16(s[2*ng+1], qlf[ks], khb[ng][2], khb[ng][3]);
                    }
                }

                const int r0g = qi*128 + wrow0 + (lane >> 2);
                const bool needmask = (kt*64 + 63 > qi*128 + wrow0);
                #pragma unroll
                for (int nf = 0; nf < 8; ++nf)
                    #pragma unroll
                    for (int ri = 0; ri < 4; ++ri) {
                        float v = s[nf][ri] * 0.125f;
                        if (needmask) {
                            int col = kt*64 + nf*8 + (lane & 3)*2 + (ri & 1);
                            int rg  = r0g + ((ri >> 1) ? 8 : 0);
                            if (col > rg) v = -1e30f;
                        }
                        s[nf][ri] = v;
                    }

                float alpha[2];
                #pragma unroll
                for (int h = 0; h < 2; ++h) {
                    float t = -1e30f;
                    #pragma unroll
                    for (int nf = 0; nf < 8; ++nf)
                        t = fmaxf(t, fmaxf(s[nf][h*2], s[nf][h*2+1]));
                    t = fmaxf(t, __shfl_xor_sync(0xffffffffu, t, 1));
                    t = fmaxf(t, __shfl_xor_sync(0xffffffffu, t, 2));
                    float nm = fmaxf(mrow[h], t);
                    alpha[h] = ex2f((mrow[h] - nm) * LOG2E);
                    mrow[h] = nm;
                }
                float rs[2] = {0.0f, 0.0f};
                #pragma unroll
                for (int nf = 0; nf < 8; ++nf)
                    #pragma unroll
                    for (int ri = 0; ri < 4; ++ri) {
                        int h = ri >> 1;
                        float p = ex2f((s[nf][ri] - mrow[h]) * LOG2E);
                        s[nf][ri] = p;
                        rs[h] += p;
                    }
                #pragma unroll
                for (int h = 0; h < 2; ++h) {
                    rs[h] += __shfl_xor_sync(0xffffffffu, rs[h], 1);
                    rs[h] += __shfl_xor_sync(0xffffffffu, rs[h], 2);
                    lrow[h] = lrow[h] * alpha[h] + rs[h];
                }
                #pragma unroll
                for (int nf = 0; nf < 8; ++nf) {
                    o[nf][0] *= alpha[0]; o[nf][1] *= alpha[0];
                    o[nf][2] *= alpha[1]; o[nf][3] *= alpha[1];
                }

                uint32_t pah[4][4], pal[4][4];
                #pragma unroll
                for (int ks = 0; ks < 4; ++ks) {
                    float a0 = s[2*ks][0],   a1 = s[2*ks][1];
                    float b0 = s[2*ks][2],   b1 = s[2*ks][3];
                    float c0 = s[2*ks+1][0], c1 = s[2*ks+1][1];
                    float d0 = s[2*ks+1][2], d1 = s[2*ks+1][3];
                    __nv_bfloat16 ha0 = __float2bfloat16(a0), ha1 = __float2bfloat16(a1);
                    __nv_bfloat16 hb0 = __float2bfloat16(b0), hb1 = __float2bfloat16(b1);
                    __nv_bfloat16 hc0 = __float2bfloat16(c0), hc1 = __float2bfloat16(c1);
                    __nv_bfloat16 hd0 = __float2bfloat16(d0), hd1 = __float2bfloat16(d1);
                    pah[ks][0] = pack2(ha0, ha1);
                    pah[ks][1] = pack2(hb0, hb1);
                    pah[ks][2] = pack2(hc0, hc1);
                    pah[ks][3] = pack2(hd0, hd1);
                    pal[ks][0] = pack_bf16x2(a0 - __bfloat162float(ha0), a1 - __bfloat162float(ha1));
                    pal[ks][1] = pack_bf16x2(b0 - __bfloat162float(hb0), b1 - __bfloat162float(hb1));
                    pal[ks][2] = pack_bf16x2(c0 - __bfloat162float(hc0), c1 - __bfloat162float(hc1));
                    pal[ks][3] = pack_bf16x2(d0 - __bfloat162float(hd0), d1 - __bfloat162float(hd1));
                }

                #pragma unroll
                for (int ks = 0; ks < 4; ++ks) {
                    const uint32_t vrb = vrowoff + ks*16*KST*2;
                    #pragma unroll
                    for (int ng = 0; ng < 4; ++ng) {
                        uint32_t vhb[4], vlb[4];
                        ldmx4t(vhb, sVh + vrb + vcol[ng]);
                        ldmx4t(vlb, sVl + vrb + vcol[ng]);
                        mma_bf16(o[2*ng+0], pah[ks], vhb[0], vhb[1]);
                        mma_bf16(o[2*ng+1], pah[ks], vhb[2], vhb[3]);
                        mma_bf16(o[2*ng+0], pah[ks], vlb[0], vlb[1]);
                        mma_bf16(o[2*ng+1], pah[ks], vlb[2], vlb[3]);
                        mma_bf16(o[2*ng+0], pal[ks], vhb[0], vhb[1]);
                        mma_bf16(o[2*ng+1], pal[ks], vhb[2], vhb[3]);
                    }
                }
            }
            __syncthreads();
        }

        // ---- epilogue: write ctx as bf16 hi/lo (row-major [M][D]) ----
        const float inv0 = 1.0f / lrow[0];
        const float inv1 = 1.0f / lrow[1];
        const int b = bh >> 4, h = bh & 15;
        const int r0 = qi*128 + wrow0 + (lane >> 2);
        #pragma unroll
        for (int nf = 0; nf < 8; ++nf) {
            const int col = h*HD + nf*8 + (lane & 3)*2;
            const size_t off0 = ((size_t)b*SS + r0)*DD + col;
            const size_t off1 = ((size_t)b*SS + r0 + 8)*DD + col;
            float x0 = o[nf][0]*inv0, y0 = o[nf][1]*inv0;
            float x1 = o[nf][2]*inv1, y1 = o[nf][3]*inv1;
            __nv_bfloat16 hx0 = __float2bfloat16(x0), hy0 = __float2bfloat16(y0);
            __nv_bfloat16 hx1 = __float2bfloat16(x1), hy1 = __float2bfloat16(y1);
            *(uint32_t*)(Chi + off0) = pack2(hx0, hy0);
            *(uint32_t*)(Chi + off1) = pack2(hx1, hy1);
            *(uint32_t*)(Clo + off0) = pack_bf16x2(x0 - __bfloat162float(hx0),
                                                   y0 - __bfloat162float(hy0));
            *(uint32_t*)(Clo + off1) = pack_bf16x2(x1 - __bfloat162float(hx1),
                                                   y1 - __bfloat162float(hy1));
        }
    }
}

// ---------------------------------------------------------------------------

extern "C" void kernel_launch(void* const* d_in, const int* in_sizes, int n_in,
                              void* d_out, int out_size)
{
    const float* x  = (const float*)d_in[0];
    const float* Wq = (const float*)d_in[1];
    const float* Wk = (const float*)d_in[2];
    const float* Wv = (const float*)d_in[3];
    const float* Wo = (const float*)d_in[4];
    const float* bo = (const float*)d_in[5];
    float* out = (float*)d_out;

    __nv_bfloat16 *ahi, *alo, *wthi, *wtlo, *qh, *ql, *kh, *kl, *vh, *vl;
    cudaGetSymbolAddress((void**)&ahi,  g_ahi);
    cudaGetSymbolAddress((void**)&alo,  g_alo);
    cudaGetSymbolAddress((void**)&wthi, g_wthi);
    cudaGetSymbolAddress((void**)&wtlo, g_wtlo);
    cudaGetSymbolAddress((void**)&qh,   g_qh);
    cudaGetSymbolAddress((void**)&ql,   g_ql);
    cudaGetSymbolAddress((void**)&kh,   g_kh);
    cudaGetSymbolAddress((void**)&kl,   g_kl);
    cudaGetSymbolAddress((void**)&vh,   g_vh);
    cudaGetSymbolAddress((void**)&vl,   g_vl);

    cudaFuncSetAttribute(attn_mma, cudaFuncAttributeMaxDynamicSharedMemorySize, ATTN_SMEM);

    // 1. split X into bf16 hi/lo
    split_kernel<<<1024, 256>>>((const float4*)x, ahi, alo, MM*DD/4);

    // 2. transpose+split all 4 weights (one launch)
    transpose_split_kernel<<<dim3(32,32,4), dim3(32,8)>>>(Wq, Wk, Wv, Wo, wthi, wtlo);

    // 3. fused Q/K/V projections (HMMA), emitting bf16 hi/lo head-major
    mma_gemm_qkv<<<dim3(24, 32), 256>>>(ahi, alo, wthi, wtlo, qh, ql, kh, kl, vh, vl);

    // 4. attention (HMMA flash, balanced pairs, cp.async pipeline)
    //    writes ctx straight into ahi/alo (x-split no longer needed)
    attn_mma<<<dim3(8, BB*HH), 256, ATTN_SMEM>>>(qh, ql, kh, kl, vh, vl, ahi, alo);

    // 5. output projection + bias
    mma_gemm_out<<<dim3(8, 32), 256>>>(ahi, alo, wthi + 3*(size_t)DD*DD, wtlo + 3*(size_t)DD*DD, out, bo);
}

// round 8
// speedup vs baseline: 3.3563x; 1.1375x over previous
#include <cuda_runtime.h>
#include <cuda_bf16.h>
#include <cstdint>

#define BB 2
#define SS 2048
#define DD 1024
#define HH 16
#define HD 64
#define MM (BB*SS)     // 4096

// ---------------- device scratch (no allocation allowed) -------------------
__device__ __nv_bfloat16 g_ahi[MM*DD];
__device__ __nv_bfloat16 g_alo[MM*DD];
__device__ __nv_bfloat16 g_wthi[4][DD*DD];
__device__ __nv_bfloat16 g_wtlo[4][DD*DD];
__device__ __nv_bfloat16 g_qh[BB*HH*SS*HD];
__device__ __nv_bfloat16 g_ql[BB*HH*SS*HD];
__device__ __nv_bfloat16 g_kh[BB*HH*SS*HD];
__device__ __nv_bfloat16 g_kl[BB*HH*SS*HD];
__device__ __nv_bfloat16 g_vh[BB*HH*SS*HD];
__device__ __nv_bfloat16 g_vl[BB*HH*SS*HD];

// ---------------- prepass: fp32 -> bf16 hi/lo split -------------------------
__global__ __launch_bounds__(256)
void split_kernel(const float4* __restrict__ X, __nv_bfloat16* __restrict__ Hi,
                  __nv_bfloat16* __restrict__ Lo, int n4)
{
    union U { __nv_bfloat16 b[4]; uint64_t u; };
    for (int i = blockIdx.x * blockDim.x + threadIdx.x; i < n4;
         i += gridDim.x * blockDim.x) {
        float4 f = X[i];
        U h, l;
        float vf[4] = {f.x, f.y, f.z, f.w};
        #pragma unroll
        for (int j = 0; j < 4; ++j) {
            __nv_bfloat16 hb = __float2bfloat16(vf[j]);
            h.b[j] = hb;
            l.b[j] = __float2bfloat16(vf[j] - __bfloat162float(hb));
        }
        ((uint64_t*)Hi)[i] = h.u;
        ((uint64_t*)Lo)[i] = l.u;
    }
}

// ---------------- prepass: 4x W[k][n] -> Wt[n][k] hi/lo split ----------------
__global__ __launch_bounds__(256)
void transpose_split_kernel(const float* __restrict__ W0, const float* __restrict__ W1,
                            const float* __restrict__ W2, const float* __restrict__ W3,
                            __nv_bfloat16* __restrict__ Th,
                            __nv_bfloat16* __restrict__ Tl)
{
    __shared__ float tile[32][33];
    const float* Ws[4] = {W0, W1, W2, W3};
    const float* W = Ws[blockIdx.z];
    __nv_bfloat16* th = Th + (size_t)blockIdx.z * DD * DD;
    __nv_bfloat16* tl = Tl + (size_t)blockIdx.z * DD * DD;
    int tx = threadIdx.x, ty = threadIdx.y;
    int x = blockIdx.x * 32 + tx;
    #pragma unroll
    for (int i = 0; i < 4; ++i) {
        int y = blockIdx.y * 32 + ty + i * 8;
        tile[ty + i * 8][tx] = W[(size_t)y * DD + x];
    }
    __syncthreads();
    int xo = blockIdx.y * 32 + tx;
    #pragma unroll
    for (int i = 0; i < 4; ++i) {
        int yo = blockIdx.x * 32 + ty + i * 8;
        float v = tile[tx][ty + i * 8];
        __nv_bfloat16 hb = __float2bfloat16(v);
        th[(size_t)yo * DD + xo] = hb;
        tl[(size_t)yo * DD + xo] = __float2bfloat16(v - __bfloat162float(hb));
    }
}

// ---------------- mma.sync / cp.async helpers --------------------------------
__device__ __forceinline__ uint32_t smem_u32(const void* p) {
    uint32_t a;
    asm("{ .reg .u64 t; cvta.to.shared.u64 t, %1; cvt.u32.u64 %0, t; }"
        : "=r"(a) : "l"(p));
    return a;
}
__device__ __forceinline__ void ldmx4(uint32_t* r, uint32_t addr) {
    asm volatile("ldmatrix.sync.aligned.m8n8.x4.shared.b16 {%0,%1,%2,%3}, [%4];"
                 : "=r"(r[0]), "=r"(r[1]), "=r"(r[2]), "=r"(r[3]) : "r"(addr));
}
__device__ __forceinline__ void ldmx4t(uint32_t* r, uint32_t addr) {
    asm volatile("ldmatrix.sync.aligned.m8n8.x4.trans.shared.b16 {%0,%1,%2,%3}, [%4];"
                 : "=r"(r[0]), "=r"(r[1]), "=r"(r[2]), "=r"(r[3]) : "r"(addr));
}
__device__ __forceinline__ void mma_bf16(float* c, const uint32_t* a,
                                         uint32_t b0, uint32_t b1) {
    asm volatile(
        "mma.sync.aligned.m16n8k16.row.col.f32.bf16.bf16.f32 "
        "{%0,%1,%2,%3}, {%4,%5,%6,%7}, {%8,%9}, {%0,%1,%2,%3};"
        : "+f"(c[0]), "+f"(c[1]), "+f"(c[2]), "+f"(c[3])
        : "r"(a[0]), "r"(a[1]), "r"(a[2]), "r"(a[3]), "r"(b0), "r"(b1));
}
__device__ __forceinline__ float ex2f(float x) {
    float y; asm("ex2.approx.f32 %0, %1;" : "=f"(y) : "f"(x)); return y;
}
__device__ __forceinline__ uint32_t pack2(__nv_bfloat16 a, __nv_bfloat16 b) {
    __nv_bfloat162 t = __halves2bfloat162(a, b);
    return *(uint32_t*)&t;
}
__device__ __forceinline__ uint32_t pack_bf16x2(float a, float b) {
    __nv_bfloat162 t = __floats2bfloat162_rn(a, b);
    return *(uint32_t*)&t;
}
__device__ __forceinline__ void cpa16(uint32_t dst, const void* src) {
    asm volatile("cp.async.cg.shared.global [%0], [%1], 16;" :: "r"(dst), "l"(src));
}
__device__ __forceinline__ void cpa_commit() {
    asm volatile("cp.async.commit_group;" ::: "memory");
}
template<int N> __device__ __forceinline__ void cpa_wait() {
    asm volatile("cp.async.wait_group %0;" :: "n"(N) : "memory");
}

// ---------------- HMMA GEMM core (cp.async 3-stage) --------------------------
#define AST 40
#define NTILES 96
#define GSTAGE (128*AST*2)               // 10240 B per matrix per stage
#define GEMM_SMEM (3 * 2 * GSTAGE)       // 61440 B

template<typename EPI>
__device__ __forceinline__ void gemm_core(
    const __nv_bfloat16* Ahi, const __nv_bfloat16* Alo,
    const __nv_bfloat16* Bhi, const __nv_bfloat16* Blo,
    int m0, int n0, EPI epi)
{
    extern __shared__ __align__(16) char gsm[];
    const uint32_t baseA = smem_u32(gsm);
    const uint32_t baseB = baseA + 3*GSTAGE;

    const int tid  = threadIdx.x;
    const int wid  = tid >> 5;
    const int lane = tid & 31;
    const int wm0 = (wid & 3) * 32;
    const int wn0 = (wid >> 2) * 64;

    const uint4* As[3] = {(const uint4*)Ahi, (const uint4*)Ahi, (const uint4*)Alo};
    const uint4* Bs[3] = {(const uint4*)Bhi, (const uint4*)Blo, (const uint4*)Bhi};

    // copy mapping: chunk = tid + i*256 (i<2); row = chunk>>2, c4 = chunk&3
    int crow[2], cc4[2];
    #pragma unroll
    for (int i = 0; i < 2; ++i) { int c = tid + i*256; crow[i] = c >> 2; cc4[i] = c & 3; }

    auto issue = [&](int t) {
        const int seg = t >> 5;
        const int kc4 = (t & 31) * 4;            // uint4 offset within 128-uint4 row
        const uint32_t so = (t % 3) * GSTAGE;
        const uint4* Ag = As[seg];
        const uint4* Bg = Bs[seg];
        #pragma unroll
        for (int i = 0; i < 2; ++i) {
            const int row = crow[i], c4 = cc4[i];
            const uint32_t d = so + row*(AST*2) + c4*16;
            cpa16(baseA + d, Ag + (size_t)(m0+row)*128 + kc4 + c4);
            cpa16(baseB + d, Bg + (size_t)(n0+row)*128 + kc4 + c4);
        }
        cpa_commit();
    };

    uint32_t aoff[2], boff[4];
    #pragma unroll
    for (int mf = 0; mf < 2; ++mf)
        aoff[mf] = ((wm0 + mf*16 + (lane & 15)) * AST + (lane >> 4) * 8) * 2;
    #pragma unroll
    for (int np = 0; np < 4; ++np)
        boff[np] = ((wn0 + np*16 + ((lane >> 4) & 1) * 8 + (lane & 7)) * AST
                    + ((lane >> 3) & 1) * 8) * 2;

    float acc[2][8][4] = {};

    auto compute = [&](int stg) {
        const uint32_t bA = baseA + stg * GSTAGE;
        const uint32_t bB = baseB + stg * GSTAGE;
        #pragma unroll
        for (int ks = 0; ks < 32; ks += 16) {
            uint32_t af[2][4], bf[4][4];
            #pragma unroll
            for (int mf = 0; mf < 2; ++mf) ldmx4(af[mf], bA + aoff[mf] + ks*2);
            #pragma unroll
            for (int np = 0; np < 4; ++np) ldmx4(bf[np], bB + boff[np] + ks*2);
            #pragma unroll
            for (int mf = 0; mf < 2; ++mf)
                #pragma unroll
                for (int np = 0; np < 4; ++np) {
                    mma_bf16(acc[mf][np*2+0], af[mf], bf[np][0], bf[np][1]);
                    mma_bf16(acc[mf][np*2+1], af[mf], bf[np][2], bf[np][3]);
                }
        }
    };

    issue(0); issue(1);
    for (int t = 0; t < NTILES; ++t) {
        if (t + 1 < NTILES) cpa_wait<1>(); else cpa_wait<0>();
        __syncthreads();
        if (t + 2 < NTILES) issue(t + 2);
        compute(t % 3);
    }

    const int qrow = lane >> 2;
    const int qcol = (lane & 3) * 2;
    #pragma unroll
    for (int mf = 0; mf < 2; ++mf)
        #pragma unroll
        for (int nf = 0; nf < 8; ++nf)
            #pragma unroll
            for (int half = 0; half < 2; ++half) {
                const int m = m0 + wm0 + mf*16 + qrow + half*8;
                const int n = n0 + wn0 + nf*8 + qcol;
                epi(m, n, acc[mf][nf][half*2 + 0], acc[mf][nf][half*2 + 1]);
            }
}

// fused QKV projection: grid.x = 24 (gemm = x>>3), grid.y = 32
__global__ __launch_bounds__(256, 2)
void mma_gemm_qkv(const __nv_bfloat16* __restrict__ Ahi, const __nv_bfloat16* __restrict__ Alo,
                  const __nv_bfloat16* __restrict__ Whi, const __nv_bfloat16* __restrict__ Wlo,
                  __nv_bfloat16* __restrict__ qh, __nv_bfloat16* __restrict__ ql,
                  __nv_bfloat16* __restrict__ kh, __nv_bfloat16* __restrict__ kl,
                  __nv_bfloat16* __restrict__ vh, __nv_bfloat16* __restrict__ vl)
{
    const int g  = blockIdx.x >> 3;
    const int n0 = (blockIdx.x & 7) * 128;
    const int m0 = blockIdx.y * 128;
    const __nv_bfloat16* Bhi = Whi + (size_t)g * DD * DD;
    const __nv_bfloat16* Blo = Wlo + (size_t)g * DD * DD;
    __nv_bfloat16* Yh = (g == 0) ? qh : (g == 1) ? kh : vh;
    __nv_bfloat16* Yl = (g == 0) ? ql : (g == 1) ? kl : vl;

    gemm_core(Ahi, Alo, Bhi, Blo, m0, n0,
        [&](int m, int n, float cx, float cy) {
            const int b = m >> 11, s = m & (SS - 1);
            const int h = n >> 6, hd = n & 63;
            const size_t off = (((size_t)b*HH + h)*SS + s)*HD + hd;
            __nv_bfloat16 hx = __float2bfloat16(cx);
            __nv_bfloat16 hy = __float2bfloat16(cy);
            *(uint32_t*)(Yh + off) = pack2(hx, hy);
            *(uint32_t*)(Yl + off) = pack_bf16x2(
                cx - __bfloat162float(hx), cy - __bfloat162float(hy));
        });
}

// output projection + bias
__global__ __launch_bounds__(256, 2)
void mma_gemm_out(const __nv_bfloat16* __restrict__ Ahi, const __nv_bfloat16* __restrict__ Alo,
                  const __nv_bfloat16* __restrict__ Bhi, const __nv_bfloat16* __restrict__ Blo,
                  float* __restrict__ Yf, const float* __restrict__ bias)
{
    const int n0 = blockIdx.x * 128;
    const int m0 = blockIdx.y * 128;
    gemm_core(Ahi, Alo, Bhi, Blo, m0, n0,
        [&](int m, int n, float cx, float cy) {
            float2* dst = (float2*)(Yf + (size_t)m * DD + n);
            *dst = make_float2(cx + bias[n], cy + bias[n + 1]);
        });
}

// ---------------- HMMA flash attention --------------------------------------
#define KST 72
#define STAGE (4*64*KST*2)           // 36864 B
#define ATTN_SMEM (2*STAGE)          // 73728 B
#define LOG2E 1.4426950408889634f

__global__ __launch_bounds__(256, 2)
void attn_mma(const __nv_bfloat16* __restrict__ Qh, const __nv_bfloat16* __restrict__ Ql,
              const __nv_bfloat16* __restrict__ Kh, const __nv_bfloat16* __restrict__ Kl,
              const __nv_bfloat16* __restrict__ Vh, const __nv_bfloat16* __restrict__ Vl,
              __nv_bfloat16* __restrict__ Chi, __nv_bfloat16* __restrict__ Clo)
{
    extern __shared__ __align__(16) char dynsm[];
    __nv_bfloat16* sm = (__nv_bfloat16*)dynsm;

    const int bh  = blockIdx.y;
    const int tid = threadIdx.x;
    const int wid = tid >> 5;
    const int lane = tid & 31;
    const int wrow0 = wid * 16;

    const size_t hbase = (size_t)bh * SS * HD;
    const uint4* Kh4 = (const uint4*)(Kh + hbase);
    const uint4* Kl4 = (const uint4*)(Kl + hbase);
    const uint4* Vh4 = (const uint4*)(Vh + hbase);
    const uint4* Vl4 = (const uint4*)(Vl + hbase);

    const uint32_t sbase = smem_u32(sm);

    uint32_t kbase[4];
    #pragma unroll
    for (int ng = 0; ng < 4; ++ng) {
        int krow = ng*16 + ((lane >> 4) & 1)*8 + (lane & 7);
        kbase[ng] = (krow * KST + ((lane >> 3) & 1) * 8) * 2;
    }
    const uint32_t vrowoff = ((((lane >> 3) & 1)*8 + (lane & 7)) * KST) * 2;
    uint32_t vcol[4];
    #pragma unroll
    for (int ng = 0; ng < 4; ++ng)
        vcol[ng] = (ng*16 + (lane >> 4) * 8) * 2;

    uint32_t cpa_dst[8];
    int cpa_src[8];
    #pragma unroll
    for (int i = 0; i < 8; ++i) {
        int idx = tid + i * 256;
        int tile = idx >> 9;
        int within = idx & 511;
        int row = within >> 3, c = within & 7;
        cpa_dst[i] = sbase + ((tile*64 + row)*KST + c*8) * 2;
        cpa_src[i] = within;
    }

    auto issue = [&](int kt) {
        const uint4* srcs[4] = {Kh4 + kt*512, Kl4 + kt*512, Vh4 + kt*512, Vl4 + kt*512};
        const uint32_t soff = (kt & 1) * STAGE;
        #pragma unroll
        for (int i = 0; i < 8; ++i) {
            int tile = (tid + i*256) >> 9;
            cpa16(cpa_dst[i] + soff, srcs[tile] + cpa_src[i]);
        }
        cpa_commit();
    };

    #pragma unroll 1
    for (int half = 0; half < 2; ++half) {
        const int qi = half ? (15 - blockIdx.x) : blockIdx.x;

        __syncthreads();
        {
            const uint4* Qh4 = (const uint4*)(Qh + hbase + (size_t)qi*128*HD);
            const uint4* Ql4 = (const uint4*)(Ql + hbase + (size_t)qi*128*HD);
            const uint4* bufs[2] = {Qh4, Ql4};
            #pragma unroll
            for (int i = 0; i < 8; ++i) {
                int idx = tid + i * 256;
                int buf = idx >> 10;
                int within = idx & 1023;
                int row = within >> 3, c = within & 7;
                uint4 v = bufs[buf][within];
                *(uint4*)&sm[(buf*128 + row)*KST + c*8] = v;
            }
        }
        __syncthreads();

        uint32_t qhf[4][4], qlf[4][4];
        {
            const uint32_t roff = ((wrow0 + (lane & 15)) * KST + (lane >> 4) * 8) * 2;
            #pragma unroll
            for (int ks = 0; ks < 4; ++ks) {
                ldmx4(qhf[ks], sbase + roff + ks * 32);
                ldmx4(qlf[ks], sbase + roff + 128*KST*2 + ks * 32);
            }
        }
        __syncthreads();

        float mrow[2] = {-1e30f, -1e30f};
        float lrow[2] = {0.0f, 0.0f};
        float o[8][4] = {};

        const int wmax = qi*128 + wrow0 + 15;
        const int nsteps = 2*qi + 2;

        issue(0);
        for (int kt = 0; kt < nsteps; ++kt) {
            if (kt + 1 < nsteps) { issue(kt + 1); cpa_wait<1>(); }
            else                 { cpa_wait<0>(); }
            __syncthreads();

            const uint32_t st = sbase + (kt & 1) * STAGE;
            const uint32_t sKh = st;
            const uint32_t sKl = st + 64*KST*2;
            const uint32_t sVh = st + 128*KST*2;
            const uint32_t sVl = st + 192*KST*2;

            if (kt*64 <= wmax) {
                // ---- scores: 3-pass split QK^T (K frags loaded per-ng) ----
                float s[8][4] = {};
                #pragma unroll
                for (int ks = 0; ks < 4; ++ks) {
                    #pragma unroll
                    for (int ng = 0; ng < 4; ++ng) {
                        uint32_t khb[4], klb[4];
                        ldmx4(khb, sKh + kbase[ng] + ks*32);
                        ldmx4(klb, sKl + kbase[ng] + ks*32);
                        mma_bf16(s[2*ng+0], qhf[ks], khb[0], khb[1]);
                        mma_bf16(s[2*ng+1], qhf[ks], khb[2], khb[3]);
                        mma_bf16(s[2*ng+0], qhf[ks], klb[0], klb[1]);
                        mma_bf16(s[2*ng+1], qhf[ks], klb[2], klb[3]);
                        mma_bf16(s[2*ng+0], qlf[ks], khb[0], khb[1]);
                        mma_bf16(s[2*ng+1], qlf[ks], khb[2], khb[3]);
                    }
                }

                const int r0g = qi*128 + wrow0 + (lane >> 2);
                const bool needmask = (kt*64 + 63 > qi*128 + wrow0);
                #pragma unroll
                for (int nf = 0; nf < 8; ++nf)
                    #pragma unroll
                    for (int ri = 0; ri < 4; ++ri) {
                        float v = s[nf][ri] * 0.125f;
                        if (needmask) {
                            int col = kt*64 + nf*8 + (lane & 3)*2 + (ri & 1);
                            int rg  = r0g + ((ri >> 1) ? 8 : 0);
                            if (col > rg) v = -1e30f;
                        }
                        s[nf][ri] = v;
                    }

                float alpha[2];
                #pragma unroll
                for (int h = 0; h < 2; ++h) {
                    float t = -1e30f;
                    #pragma unroll
                    for (int nf = 0; nf < 8; ++nf)
                        t = fmaxf(t, fmaxf(s[nf][h*2], s[nf][h*2+1]));
                    t = fmaxf(t, __shfl_xor_sync(0xffffffffu, t, 1));
                    t = fmaxf(t, __shfl_xor_sync(0xffffffffu, t, 2));
                    float nm = fmaxf(mrow[h], t);
                    alpha[h] = ex2f((mrow[h] - nm) * LOG2E);
                    mrow[h] = nm;
                }
                float rs[2] = {0.0f, 0.0f};
                #pragma unroll
                for (int nf = 0; nf < 8; ++nf)
                    #pragma unroll
                    for (int ri = 0; ri < 4; ++ri) {
                        int h = ri >> 1;
                        float p = ex2f((s[nf][ri] - mrow[h]) * LOG2E);
                        s[nf][ri] = p;
                        rs[h] += p;
                    }
                #pragma unroll
                for (int h = 0; h < 2; ++h) {
                    rs[h] += __shfl_xor_sync(0xffffffffu, rs[h], 1);
                    rs[h] += __shfl_xor_sync(0xffffffffu, rs[h], 2);
                    lrow[h] = lrow[h] * alpha[h] + rs[h];
                }
                #pragma unroll
                for (int nf = 0; nf < 8; ++nf) {
                    o[nf][0] *= alpha[0]; o[nf][1] *= alpha[0];
                    o[nf][2] *= alpha[1]; o[nf][3] *= alpha[1];
                }

                uint32_t pah[4][4], pal[4][4];
                #pragma unroll
                for (int ks = 0; ks < 4; ++ks) {
                    float a0 = s[2*ks][0],   a1 = s[2*ks][1];
                    float b0 = s[2*ks][2],   b1 = s[2*ks][3];
                    float c0 = s[2*ks+1][0], c1 = s[2*ks+1][1];
                    float d0 = s[2*ks+1][2], d1 = s[2*ks+1][3];
                    __nv_bfloat16 ha0 = __float2bfloat16(a0), ha1 = __float2bfloat16(a1);
                    __nv_bfloat16 hb0 = __float2bfloat16(b0), hb1 = __float2bfloat16(b1);
                    __nv_bfloat16 hc0 = __float2bfloat16(c0), hc1 = __float2bfloat16(c1);
                    __nv_bfloat16 hd0 = __float2bfloat16(d0), hd1 = __float2bfloat16(d1);
                    pah[ks][0] = pack2(ha0, ha1);
                    pah[ks][1] = pack2(hb0, hb1);
                    pah[ks][2] = pack2(hc0, hc1);
                    pah[ks][3] = pack2(hd0, hd1);
                    pal[ks][0] = pack_bf16x2(a0 - __bfloat162float(ha0), a1 - __bfloat162float(ha1));
                    pal[ks][1] = pack_bf16x2(b0 - __bfloat162float(hb0), b1 - __bfloat162float(hb1));
                    pal[ks][2] = pack_bf16x2(c0 - __bfloat162float(hc0), c1 - __bfloat162float(hc1));
                    pal[ks][3] = pack_bf16x2(d0 - __bfloat162float(hd0), d1 - __bfloat162float(hd1));
                }

                #pragma unroll
                for (int ks = 0; ks < 4; ++ks) {
                    const uint32_t vrb = vrowoff + ks*16*KST*2;
                    #pragma unroll
                    for (int ng = 0; ng < 4; ++ng) {
                        uint32_t vhb[4], vlb[4];
                        ldmx4t(vhb, sVh + vrb + vcol[ng]);
                        ldmx4t(vlb, sVl + vrb + vcol[ng]);
                        mma_bf16(o[2*ng+0], pah[ks], vhb[0], vhb[1]);
                        mma_bf16(o[2*ng+1], pah[ks], vhb[2], vhb[3]);
                        mma_bf16(o[2*ng+0], pah[ks], vlb[0], vlb[1]);
                        mma_bf16(o[2*ng+1], pah[ks], vlb[2], vlb[3]);
                        mma_bf16(o[2*ng+0], pal[ks], vhb[0], vhb[1]);
                        mma_bf16(o[2*ng+1], pal[ks], vhb[2], vhb[3]);
                    }
                }
            }
            __syncthreads();
        }

        // ---- epilogue: write ctx as bf16 hi/lo (row-major [M][D]) ----
        const float inv0 = 1.0f / lrow[0];
        const float inv1 = 1.0f / lrow[1];
        const int b = bh >> 4, h = bh & 15;
        const int r0 = qi*128 + wrow0 + (lane >> 2);
        #pragma unroll
        for (int nf = 0; nf < 8; ++nf) {
            const int col = h*HD + nf*8 + (lane & 3)*2;
            const size_t off0 = ((size_t)b*SS + r0)*DD + col;
            const size_t off1 = ((size_t)b*SS + r0 + 8)*DD + col;
            float x0 = o[nf][0]*inv0, y0 = o[nf][1]*inv0;
            float x1 = o[nf][2]*inv1, y1 = o[nf][3]*inv1;
            __nv_bfloat16 hx0 = __float2bfloat16(x0), hy0 = __float2bfloat16(y0);
            __nv_bfloat16 hx1 = __float2bfloat16(x1), hy1 = __float2bfloat16(y1);
            *(uint32_t*)(Chi + off0) = pack2(hx0, hy0);
            *(uint32_t*)(Chi + off1) = pack2(hx1, hy1);
            *(uint32_t*)(Clo + off0) = pack_bf16x2(x0 - __bfloat162float(hx0),
                                                   y0 - __bfloat162float(hy0));
            *(uint32_t*)(Clo + off1) = pack_bf16x2(x1 - __bfloat162float(hx1),
                                                   y1 - __bfloat162float(hy1));
        }
    }
}

// ---------------------------------------------------------------------------

extern "C" void kernel_launch(void* const* d_in, const int* in_sizes, int n_in,
                              void* d_out, int out_size)
{
    const float* x  = (const float*)d_in[0];
    const float* Wq = (const float*)d_in[1];
    const float* Wk = (const float*)d_in[2];
    const float* Wv = (const float*)d_in[3];
    const float* Wo = (const float*)d_in[4];
    const float* bo = (const float*)d_in[5];
    float* out = (float*)d_out;

    __nv_bfloat16 *ahi, *alo, *wthi, *wtlo, *qh, *ql, *kh, *kl, *vh, *vl;
    cudaGetSymbolAddress((void**)&ahi,  g_ahi);
    cudaGetSymbolAddress((void**)&alo,  g_alo);
    cudaGetSymbolAddress((void**)&wthi, g_wthi);
    cudaGetSymbolAddress((void**)&wtlo, g_wtlo);
    cudaGetSymbolAddress((void**)&qh,   g_qh);
    cudaGetSymbolAddress((void**)&ql,   g_ql);
    cudaGetSymbolAddress((void**)&kh,   g_kh);
    cudaGetSymbolAddress((void**)&kl,   g_kl);
    cudaGetSymbolAddress((void**)&vh,   g_vh);
    cudaGetSymbolAddress((void**)&vl,   g_vl);

    cudaFuncSetAttribute(attn_mma, cudaFuncAttributeMaxDynamicSharedMemorySize, ATTN_SMEM);
    cudaFuncSetAttribute(mma_gemm_qkv, cudaFuncAttributeMaxDynamicSharedMemorySize, GEMM_SMEM);
    cudaFuncSetAttribute(mma_gemm_out, cudaFuncAttributeMaxDynamicSharedMemorySize, GEMM_SMEM);

    // 1. split X into bf16 hi/lo
    split_kernel<<<1024, 256>>>((const float4*)x, ahi, alo, MM*DD/4);

    // 2. transpose+split all 4 weights (one launch)
    transpose_split_kernel<<<dim3(32,32,4), dim3(32,8)>>>(Wq, Wk, Wv, Wo, wthi, wtlo);

    // 3. fused Q/K/V projections (HMMA, cp.async 3-stage)
    mma_gemm_qkv<<<dim3(24, 32), 256, GEMM_SMEM>>>(ahi, alo, wthi, wtlo, qh, ql, kh, kl, vh, vl);

    // 4. attention (HMMA flash, balanced pairs, cp.async pipeline)
    attn_mma<<<dim3(8, BB*HH), 256, ATTN_SMEM>>>(qh, ql, kh, kl, vh, vl, ahi, alo);

    // 5. output projection + bias
    mma_gemm_out<<<dim3(8, 32), 256, GEMM_SMEM>>>(ahi, alo, wthi + 3*(size_t)DD*DD, wtlo + 3*(size_t)DD*DD, out, bo);
}

// round 9
// speedup vs baseline: 3.6231x; 1.0795x over previous
#include <cuda_runtime.h>
#include <cuda_bf16.h>
#include <cstdint>

#define BB 2
#define SS 2048
#define DD 1024
#define HH 16
#define HD 64
#define MM (BB*SS)     // 4096

// ---------------- device scratch (no allocation allowed) -------------------
__device__ __nv_bfloat16 g_ahi[MM*DD];
__device__ __nv_bfloat16 g_alo[MM*DD];
__device__ __nv_bfloat16 g_wthi[4][DD*DD];
__device__ __nv_bfloat16 g_wtlo[4][DD*DD];
__device__ __nv_bfloat16 g_qh[BB*HH*SS*HD];
__device__ __nv_bfloat16 g_ql[BB*HH*SS*HD];
__device__ __nv_bfloat16 g_kh[BB*HH*SS*HD];
__device__ __nv_bfloat16 g_kl[BB*HH*SS*HD];
__device__ __nv_bfloat16 g_vh[BB*HH*SS*HD];
__device__ __nv_bfloat16 g_vl[BB*HH*SS*HD];

// ---------------- prepass: fp32 -> bf16 hi/lo split -------------------------
__global__ __launch_bounds__(256)
void split_kernel(const float4* __restrict__ X, __nv_bfloat16* __restrict__ Hi,
                  __nv_bfloat16* __restrict__ Lo, int n4)
{
    union U { __nv_bfloat16 b[4]; uint64_t u; };
    for (int i = blockIdx.x * blockDim.x + threadIdx.x; i < n4;
         i += gridDim.x * blockDim.x) {
        float4 f = X[i];
        U h, l;
        float vf[4] = {f.x, f.y, f.z, f.w};
        #pragma unroll
        for (int j = 0; j < 4; ++j) {
            __nv_bfloat16 hb = __float2bfloat16(vf[j]);
            h.b[j] = hb;
            l.b[j] = __float2bfloat16(vf[j] - __bfloat162float(hb));
        }
        ((uint64_t*)Hi)[i] = h.u;
        ((uint64_t*)Lo)[i] = l.u;
    }
}

// ---------------- prepass: 4x W[k][n] -> Wt[n][k] hi/lo split ----------------
__global__ __launch_bounds__(256)
void transpose_split_kernel(const float* __restrict__ W0, const float* __restrict__ W1,
                            const float* __restrict__ W2, const float* __restrict__ W3,
                            __nv_bfloat16* __restrict__ Th,
                            __nv_bfloat16* __restrict__ Tl)
{
    __shared__ float tile[32][33];
    const float* Ws[4] = {W0, W1, W2, W3};
    const float* W = Ws[blockIdx.z];
    __nv_bfloat16* th = Th + (size_t)blockIdx.z * DD * DD;
    __nv_bfloat16* tl = Tl + (size_t)blockIdx.z * DD * DD;
    int tx = threadIdx.x, ty = threadIdx.y;
    int x = blockIdx.x * 32 + tx;
    #pragma unroll
    for (int i = 0; i < 4; ++i) {
        int y = blockIdx.y * 32 + ty + i * 8;
        tile[ty + i * 8][tx] = W[(size_t)y * DD + x];
    }
    __syncthreads();
    int xo = blockIdx.y * 32 + tx;
    #pragma unroll
    for (int i = 0; i < 4; ++i) {
        int yo = blockIdx.x * 32 + ty + i * 8;
        float v = tile[tx][ty + i * 8];
        __nv_bfloat16 hb = __float2bfloat16(v);
        th[(size_t)yo * DD + xo] = hb;
        tl[(size_t)yo * DD + xo] = __float2bfloat16(v - __bfloat162float(hb));
    }
}

// ---------------- mma.sync / cp.async helpers --------------------------------
__device__ __forceinline__ uint32_t smem_u32(const void* p) {
    uint32_t a;
    asm("{ .reg .u64 t; cvta.to.shared.u64 t, %1; cvt.u32.u64 %0, t; }"
        : "=r"(a) : "l"(p));
    return a;
}
__device__ __forceinline__ void ldmx4(uint32_t* r, uint32_t addr) {
    asm volatile("ldmatrix.sync.aligned.m8n8.x4.shared.b16 {%0,%1,%2,%3}, [%4];"
                 : "=r"(r[0]), "=r"(r[1]), "=r"(r[2]), "=r"(r[3]) : "r"(addr));
}
__device__ __forceinline__ void ldmx4t(uint32_t* r, uint32_t addr) {
    asm volatile("ldmatrix.sync.aligned.m8n8.x4.trans.shared.b16 {%0,%1,%2,%3}, [%4];"
                 : "=r"(r[0]), "=r"(r[1]), "=r"(r[2]), "=r"(r[3]) : "r"(addr));
}
__device__ __forceinline__ void mma_bf16(float* c, const uint32_t* a,
                                         uint32_t b0, uint32_t b1) {
    asm volatile(
        "mma.sync.aligned.m16n8k16.row.col.f32.bf16.bf16.f32 "
        "{%0,%1,%2,%3}, {%4,%5,%6,%7}, {%8,%9}, {%0,%1,%2,%3};"
        : "+f"(c[0]), "+f"(c[1]), "+f"(c[2]), "+f"(c[3])
        : "r"(a[0]), "r"(a[1]), "r"(a[2]), "r"(a[3]), "r"(b0), "r"(b1));
}
__device__ __forceinline__ float ex2f(float x) {
    float y; asm("ex2.approx.f32 %0, %1;" : "=f"(y) : "f"(x)); return y;
}
__device__ __forceinline__ uint32_t pack2(__nv_bfloat16 a, __nv_bfloat16 b) {
    __nv_bfloat162 t = __halves2bfloat162(a, b);
    return *(uint32_t*)&t;
}
__device__ __forceinline__ uint32_t pack_bf16x2(float a, float b) {
    __nv_bfloat162 t = __floats2bfloat162_rn(a, b);
    return *(uint32_t*)&t;
}
__device__ __forceinline__ void cpa16(uint32_t dst, const void* src) {
    asm volatile("cp.async.cg.shared.global [%0], [%1], 16;" :: "r"(dst), "l"(src));
}
__device__ __forceinline__ void cpa_commit() {
    asm volatile("cp.async.commit_group;" ::: "memory");
}
template<int N> __device__ __forceinline__ void cpa_wait() {
    asm volatile("cp.async.wait_group %0;" :: "n"(N) : "memory");
}

// ---------------- HMMA GEMM core (load-once, 3 passes from smem) -------------
// Stage holds Ahi|Alo|Bhi|Blo 128x32 tiles. 2 stages, 32 k-chunks.
#define AST 40
#define GCH 32
#define GOP (128*AST*2)              // 10240 B per operand
#define GSTG (4*GOP)                 // 40960 B per stage
#define GEMM_SMEM (2*GSTG)           // 81920 B

template<typename EPI>
__device__ __forceinline__ void gemm_core(
    const __nv_bfloat16* Ahi, const __nv_bfloat16* Alo,
    const __nv_bfloat16* Bhi, const __nv_bfloat16* Blo,
    int m0, int n0, EPI epi)
{
    extern __shared__ __align__(16) char gsm[];
    const uint32_t base = smem_u32(gsm);

    const int tid  = threadIdx.x;
    const int wid  = tid >> 5;
    const int lane = tid & 31;
    const int wm0 = (wid & 3) * 32;
    const int wn0 = (wid >> 2) * 64;

    const uint4* srcs[4] = {(const uint4*)Ahi, (const uint4*)Alo,
                            (const uint4*)Bhi, (const uint4*)Blo};

    // copy mapping: 2048 uint4 per chunk, 8 per thread
    int cmat[8], crow[8], cc4[8];
    uint32_t cdst[8];
    #pragma unroll
    for (int i = 0; i < 8; ++i) {
        int idx = tid + i * 256;
        cmat[i] = idx >> 9;
        int w = idx & 511;
        crow[i] = w >> 2;
        cc4[i]  = w & 3;
        cdst[i] = base + cmat[i]*GOP + (crow[i]*AST + cc4[i]*8) * 2;
    }

    auto issue = [&](int t) {
        const uint32_t so = (t & 1) * GSTG;
        #pragma unroll
        for (int i = 0; i < 8; ++i) {
            const int r0 = (cmat[i] < 2) ? m0 : n0;
            cpa16(cdst[i] + so, srcs[cmat[i]] + (size_t)(r0 + crow[i])*128 + t*4 + cc4[i]);
        }
        cpa_commit();
    };

    uint32_t aoff[2], boff[4];
    #pragma unroll
    for (int mf = 0; mf < 2; ++mf)
        aoff[mf] = ((wm0 + mf*16 + (lane & 15)) * AST + (lane >> 4) * 8) * 2;
    #pragma unroll
    for (int np = 0; np < 4; ++np)
        boff[np] = ((wn0 + np*16 + ((lane >> 4) & 1) * 8 + (lane & 7)) * AST
                    + ((lane >> 3) & 1) * 8) * 2;

    float acc[2][8][4] = {};

    auto compute = [&](int stg) {
        const uint32_t sb = base + stg * GSTG;
        #pragma unroll
        for (int ks = 0; ks < 32; ks += 16) {
            uint32_t afh[2][4], afl[2][4], bfh[4][4], bfl[4][4];
            #pragma unroll
            for (int mf = 0; mf < 2; ++mf) {
                ldmx4(afh[mf], sb + aoff[mf] + ks*2);
                ldmx4(afl[mf], sb + GOP + aoff[mf] + ks*2);
            }
            #pragma unroll
            for (int np = 0; np < 4; ++np) {
                ldmx4(bfh[np], sb + 2*GOP + boff[np] + ks*2);
                ldmx4(bfl[np], sb + 3*GOP + boff[np] + ks*2);
            }
            #pragma unroll
            for (int mf = 0; mf < 2; ++mf)
                #pragma unroll
                for (int np = 0; np < 4; ++np) {
                    mma_bf16(acc[mf][np*2+0], afh[mf], bfh[np][0], bfh[np][1]);
                    mma_bf16(acc[mf][np*2+1], afh[mf], bfh[np][2], bfh[np][3]);
                    mma_bf16(acc[mf][np*2+0], afh[mf], bfl[np][0], bfl[np][1]);
                    mma_bf16(acc[mf][np*2+1], afh[mf], bfl[np][2], bfl[np][3]);
                    mma_bf16(acc[mf][np*2+0], afl[mf], bfh[np][0], bfh[np][1]);
                    mma_bf16(acc[mf][np*2+1], afl[mf], bfh[np][2], bfh[np][3]);
                }
        }
    };

    issue(0);
    for (int t = 0; t < GCH; ++t) {
        cpa_wait<0>();
        __syncthreads();
        if (t + 1 < GCH) issue(t + 1);
        compute(t & 1);
    }

    const int qrow = lane >> 2;
    const int qcol = (lane & 3) * 2;
    #pragma unroll
    for (int mf = 0; mf < 2; ++mf)
        #pragma unroll
        for (int nf = 0; nf < 8; ++nf)
            #pragma unroll
            for (int half = 0; half < 2; ++half) {
                const int m = m0 + wm0 + mf*16 + qrow + half*8;
                const int n = n0 + wn0 + nf*8 + qcol;
                epi(m, n, acc[mf][nf][half*2 + 0], acc[mf][nf][half*2 + 1]);
            }
}

// fused QKV projection: grid.x = 24 (gemm = x>>3), grid.y = 32
__global__ __launch_bounds__(256, 2)
void mma_gemm_qkv(const __nv_bfloat16* __restrict__ Ahi, const __nv_bfloat16* __restrict__ Alo,
                  const __nv_bfloat16* __restrict__ Whi, const __nv_bfloat16* __restrict__ Wlo,
                  __nv_bfloat16* __restrict__ qh, __nv_bfloat16* __restrict__ ql,
                  __nv_bfloat16* __restrict__ kh, __nv_bfloat16* __restrict__ kl,
                  __nv_bfloat16* __restrict__ vh, __nv_bfloat16* __restrict__ vl)
{
    const int g  = blockIdx.x >> 3;
    const int n0 = (blockIdx.x & 7) * 128;
    const int m0 = blockIdx.y * 128;
    const __nv_bfloat16* Bhi = Whi + (size_t)g * DD * DD;
    const __nv_bfloat16* Blo = Wlo + (size_t)g * DD * DD;
    __nv_bfloat16* Yh = (g == 0) ? qh : (g == 1) ? kh : vh;
    __nv_bfloat16* Yl = (g == 0) ? ql : (g == 1) ? kl : vl;

    gemm_core(Ahi, Alo, Bhi, Blo, m0, n0,
        [&](int m, int n, float cx, float cy) {
            const int b = m >> 11, s = m & (SS - 1);
            const int h = n >> 6, hd = n & 63;
            const size_t off = (((size_t)b*HH + h)*SS + s)*HD + hd;
            __nv_bfloat16 hx = __float2bfloat16(cx);
            __nv_bfloat16 hy = __float2bfloat16(cy);
            *(uint32_t*)(Yh + off) = pack2(hx, hy);
            *(uint32_t*)(Yl + off) = pack_bf16x2(
                cx - __bfloat162float(hx), cy - __bfloat162float(hy));
        });
}

// output projection + bias
__global__ __launch_bounds__(256, 2)
void mma_gemm_out(const __nv_bfloat16* __restrict__ Ahi, const __nv_bfloat16* __restrict__ Alo,
                  const __nv_bfloat16* __restrict__ Bhi, const __nv_bfloat16* __restrict__ Blo,
                  float* __restrict__ Yf, const float* __restrict__ bias)
{
    const int n0 = blockIdx.x * 128;
    const int m0 = blockIdx.y * 128;
    gemm_core(Ahi, Alo, Bhi, Blo, m0, n0,
        [&](int m, int n, float cx, float cy) {
            float2* dst = (float2*)(Yf + (size_t)m * DD + n);
            *dst = make_float2(cx + bias[n], cy + bias[n + 1]);
        });
}

// ---------------- HMMA flash attention --------------------------------------
// Fixed-max softmax: p = exp2(s*SC - SBIAS); l reduced once in epilogue.
#define KST 72
#define STAGE (4*64*KST*2)           // 36864 B
#define ATTN_SMEM (2*STAGE)          // 73728 B
#define LOG2E 1.4426950408889634f
#define SBIAS (16.0f * LOG2E)

__global__ __launch_bounds__(256, 2)
void attn_mma(const __nv_bfloat16* __restrict__ Qh, const __nv_bfloat16* __restrict__ Ql,
              const __nv_bfloat16* __restrict__ Kh, const __nv_bfloat16* __restrict__ Kl,
              const __nv_bfloat16* __restrict__ Vh, const __nv_bfloat16* __restrict__ Vl,
              __nv_bfloat16* __restrict__ Chi, __nv_bfloat16* __restrict__ Clo)
{
    extern __shared__ __align__(16) char dynsm[];
    __nv_bfloat16* sm = (__nv_bfloat16*)dynsm;

    const int bh  = blockIdx.y;
    const int tid = threadIdx.x;
    const int wid = tid >> 5;
    const int lane = tid & 31;
    const int wrow0 = wid * 16;

    const size_t hbase = (size_t)bh * SS * HD;
    const uint4* Kh4 = (const uint4*)(Kh + hbase);
    const uint4* Kl4 = (const uint4*)(Kl + hbase);
    const uint4* Vh4 = (const uint4*)(Vh + hbase);
    const uint4* Vl4 = (const uint4*)(Vl + hbase);

    const uint32_t sbase = smem_u32(sm);

    uint32_t kbase[4];
    #pragma unroll
    for (int ng = 0; ng < 4; ++ng) {
        int krow = ng*16 + ((lane >> 4) & 1)*8 + (lane & 7);
        kbase[ng] = (krow * KST + ((lane >> 3) & 1) * 8) * 2;
    }
    const uint32_t vrowoff = ((((lane >> 3) & 1)*8 + (lane & 7)) * KST) * 2;
    uint32_t vcol[4];
    #pragma unroll
    for (int ng = 0; ng < 4; ++ng)
        vcol[ng] = (ng*16 + (lane >> 4) * 8) * 2;

    uint32_t cpa_dst[8];
    int cpa_src[8];
    #pragma unroll
    for (int i = 0; i < 8; ++i) {
        int idx = tid + i * 256;
        int tile = idx >> 9;
        int within = idx & 511;
        int row = within >> 3, c = within & 7;
        cpa_dst[i] = sbase + ((tile*64 + row)*KST + c*8) * 2;
        cpa_src[i] = within;
    }

    auto issue = [&](int kt) {
        const uint4* srcs[4] = {Kh4 + kt*512, Kl4 + kt*512, Vh4 + kt*512, Vl4 + kt*512};
        const uint32_t soff = (kt & 1) * STAGE;
        #pragma unroll
        for (int i = 0; i < 8; ++i) {
            int tile = (tid + i*256) >> 9;
            cpa16(cpa_dst[i] + soff, srcs[tile] + cpa_src[i]);
        }
        cpa_commit();
    };

    #pragma unroll 1
    for (int half = 0; half < 2; ++half) {
        const int qi = half ? (15 - blockIdx.x) : blockIdx.x;

        __syncthreads();
        {
            const uint4* Qh4 = (const uint4*)(Qh + hbase + (size_t)qi*128*HD);
            const uint4* Ql4 = (const uint4*)(Ql + hbase + (size_t)qi*128*HD);
            const uint4* bufs[2] = {Qh4, Ql4};
            #pragma unroll
            for (int i = 0; i < 8; ++i) {
                int idx = tid + i * 256;
                int buf = idx >> 10;
                int within = idx & 1023;
                int row = within >> 3, c = within & 7;
                uint4 v = bufs[buf][within];
                *(uint4*)&sm[(buf*128 + row)*KST + c*8] = v;
            }
        }
        __syncthreads();

        uint32_t qhf[4][4], qlf[4][4];
        {
            const uint32_t roff = ((wrow0 + (lane & 15)) * KST + (lane >> 4) * 8) * 2;
            #pragma unroll
            for (int ks = 0; ks < 4; ++ks) {
                ldmx4(qhf[ks], sbase + roff + ks * 32);
                ldmx4(qlf[ks], sbase + roff + 128*KST*2 + ks * 32);
            }
        }
        __syncthreads();

        float lrow[2] = {0.0f, 0.0f};
        float o[8][4] = {};

        const int wmax = qi*128 + wrow0 + 15;
        const int nsteps = 2*qi + 2;

        issue(0);
        for (int kt = 0; kt < nsteps; ++kt) {
            if (kt + 1 < nsteps) { issue(kt + 1); cpa_wait<1>(); }
            else                 { cpa_wait<0>(); }
            __syncthreads();

            const uint32_t st = sbase + (kt & 1) * STAGE;
            const uint32_t sKh = st;
            const uint32_t sKl = st + 64*KST*2;
            const uint32_t sVh = st + 128*KST*2;
            const uint32_t sVl = st + 192*KST*2;

            if (kt*64 <= wmax) {
                float s[8][4] = {};
                #pragma unroll
                for (int ks = 0; ks < 4; ++ks) {
                    #pragma unroll
                    for (int ng = 0; ng < 4; ++ng) {
                        uint32_t khb[4], klb[4];
                        ldmx4(khb, sKh + kbase[ng] + ks*32);
                        ldmx4(klb, sKl + kbase[ng] + ks*32);
                        mma_bf16(s[2*ng+0], qhf[ks], khb[0], khb[1]);
                        mma_bf16(s[2*ng+1], qhf[ks], khb[2], khb[3]);
                        mma_bf16(s[2*ng+0], qhf[ks], klb[0], klb[1]);
                        mma_bf16(s[2*ng+1], qhf[ks], klb[2], klb[3]);
                        mma_bf16(s[2*ng+0], qlf[ks], khb[0], khb[1]);
                        mma_bf16(s[2*ng+1], qlf[ks], khb[2], khb[3]);
                    }
                }

                // ---- fixed-max softmax: p = exp2(s*SC - SBIAS) ----
                const float SC = 0.125f * LOG2E;
                const int r0g = qi*128 + wrow0 + (lane >> 2);
                const bool needmask = (kt*64 + 63 > qi*128 + wrow0);
                #pragma unroll
                for (int nf = 0; nf < 8; ++nf)
                    #pragma unroll
                    for (int ri = 0; ri < 4; ++ri) {
                        float v = s[nf][ri] * SC - SBIAS;
                        if (needmask) {
                            int col = kt*64 + nf*8 + (lane & 3)*2 + (ri & 1);
                            int rg  = r0g + ((ri >> 1) ? 8 : 0);
                            if (col > rg) v = -1e30f;
                        }
                        float p = ex2f(v);
                        s[nf][ri] = p;
                        lrow[ri >> 1] += p;
                    }

                uint32_t pah[4][4], pal[4][4];
                #pragma unroll
                for (int ks = 0; ks < 4; ++ks) {
                    float a0 = s[2*ks][0],   a1 = s[2*ks][1];
                    float b0 = s[2*ks][2],   b1 = s[2*ks][3];
                    float c0 = s[2*ks+1][0], c1 = s[2*ks+1][1];
                    float d0 = s[2*ks+1][2], d1 = s[2*ks+1][3];
                    __nv_bfloat16 ha0 = __float2bfloat16(a0), ha1 = __float2bfloat16(a1);
                    __nv_bfloat16 hb0 = __float2bfloat16(b0), hb1 = __float2bfloat16(b1);
                    __nv_bfloat16 hc0 = __float2bfloat16(c0), hc1 = __float2bfloat16(c1);
                    __nv_bfloat16 hd0 = __float2bfloat16(d0), hd1 = __float2bfloat16(d1);
                    pah[ks][0] = pack2(ha0, ha1);
                    pah[ks][1] = pack2(hb0, hb1);
                    pah[ks][2] = pack2(hc0, hc1);
                    pah[ks][3] = pack2(hd0, hd1);
                    pal[ks][0] = pack_bf16x2(a0 - __bfloat162float(ha0), a1 - __bfloat162float(ha1));
                    pal[ks][1] = pack_bf16x2(b0 - __bfloat162float(hb0), b1 - __bfloat162float(hb1));
                    pal[ks][2] = pack_bf16x2(c0 - __bfloat162float(hc0), c1 - __bfloat162float(hc1));
                    pal[ks][3] = pack_bf16x2(d0 - __bfloat162float(hd0), d1 - __bfloat162float(hd1));
                }

                #pragma unroll
                for (int ks = 0; ks < 4; ++ks) {
                    const uint32_t vrb = vrowoff + ks*16*KST*2;
                    #pragma unroll
                    for (int ng = 0; ng < 4; ++ng) {
                        uint32_t vhb[4], vlb[4];
                        ldmx4t(vhb, sVh + vrb + vcol[ng]);
                        ldmx4t(vlb, sVl + vrb + vcol[ng]);
                        mma_bf16(o[2*ng+0], pah[ks], vhb[0], vhb[1]);
                        mma_bf16(o[2*ng+1], pah[ks], vhb[2], vhb[3]);
                        mma_bf16(o[2*ng+0], pah[ks], vlb[0], vlb[1]);
                        mma_bf16(o[2*ng+1], pah[ks], vlb[2], vlb[3]);
                        mma_bf16(o[2*ng+0], pal[ks], vhb[0], vhb[1]);
                        mma_bf16(o[2*ng+1], pal[ks], vhb[2], vhb[3]);
                    }
                }
            }
            __syncthreads();
        }

        // ---- epilogue: reduce l, write ctx as bf16 hi/lo (row-major [M][D]) ----
        float l0 = lrow[0], l1 = lrow[1];
        l0 += __shfl_xor_sync(0xffffffffu, l0, 1);
        l0 += __shfl_xor_sync(0xffffffffu, l0, 2);
        l1 += __shfl_xor_sync(0xffffffffu, l1, 1);
        l1 += __shfl_xor_sync(0xffffffffu, l1, 2);
        const float inv0 = 1.0f / l0;
        const float inv1 = 1.0f / l1;
        const int b = bh >> 4, h = bh & 15;
        const int r0 = qi*128 + wrow0 + (lane >> 2);
        #pragma unroll
        for (int nf = 0; nf < 8; ++nf) {
            const int col = h*HD + nf*8 + (lane & 3)*2;
            const size_t off0 = ((size_t)b*SS + r0)*DD + col;
            const size_t off1 = ((size_t)b*SS + r0 + 8)*DD + col;
            float x0 = o[nf][0]*inv0, y0 = o[nf][1]*inv0;
            float x1 = o[nf][2]*inv1, y1 = o[nf][3]*inv1;
            __nv_bfloat16 hx0 = __float2bfloat16(x0), hy0 = __float2bfloat16(y0);
            __nv_bfloat16 hx1 = __float2bfloat16(x1), hy1 = __float2bfloat16(y1);
            *(uint32_t*)(Chi + off0) = pack2(hx0, hy0);
            *(uint32_t*)(Chi + off1) = pack2(hx1, hy1);
            *(uint32_t*)(Clo + off0) = pack_bf16x2(x0 - __bfloat162float(hx0),
                                                   y0 - __bfloat162float(hy0));
            *(uint32_t*)(Clo + off1) = pack_bf16x2(x1 - __bfloat162float(hx1),
                                                   y1 - __bfloat162float(hy1));
        }
    }
}

// ---------------------------------------------------------------------------

extern "C" void kernel_launch(void* const* d_in, const int* in_sizes, int n_in,
                              void* d_out, int out_size)
{
    const float* x  = (const float*)d_in[0];
    const float* Wq = (const float*)d_in[1];
    const float* Wk = (const float*)d_in[2];
    const float* Wv = (const float*)d_in[3];
    const float* Wo = (const float*)d_in[4];
    const float* bo = (const float*)d_in[5];
    float* out = (float*)d_out;

    __nv_bfloat16 *ahi, *alo, *wthi, *wtlo, *qh, *ql, *kh, *kl, *vh, *vl;
    cudaGetSymbolAddress((void**)&ahi,  g_ahi);
    cudaGetSymbolAddress((void**)&alo,  g_alo);
    cudaGetSymbolAddress((void**)&wthi, g_wthi);
    cudaGetSymbolAddress((void**)&wtlo, g_wtlo);
    cudaGetSymbolAddress((void**)&qh,   g_qh);
    cudaGetSymbolAddress((void**)&ql,   g_ql);
    cudaGetSymbolAddress((void**)&kh,   g_kh);
    cudaGetSymbolAddress((void**)&kl,   g_kl);
    cudaGetSymbolAddress((void**)&vh,   g_vh);
    cudaGetSymbolAddress((void**)&vl,   g_vl);

    cudaFuncSetAttribute(attn_mma, cudaFuncAttributeMaxDynamicSharedMemorySize, ATTN_SMEM);
    cudaFuncSetAttribute(mma_gemm_qkv, cudaFuncAttributeMaxDynamicSharedMemorySize, GEMM_SMEM);
    cudaFuncSetAttribute(mma_gemm_out, cudaFuncAttributeMaxDynamicSharedMemorySize, GEMM_SMEM);

    // 1. split X into bf16 hi/lo
    split_kernel<<<1024, 256>>>((const float4*)x, ahi, alo, MM*DD/4);

    // 2. transpose+split all 4 weights (one launch)
    transpose_split_kernel<<<dim3(32,32,4), dim3(32,8)>>>(Wq, Wk, Wv, Wo, wthi, wtlo);

    // 3. fused Q/K/V projections (HMMA, load-once 3-pass, cp.async 2-stage)
    mma_gemm_qkv<<<dim3(24, 32), 256, GEMM_SMEM>>>(ahi, alo, wthi, wtlo, qh, ql, kh, kl, vh, vl);

    // 4. attention (HMMA flash, balanced pairs, cp.async, fixed-max softmax)
    attn_mma<<<dim3(8, BB*HH), 256, ATTN_SMEM>>>(qh, ql, kh, kl, vh, vl, ahi, alo);

    // 5. output projection + bias
    mma_gemm_out<<<dim3(8, 32), 256, GEMM_SMEM>>>(ahi, alo, wthi + 3*(size_t)DD*DD, wtlo + 3*(size_t)DD*DD, out, bo);
}

// round 10
// speedup vs baseline: 3.7903x; 1.0462x over previous
#include <cuda_runtime.h>
#include <cuda_bf16.h>
#include <cstdint>

#define BB 2
#define SS 2048
#define DD 1024
#define HH 16
#define HD 64
#define MM (BB*SS)     // 4096

// ---------------- device scratch (no allocation allowed) -------------------
__device__ __nv_bfloat16 g_ahi[MM*DD];
__device__ __nv_bfloat16 g_alo[MM*DD];
__device__ __nv_bfloat16 g_wthi[4][DD*DD];
__device__ __nv_bfloat16 g_wtlo[4][DD*DD];
__device__ __nv_bfloat16 g_qh[BB*HH*SS*HD];
__device__ __nv_bfloat16 g_ql[BB*HH*SS*HD];
__device__ __nv_bfloat16 g_kh[BB*HH*SS*HD];
__device__ __nv_bfloat16 g_kl[BB*HH*SS*HD];
__device__ __nv_bfloat16 g_vh[BB*HH*SS*HD];
__device__ __nv_bfloat16 g_vl[BB*HH*SS*HD];

// ---------------- prepass: fp32 -> bf16 hi/lo split -------------------------
__global__ __launch_bounds__(256)
void split_kernel(const float4* __restrict__ X, __nv_bfloat16* __restrict__ Hi,
                  __nv_bfloat16* __restrict__ Lo, int n4)
{
    union U { __nv_bfloat16 b[4]; uint64_t u; };
    for (int i = blockIdx.x * blockDim.x + threadIdx.x; i < n4;
         i += gridDim.x * blockDim.x) {
        float4 f = X[i];
        U h, l;
        float vf[4] = {f.x, f.y, f.z, f.w};
        #pragma unroll
        for (int j = 0; j < 4; ++j) {
            __nv_bfloat16 hb = __float2bfloat16(vf[j]);
            h.b[j] = hb;
            l.b[j] = __float2bfloat16(vf[j] - __bfloat162float(hb));
        }
        ((uint64_t*)Hi)[i] = h.u;
        ((uint64_t*)Lo)[i] = l.u;
    }
}

// ---------------- prepass: 4x W[k][n] -> Wt[n][k] hi/lo split ----------------
__global__ __launch_bounds__(256)
void transpose_split_kernel(const float* __restrict__ W0, const float* __restrict__ W1,
                            const float* __restrict__ W2, const float* __restrict__ W3,
                            __nv_bfloat16* __restrict__ Th,
                            __nv_bfloat16* __restrict__ Tl)
{
    __shared__ float tile[32][33];
    const float* Ws[4] = {W0, W1, W2, W3};
    const float* W = Ws[blockIdx.z];
    __nv_bfloat16* th = Th + (size_t)blockIdx.z * DD * DD;
    __nv_bfloat16* tl = Tl + (size_t)blockIdx.z * DD * DD;
    int tx = threadIdx.x, ty = threadIdx.y;
    int x = blockIdx.x * 32 + tx;
    #pragma unroll
    for (int i = 0; i < 4; ++i) {
        int y = blockIdx.y * 32 + ty + i * 8;
        tile[ty + i * 8][tx] = W[(size_t)y * DD + x];
    }
    __syncthreads();
    int xo = blockIdx.y * 32 + tx;
    #pragma unroll
    for (int i = 0; i < 4; ++i) {
        int yo = blockIdx.x * 32 + ty + i * 8;
        float v = tile[tx][ty + i * 8];
        __nv_bfloat16 hb = __float2bfloat16(v);
        th[(size_t)yo * DD + xo] = hb;
        tl[(size_t)yo * DD + xo] = __float2bfloat16(v - __bfloat162float(hb));
    }
}

// ---------------- mma.sync / cp.async helpers --------------------------------
__device__ __forceinline__ uint32_t smem_u32(const void* p) {
    uint32_t a;
    asm("{ .reg .u64 t; cvta.to.shared.u64 t, %1; cvt.u32.u64 %0, t; }"
        : "=r"(a) : "l"(p));
    return a;
}
__device__ __forceinline__ void ldmx4(uint32_t* r, uint32_t addr) {
    asm volatile("ldmatrix.sync.aligned.m8n8.x4.shared.b16 {%0,%1,%2,%3}, [%4];"
                 : "=r"(r[0]), "=r"(r[1]), "=r"(r[2]), "=r"(r[3]) : "r"(addr));
}
__device__ __forceinline__ void ldmx4t(uint32_t* r, uint32_t addr) {
    asm volatile("ldmatrix.sync.aligned.m8n8.x4.trans.shared.b16 {%0,%1,%2,%3}, [%4];"
                 : "=r"(r[0]), "=r"(r[1]), "=r"(r[2]), "=r"(r[3]) : "r"(addr));
}
__device__ __forceinline__ void mma_bf16(float* c, const uint32_t* a,
                                         uint32_t b0, uint32_t b1) {
    asm volatile(
        "mma.sync.aligned.m16n8k16.row.col.f32.bf16.bf16.f32 "
        "{%0,%1,%2,%3}, {%4,%5,%6,%7}, {%8,%9}, {%0,%1,%2,%3};"
        : "+f"(c[0]), "+f"(c[1]), "+f"(c[2]), "+f"(c[3])
        : "r"(a[0]), "r"(a[1]), "r"(a[2]), "r"(a[3]), "r"(b0), "r"(b1));
}
__device__ __forceinline__ float ex2f(float x) {
    float y; asm("ex2.approx.f32 %0, %1;" : "=f"(y) : "f"(x)); return y;
}
__device__ __forceinline__ uint32_t pack2(__nv_bfloat16 a, __nv_bfloat16 b) {
    __nv_bfloat162 t = __halves2bfloat162(a, b);
    return *(uint32_t*)&t;
}
__device__ __forceinline__ uint32_t pack_bf16x2(float a, float b) {
    __nv_bfloat162 t = __floats2bfloat162_rn(a, b);
    return *(uint32_t*)&t;
}
__device__ __forceinline__ void cpa16(uint32_t dst, const void* src) {
    asm volatile("cp.async.cg.shared.global [%0], [%1], 16;" :: "r"(dst), "l"(src));
}
__device__ __forceinline__ void cpa_commit() {
    asm volatile("cp.async.commit_group;" ::: "memory");
}
template<int N> __device__ __forceinline__ void cpa_wait() {
    asm volatile("cp.async.wait_group %0;" :: "n"(N) : "memory");
}

// ---------------- HMMA GEMM core (swizzled 64B rows, 3-stage) ----------------
// Stage holds Ahi|Alo|Bhi|Blo 128x32 bf16 tiles (64B rows, XOR swizzle).
#define GCH 32
#define GOP 8192                     // 128 rows * 64 B
#define GSTG (4*GOP)                 // 32768 B per stage
#define GEMM_SMEM (3*GSTG)           // 98304 B

// swizzle for 64B rows: slot(c16) ^= (row>>1)&3  (conflict-free 8-row phases)
__device__ __forceinline__ uint32_t sw64(uint32_t off) {
    return off ^ (((off >> 7) & 3u) << 4);
}

template<typename EPI>
__device__ __forceinline__ void gemm_core(
    const __nv_bfloat16* Ahi, const __nv_bfloat16* Alo,
    const __nv_bfloat16* Bhi, const __nv_bfloat16* Blo,
    int m0, int n0, EPI epi)
{
    extern __shared__ __align__(16) char gsm[];
    const uint32_t base = smem_u32(gsm);

    const int tid  = threadIdx.x;
    const int wid  = tid >> 5;
    const int lane = tid & 31;
    const int wm0 = (wid & 3) * 32;
    const int wn0 = (wid >> 2) * 64;

    const uint4* srcs[4] = {(const uint4*)Ahi, (const uint4*)Alo,
                            (const uint4*)Bhi, (const uint4*)Blo};

    // copy mapping: 2048 uint4 per chunk, 8 per thread
    int cmat[8], crow[8], cc4[8];
    uint32_t cdst[8];
    #pragma unroll
    for (int i = 0; i < 8; ++i) {
        int idx = tid + i * 256;
        cmat[i] = idx >> 9;
        int w = idx & 511;
        crow[i] = w >> 2;
        cc4[i]  = w & 3;
        cdst[i] = base + cmat[i]*GOP + sw64(crow[i]*64 + cc4[i]*16);
    }

    auto issue = [&](int t) {
        const uint32_t so = (t % 3) * GSTG;
        #pragma unroll
        for (int i = 0; i < 8; ++i) {
            const int r0 = (cmat[i] < 2) ? m0 : n0;
            cpa16(cdst[i] + so, srcs[cmat[i]] + (size_t)(r0 + crow[i])*128 + t*4 + cc4[i]);
        }
        cpa_commit();
    };

    // frag byte offsets within operand (row*64 + col), XOR constant per frag
    uint32_t aoffb[2], axor[2], boffb[4], bxor[4];
    #pragma unroll
    for (int mf = 0; mf < 2; ++mf) {
        int row = wm0 + mf*16 + (lane & 15);
        aoffb[mf] = row*64 + (lane >> 4)*16;
        axor[mf]  = ((row >> 1) & 3u) << 4;
    }
    #pragma unroll
    for (int np = 0; np < 4; ++np) {
        int row = wn0 + np*16 + ((lane >> 4) & 1)*8 + (lane & 7);
        boffb[np] = row*64 + ((lane >> 3) & 1)*16;
        bxor[np]  = ((row >> 1) & 3u) << 4;
    }

    float acc[2][8][4] = {};

    auto compute = [&](int stg) {
        const uint32_t sb = base + stg * GSTG;
        #pragma unroll
        for (int ks2 = 0; ks2 < 64; ks2 += 32) {       // bytes: k16 step = 32B
            uint32_t afh[2][4], afl[2][4], bfh[4][4], bfl[4][4];
            #pragma unroll
            for (int mf = 0; mf < 2; ++mf) {
                uint32_t o = (aoffb[mf] + ks2) ^ axor[mf];
                ldmx4(afh[mf], sb + o);
                ldmx4(afl[mf], sb + GOP + o);
            }
            #pragma unroll
            for (int np = 0; np < 4; ++np) {
                uint32_t o = (boffb[np] + ks2) ^ bxor[np];
                ldmx4(bfh[np], sb + 2*GOP + o);
                ldmx4(bfl[np], sb + 3*GOP + o);
            }
            #pragma unroll
            for (int mf = 0; mf < 2; ++mf)
                #pragma unroll
                for (int np = 0; np < 4; ++np) {
                    mma_bf16(acc[mf][np*2+0], afh[mf], bfh[np][0], bfh[np][1]);
                    mma_bf16(acc[mf][np*2+1], afh[mf], bfh[np][2], bfh[np][3]);
                    mma_bf16(acc[mf][np*2+0], afh[mf], bfl[np][0], bfl[np][1]);
                    mma_bf16(acc[mf][np*2+1], afh[mf], bfl[np][2], bfl[np][3]);
                    mma_bf16(acc[mf][np*2+0], afl[mf], bfh[np][0], bfh[np][1]);
                    mma_bf16(acc[mf][np*2+1], afl[mf], bfh[np][2], bfh[np][3]);
                }
        }
    };

    issue(0); issue(1);
    for (int t = 0; t < GCH; ++t) {
        if (t + 1 < GCH) cpa_wait<1>(); else cpa_wait<0>();
        __syncthreads();
        if (t + 2 < GCH) issue(t + 2);
        compute(t % 3);
    }

    const int qrow = lane >> 2;
    const int qcol = (lane & 3) * 2;
    #pragma unroll
    for (int mf = 0; mf < 2; ++mf)
        #pragma unroll
        for (int nf = 0; nf < 8; ++nf)
            #pragma unroll
            for (int half = 0; half < 2; ++half) {
                const int m = m0 + wm0 + mf*16 + qrow + half*8;
                const int n = n0 + wn0 + nf*8 + qcol;
                epi(m, n, acc[mf][nf][half*2 + 0], acc[mf][nf][half*2 + 1]);
            }
}

// fused QKV projection: grid.x = 24 (gemm = x>>3), grid.y = 32
__global__ __launch_bounds__(256, 2)
void mma_gemm_qkv(const __nv_bfloat16* __restrict__ Ahi, const __nv_bfloat16* __restrict__ Alo,
                  const __nv_bfloat16* __restrict__ Whi, const __nv_bfloat16* __restrict__ Wlo,
                  __nv_bfloat16* __restrict__ qh, __nv_bfloat16* __restrict__ ql,
                  __nv_bfloat16* __restrict__ kh, __nv_bfloat16* __restrict__ kl,
                  __nv_bfloat16* __restrict__ vh, __nv_bfloat16* __restrict__ vl)
{
    const int g  = blockIdx.x >> 3;
    const int n0 = (blockIdx.x & 7) * 128;
    const int m0 = blockIdx.y * 128;
    const __nv_bfloat16* Bhi = Whi + (size_t)g * DD * DD;
    const __nv_bfloat16* Blo = Wlo + (size_t)g * DD * DD;
    __nv_bfloat16* Yh = (g == 0) ? qh : (g == 1) ? kh : vh;
    __nv_bfloat16* Yl = (g == 0) ? ql : (g == 1) ? kl : vl;

    gemm_core(Ahi, Alo, Bhi, Blo, m0, n0,
        [&](int m, int n, float cx, float cy) {
            const int b = m >> 11, s = m & (SS - 1);
            const int h = n >> 6, hd = n & 63;
            const size_t off = (((size_t)b*HH + h)*SS + s)*HD + hd;
            __nv_bfloat16 hx = __float2bfloat16(cx);
            __nv_bfloat16 hy = __float2bfloat16(cy);
            *(uint32_t*)(Yh + off) = pack2(hx, hy);
            *(uint32_t*)(Yl + off) = pack_bf16x2(
                cx - __bfloat162float(hx), cy - __bfloat162float(hy));
        });
}

// output projection + bias
__global__ __launch_bounds__(256, 2)
void mma_gemm_out(const __nv_bfloat16* __restrict__ Ahi, const __nv_bfloat16* __restrict__ Alo,
                  const __nv_bfloat16* __restrict__ Bhi, const __nv_bfloat16* __restrict__ Blo,
                  float* __restrict__ Yf, const float* __restrict__ bias)
{
    const int n0 = blockIdx.x * 128;
    const int m0 = blockIdx.y * 128;
    gemm_core(Ahi, Alo, Bhi, Blo, m0, n0,
        [&](int m, int n, float cx, float cy) {
            float2* dst = (float2*)(Yf + (size_t)m * DD + n);
            *dst = make_float2(cx + bias[n], cy + bias[n + 1]);
        });
}

// ---------------- HMMA flash attention (3-stage, 1 sync/step) ----------------
#define KST 72
#define STAGE (4*64*KST*2)           // 36864 B
#define ATTN_SMEM (3*STAGE)          // 110592 B
#define LOG2E 1.4426950408889634f
#define SBIAS (16.0f * LOG2E)

__global__ __launch_bounds__(256, 2)
void attn_mma(const __nv_bfloat16* __restrict__ Qh, const __nv_bfloat16* __restrict__ Ql,
              const __nv_bfloat16* __restrict__ Kh, const __nv_bfloat16* __restrict__ Kl,
              const __nv_bfloat16* __restrict__ Vh, const __nv_bfloat16* __restrict__ Vl,
              __nv_bfloat16* __restrict__ Chi, __nv_bfloat16* __restrict__ Clo)
{
    extern __shared__ __align__(16) char dynsm[];
    __nv_bfloat16* sm = (__nv_bfloat16*)dynsm;

    const int bh  = blockIdx.y;
    const int tid = threadIdx.x;
    const int wid = tid >> 5;
    const int lane = tid & 31;
    const int wrow0 = wid * 16;

    const size_t hbase = (size_t)bh * SS * HD;
    const uint4* Kh4 = (const uint4*)(Kh + hbase);
    const uint4* Kl4 = (const uint4*)(Kl + hbase);
    const uint4* Vh4 = (const uint4*)(Vh + hbase);
    const uint4* Vl4 = (const uint4*)(Vl + hbase);

    const uint32_t sbase = smem_u32(sm);

    uint32_t kbase[4];
    #pragma unroll
    for (int ng = 0; ng < 4; ++ng) {
        int krow = ng*16 + ((lane >> 4) & 1)*8 + (lane & 7);
        kbase[ng] = (krow * KST + ((lane >> 3) & 1) * 8) * 2;
    }
    const uint32_t vrowoff = ((((lane >> 3) & 1)*8 + (lane & 7)) * KST) * 2;
    uint32_t vcol[4];
    #pragma unroll
    for (int ng = 0; ng < 4; ++ng)
        vcol[ng] = (ng*16 + (lane >> 4) * 8) * 2;

    uint32_t cpa_dst[8];
    int cpa_src[8];
    #pragma unroll
    for (int i = 0; i < 8; ++i) {
        int idx = tid + i * 256;
        int tile = idx >> 9;
        int within = idx & 511;
        int row = within >> 3, c = within & 7;
        cpa_dst[i] = sbase + ((tile*64 + row)*KST + c*8) * 2;
        cpa_src[i] = within;
    }

    auto issue = [&](int kt) {
        const uint4* srcs[4] = {Kh4 + kt*512, Kl4 + kt*512, Vh4 + kt*512, Vl4 + kt*512};
        const uint32_t soff = (kt % 3) * STAGE;
        #pragma unroll
        for (int i = 0; i < 8; ++i) {
            int tile = (tid + i*256) >> 9;
            cpa16(cpa_dst[i] + soff, srcs[tile] + cpa_src[i]);
        }
        cpa_commit();
    };

    #pragma unroll 1
    for (int half = 0; half < 2; ++half) {
        const int qi = half ? (15 - blockIdx.x) : blockIdx.x;

        __syncthreads();
        {
            const uint4* Qh4 = (const uint4*)(Qh + hbase + (size_t)qi*128*HD);
            const uint4* Ql4 = (const uint4*)(Ql + hbase + (size_t)qi*128*HD);
            const uint4* bufs[2] = {Qh4, Ql4};
            #pragma unroll
            for (int i = 0; i < 8; ++i) {
                int idx = tid + i * 256;
                int buf = idx >> 10;
                int within = idx & 1023;
                int row = within >> 3, c = within & 7;
                uint4 v = bufs[buf][within];
                *(uint4*)&sm[(buf*128 + row)*KST + c*8] = v;
            }
        }
        __syncthreads();

        uint32_t qhf[4][4], qlf[4][4];
        {
            const uint32_t roff = ((wrow0 + (lane & 15)) * KST + (lane >> 4) * 8) * 2;
            #pragma unroll
            for (int ks = 0; ks < 4; ++ks) {
                ldmx4(qhf[ks], sbase + roff + ks * 32);
                ldmx4(qlf[ks], sbase + roff + 128*KST*2 + ks * 32);
            }
        }
        __syncthreads();

        float lrow[2] = {0.0f, 0.0f};
        float o[8][4] = {};

        const int wmax = qi*128 + wrow0 + 15;
        const int nsteps = 2*qi + 2;

        issue(0);
        issue(1);            // nsteps >= 2 always
        for (int kt = 0; kt < nsteps; ++kt) {
            if (kt + 1 < nsteps) cpa_wait<1>(); else cpa_wait<0>();
            __syncthreads();
            if (kt + 2 < nsteps) issue(kt + 2);

            const uint32_t st = sbase + (kt % 3) * STAGE;
            const uint32_t sKh = st;
            const uint32_t sKl = st + 64*KST*2;
            const uint32_t sVh = st + 128*KST*2;
            const uint32_t sVl = st + 192*KST*2;

            if (kt*64 <= wmax) {
                float s[8][4] = {};
                #pragma unroll
                for (int ks = 0; ks < 4; ++ks) {
                    #pragma unroll
                    for (int ng = 0; ng < 4; ++ng) {
                        uint32_t khb[4], klb[4];
                        ldmx4(khb, sKh + kbase[ng] + ks*32);
                        ldmx4(klb, sKl + kbase[ng] + ks*32);
                        mma_bf16(s[2*ng+0], qhf[ks], khb[0], khb[1]);
                        mma_bf16(s[2*ng+1], qhf[ks], khb[2], khb[3]);
                        mma_bf16(s[2*ng+0], qhf[ks], klb[0], klb[1]);
                        mma_bf16(s[2*ng+1], qhf[ks], klb[2], klb[3]);
                        mma_bf16(s[2*ng+0], qlf[ks], khb[0], khb[1]);
                        mma_bf16(s[2*ng+1], qlf[ks], khb[2], khb[3]);
                    }
                }

                // ---- fixed-max softmax: p = exp2(s*SC - SBIAS) ----
                const float SC = 0.125f * LOG2E;
                const int r0g = qi*128 + wrow0 + (lane >> 2);
                const bool needmask = (kt*64 + 63 > qi*128 + wrow0);
                #pragma unroll
                for (int nf = 0; nf < 8; ++nf)
                    #pragma unroll
                    for (int ri = 0; ri < 4; ++ri) {
                        float v = s[nf][ri] * SC - SBIAS;
                        if (needmask) {
                            int col = kt*64 + nf*8 + (lane & 3)*2 + (ri & 1);
                            int rg  = r0g + ((ri >> 1) ? 8 : 0);
                            if (col > rg) v = -1e30f;
                        }
                        float p = ex2f(v);
                        s[nf][ri] = p;
                        lrow[ri >> 1] += p;
                    }

                uint32_t pah[4][4], pal[4][4];
                #pragma unroll
                for (int ks = 0; ks < 4; ++ks) {
                    float a0 = s[2*ks][0],   a1 = s[2*ks][1];
                    float b0 = s[2*ks][2],   b1 = s[2*ks][3];
                    float c0 = s[2*ks+1][0], c1 = s[2*ks+1][1];
                    float d0 = s[2*ks+1][2], d1 = s[2*ks+1][3];
                    __nv_bfloat16 ha0 = __float2bfloat16(a0), ha1 = __float2bfloat16(a1);
                    __nv_bfloat16 hb0 = __float2bfloat16(b0), hb1 = __float2bfloat16(b1);
                    __nv_bfloat16 hc0 = __float2bfloat16(c0), hc1 = __float2bfloat16(c1);
                    __nv_bfloat16 hd0 = __float2bfloat16(d0), hd1 = __float2bfloat16(d1);
                    pah[ks][0] = pack2(ha0, ha1);
                    pah[ks][1] = pack2(hb0, hb1);
                    pah[ks][2] = pack2(hc0, hc1);
                    pah[ks][3] = pack2(hd0, hd1);
                    pal[ks][0] = pack_bf16x2(a0 - __bfloat162float(ha0), a1 - __bfloat162float(ha1));
                    pal[ks][1] = pack_bf16x2(b0 - __bfloat162float(hb0), b1 - __bfloat162float(hb1));
                    pal[ks][2] = pack_bf16x2(c0 - __bfloat162float(hc0), c1 - __bfloat162float(hc1));
                    pal[ks][3] = pack_bf16x2(d0 - __bfloat162float(hd0), d1 - __bfloat162float(hd1));
                }

                #pragma unroll
                for (int ks = 0; ks < 4; ++ks) {
                    const uint32_t vrb = vrowoff + ks*16*KST*2;
                    #pragma unroll
                    for (int ng = 0; ng < 4; ++ng) {
                        uint32_t vhb[4], vlb[4];
                        ldmx4t(vhb, sVh + vrb + vcol[ng]);
                        ldmx4t(vlb, sVl + vrb + vcol[ng]);
                        mma_bf16(o[2*ng+0], pah[ks], vhb[0], vhb[1]);
                        mma_bf16(o[2*ng+1], pah[ks], vhb[2], vhb[3]);
                        mma_bf16(o[2*ng+0], pah[ks], vlb[0], vlb[1]);
                        mma_bf16(o[2*ng+1], pah[ks], vlb[2], vlb[3]);
                        mma_bf16(o[2*ng+0], pal[ks], vhb[0], vhb[1]);
                        mma_bf16(o[2*ng+1], pal[ks], vhb[2], vhb[3]);
                    }
                }
            }
        }

        // ---- epilogue: reduce l, write ctx as bf16 hi/lo (row-major [M][D]) ----
        float l0 = lrow[0], l1 = lrow[1];
        l0 += __shfl_xor_sync(0xffffffffu, l0, 1);
        l0 += __shfl_xor_sync(0xffffffffu, l0, 2);
        l1 += __shfl_xor_sync(0xffffffffu, l1, 1);
        l1 += __shfl_xor_sync(0xffffffffu, l1, 2);
        const float inv0 = 1.0f / l0;
        const float inv1 = 1.0f / l1;
        const int b = bh >> 4, h = bh & 15;
        const int r0 = qi*128 + wrow0 + (lane >> 2);
        #pragma unroll
        for (int nf = 0; nf < 8; ++nf) {
            const int col = h*HD + nf*8 + (lane & 3)*2;
            const size_t off0 = ((size_t)b*SS + r0)*DD + col;
            const size_t off1 = ((size_t)b*SS + r0 + 8)*DD + col;
            float x0 = o[nf][0]*inv0, y0 = o[nf][1]*inv0;
            float x1 = o[nf][2]*inv1, y1 = o[nf][3]*inv1;
            __nv_bfloat16 hx0 = __float2bfloat16(x0), hy0 = __float2bfloat16(y0);
            __nv_bfloat16 hx1 = __float2bfloat16(x1), hy1 = __float2bfloat16(y1);
            *(uint32_t*)(Chi + off0) = pack2(hx0, hy0);
            *(uint32_t*)(Chi + off1) = pack2(hx1, hy1);
            *(uint32_t*)(Clo + off0) = pack_bf16x2(x0 - __bfloat162float(hx0),
                                                   y0 - __bfloat162float(hy0));
            *(uint32_t*)(Clo + off1) = pack_bf16x2(x1 - __bfloat162float(hx1),
                                                   y1 - __bfloat162float(hy1));
        }
    }
}

// ---------------------------------------------------------------------------

extern "C" void kernel_launch(void* const* d_in, const int* in_sizes, int n_in,
                              void* d_out, int out_size)
{
    const float* x  = (const float*)d_in[0];
    const float* Wq = (const float*)d_in[1];
    const float* Wk = (const float*)d_in[2];
    const float* Wv = (const float*)d_in[3];
    const float* Wo = (const float*)d_in[4];
    const float* bo = (const float*)d_in[5];
    float* out = (float*)d_out;

    __nv_bfloat16 *ahi, *alo, *wthi, *wtlo, *qh, *ql, *kh, *kl, *vh, *vl;
    cudaGetSymbolAddress((void**)&ahi,  g_ahi);
    cudaGetSymbolAddress((void**)&alo,  g_alo);
    cudaGetSymbolAddress((void**)&wthi, g_wthi);
    cudaGetSymbolAddress((void**)&wtlo, g_wtlo);
    cudaGetSymbolAddress((void**)&qh,   g_qh);
    cudaGetSymbolAddress((void**)&ql,   g_ql);
    cudaGetSymbolAddress((void**)&kh,   g_kh);
    cudaGetSymbolAddress((void**)&kl,   g_kl);
    cudaGetSymbolAddress((void**)&vh,   g_vh);
    cudaGetSymbolAddress((void**)&vl,   g_vl);

    cudaFuncSetAttribute(attn_mma, cudaFuncAttributeMaxDynamicSharedMemorySize, ATTN_SMEM);
    cudaFuncSetAttribute(mma_gemm_qkv, cudaFuncAttributeMaxDynamicSharedMemorySize, GEMM_SMEM);
    cudaFuncSetAttribute(mma_gemm_out, cudaFuncAttributeMaxDynamicSharedMemorySize, GEMM_SMEM);

    // 1. split X into bf16 hi/lo
    split_kernel<<<1024, 256>>>((const float4*)x, ahi, alo, MM*DD/4);

    // 2. transpose+split all 4 weights (one launch)
    transpose_split_kernel<<<dim3(32,32,4), dim3(32,8)>>>(Wq, Wk, Wv, Wo, wthi, wtlo);

    // 3. fused Q/K/V projections (HMMA, load-once 3-pass, 3-stage cp.async)
    mma_gemm_qkv<<<dim3(24, 32), 256, GEMM_SMEM>>>(ahi, alo, wthi, wtlo, qh, ql, kh, kl, vh, vl);

    // 4. attention (HMMA flash, balanced pairs, 3-stage cp.async, fixed-max softmax)
    attn_mma<<<dim3(8, BB*HH), 256, ATTN_SMEM>>>(qh, ql, kh, kl, vh, vl, ahi, alo);

    // 5. output projection + bias
    mma_gemm_out<<<dim3(8, 32), 256, GEMM_SMEM>>>(ahi, alo, wthi + 3*(size_t)DD*DD, wtlo + 3*(size_t)DD*DD, out, bo);
}

// round 12
// speedup vs baseline: 3.8068x; 1.0043x over previous
#include <cuda_runtime.h>
#include <cuda_bf16.h>
#include <cstdint>

#define BB 2
#define SS 2048
#define DD 1024
#define HH 16
#define HD 64
#define MM (BB*SS)     // 4096

// ---------------- device scratch (no allocation allowed) -------------------
__device__ __nv_bfloat16 g_ahi[MM*DD];
__device__ __nv_bfloat16 g_alo[MM*DD];
__device__ __nv_bfloat16 g_wthi[4][DD*DD];
__device__ __nv_bfloat16 g_wtlo[4][DD*DD];
__device__ __nv_bfloat16 g_qh[BB*HH*SS*HD];
__device__ __nv_bfloat16 g_ql[BB*HH*SS*HD];
__device__ __nv_bfloat16 g_kh[BB*HH*SS*HD];
__device__ __nv_bfloat16 g_kl[BB*HH*SS*HD];
__device__ __nv_bfloat16 g_vh[BB*HH*SS*HD];
__device__ __nv_bfloat16 g_vl[BB*HH*SS*HD];

// ---------------- prepass: fp32 -> bf16 hi/lo split -------------------------
__global__ __launch_bounds__(256)
void split_kernel(const float4* __restrict__ X, __nv_bfloat16* __restrict__ Hi,
                  __nv_bfloat16* __restrict__ Lo, int n4)
{
    union U { __nv_bfloat16 b[4]; uint64_t u; };
    for (int i = blockIdx.x * blockDim.x + threadIdx.x; i < n4;
         i += gridDim.x * blockDim.x) {
        float4 f = X[i];
        U h, l;
        float vf[4] = {f.x, f.y, f.z, f.w};
        #pragma unroll
        for (int j = 0; j < 4; ++j) {
            __nv_bfloat16 hb = __float2bfloat16(vf[j]);
            h.b[j] = hb;
            l.b[j] = __float2bfloat16(vf[j] - __bfloat162float(hb));
        }
        ((uint64_t*)Hi)[i] = h.u;
        ((uint64_t*)Lo)[i] = l.u;
    }
}

// ---------------- prepass: 4x W[k][n] -> Wt[n][k] hi/lo split ----------------
__global__ __launch_bounds__(256)
void transpose_split_kernel(const float* __restrict__ W0, const float* __restrict__ W1,
                            const float* __restrict__ W2, const float* __restrict__ W3,
                            __nv_bfloat16* __restrict__ Th,
                            __nv_bfloat16* __restrict__ Tl)
{
    __shared__ float tile[32][33];
    const float* Ws[4] = {W0, W1, W2, W3};
    const float* W = Ws[blockIdx.z];
    __nv_bfloat16* th = Th + (size_t)blockIdx.z * DD * DD;
    __nv_bfloat16* tl = Tl + (size_t)blockIdx.z * DD * DD;
    int tx = threadIdx.x, ty = threadIdx.y;
    int x = blockIdx.x * 32 + tx;
    #pragma unroll
    for (int i = 0; i < 4; ++i) {
        int y = blockIdx.y * 32 + ty + i * 8;
        tile[ty + i * 8][tx] = W[(size_t)y * DD + x];
    }
    __syncthreads();
    int xo = blockIdx.y * 32 + tx;
    #pragma unroll
    for (int i = 0; i < 4; ++i) {
        int yo = blockIdx.x * 32 + ty + i * 8;
        float v = tile[tx][ty + i * 8];
        __nv_bfloat16 hb = __float2bfloat16(v);
        th[(size_t)yo * DD + xo] = hb;
        tl[(size_t)yo * DD + xo] = __float2bfloat16(v - __bfloat162float(hb));
    }
}

// ---------------- mma.sync / cp.async helpers --------------------------------
__device__ __forceinline__ uint32_t smem_u32(const void* p) {
    uint32_t a;
    asm("{ .reg .u64 t; cvta.to.shared.u64 t, %1; cvt.u32.u64 %0, t; }"
        : "=r"(a) : "l"(p));
    return a;
}
__device__ __forceinline__ void ldmx4(uint32_t* r, uint32_t addr) {
    asm volatile("ldmatrix.sync.aligned.m8n8.x4.shared.b16 {%0,%1,%2,%3}, [%4];"
                 : "=r"(r[0]), "=r"(r[1]), "=r"(r[2]), "=r"(r[3]) : "r"(addr));
}
__device__ __forceinline__ void ldmx4t(uint32_t* r, uint32_t addr) {
    asm volatile("ldmatrix.sync.aligned.m8n8.x4.trans.shared.b16 {%0,%1,%2,%3}, [%4];"
                 : "=r"(r[0]), "=r"(r[1]), "=r"(r[2]), "=r"(r[3]) : "r"(addr));
}
__device__ __forceinline__ void mma_bf16(float* c, const uint32_t* a,
                                         uint32_t b0, uint32_t b1) {
    asm volatile(
        "mma.sync.aligned.m16n8k16.row.col.f32.bf16.bf16.f32 "
        "{%0,%1,%2,%3}, {%4,%5,%6,%7}, {%8,%9}, {%0,%1,%2,%3};"
        : "+f"(c[0]), "+f"(c[1]), "+f"(c[2]), "+f"(c[3])
        : "r"(a[0]), "r"(a[1]), "r"(a[2]), "r"(a[3]), "r"(b0), "r"(b1));
}
__device__ __forceinline__ float ex2f(float x) {
    float y; asm("ex2.approx.f32 %0, %1;" : "=f"(y) : "f"(x)); return y;
}
__device__ __forceinline__ uint32_t pack2(__nv_bfloat16 a, __nv_bfloat16 b) {
    __nv_bfloat162 t = __halves2bfloat162(a, b);
    return *(uint32_t*)&t;
}
__device__ __forceinline__ uint32_t pack_bf16x2(float a, float b) {
    __nv_bfloat162 t = __floats2bfloat162_rn(a, b);
    return *(uint32_t*)&t;
}
__device__ __forceinline__ void cpa16(uint32_t dst, const void* src) {
    asm volatile("cp.async.cg.shared.global [%0], [%1], 16;" :: "r"(dst), "l"(src));
}
__device__ __forceinline__ void cpa_commit() {
    asm volatile("cp.async.commit_group;" ::: "memory");
}
template<int N> __device__ __forceinline__ void cpa_wait() {
    asm volatile("cp.async.wait_group %0;" :: "n"(N) : "memory");
}

// ---------------- HMMA GEMM core (swizzled 64B rows, 3-stage) ----------------
#define GCH 32
#define GOP 8192                     // 128 rows * 64 B
#define GSTG (4*GOP)                 // 32768 B per stage
#define GEMM_SMEM (3*GSTG)           // 98304 B

__device__ __forceinline__ uint32_t sw64(uint32_t off) {
    return off ^ (((off >> 7) & 3u) << 4);
}

template<typename EPI>
__device__ __forceinline__ void gemm_core(
    const __nv_bfloat16* Ahi, const __nv_bfloat16* Alo,
    const __nv_bfloat16* Bhi, const __nv_bfloat16* Blo,
    int m0, int n0, EPI epi)
{
    extern __shared__ __align__(16) char gsm[];
    const uint32_t base = smem_u32(gsm);

    const int tid  = threadIdx.x;
    const int wid  = tid >> 5;
    const int lane = tid & 31;
    const int wm0 = (wid & 3) * 32;
    const int wn0 = (wid >> 2) * 64;

    const uint4* srcs[4] = {(const uint4*)Ahi, (const uint4*)Alo,
                            (const uint4*)Bhi, (const uint4*)Blo};

    int cmat[8], crow[8], cc4[8];
    uint32_t cdst[8];
    #pragma unroll
    for (int i = 0; i < 8; ++i) {
        int idx = tid + i * 256;
        cmat[i] = idx >> 9;
        int w = idx & 511;
        crow[i] = w >> 2;
        cc4[i]  = w & 3;
        cdst[i] = base + cmat[i]*GOP + sw64(crow[i]*64 + cc4[i]*16);
    }

    auto issue = [&](int t) {
        const uint32_t so = (t % 3) * GSTG;
        #pragma unroll
        for (int i = 0; i < 8; ++i) {
            const int r0 = (cmat[i] < 2) ? m0 : n0;
            cpa16(cdst[i] + so, srcs[cmat[i]] + (size_t)(r0 + crow[i])*128 + t*4 + cc4[i]);
        }
        cpa_commit();
    };

    uint32_t aoffb[2], axor[2], boffb[4], bxor[4];
    #pragma unroll
    for (int mf = 0; mf < 2; ++mf) {
        int row = wm0 + mf*16 + (lane & 15);
        aoffb[mf] = row*64 + (lane >> 4)*16;
        axor[mf]  = ((row >> 1) & 3u) << 4;
    }
    #pragma unroll
    for (int np = 0; np < 4; ++np) {
        int row = wn0 + np*16 + ((lane >> 4) & 1)*8 + (lane & 7);
        boffb[np] = row*64 + ((lane >> 3) & 1)*16;
        bxor[np]  = ((row >> 1) & 3u) << 4;
    }

    float acc[2][8][4] = {};

    auto compute = [&](int stg) {
        const uint32_t sb = base + stg * GSTG;
        #pragma unroll
        for (int ks2 = 0; ks2 < 64; ks2 += 32) {
            uint32_t afh[2][4], afl[2][4], bfh[4][4], bfl[4][4];
            #pragma unroll
            for (int mf = 0; mf < 2; ++mf) {
                uint32_t o = (aoffb[mf] + ks2) ^ axor[mf];
                ldmx4(afh[mf], sb + o);
                ldmx4(afl[mf], sb + GOP + o);
            }
            #pragma unroll
            for (int np = 0; np < 4; ++np) {
                uint32_t o = (boffb[np] + ks2) ^ bxor[np];
                ldmx4(bfh[np], sb + 2*GOP + o);
                ldmx4(bfl[np], sb + 3*GOP + o);
            }
            #pragma unroll
            for (int mf = 0; mf < 2; ++mf)
                #pragma unroll
                for (int np = 0; np < 4; ++np) {
                    mma_bf16(acc[mf][np*2+0], afh[mf], bfh[np][0], bfh[np][1]);
                    mma_bf16(acc[mf][np*2+1], afh[mf], bfh[np][2], bfh[np][3]);
                    mma_bf16(acc[mf][np*2+0], afh[mf], bfl[np][0], bfl[np][1]);
                    mma_bf16(acc[mf][np*2+1], afh[mf], bfl[np][2], bfl[np][3]);
                    mma_bf16(acc[mf][np*2+0], afl[mf], bfh[np][0], bfh[np][1]);
                    mma_bf16(acc[mf][np*2+1], afl[mf], bfh[np][2], bfh[np][3]);
                }
        }
    };

    issue(0); issue(1);
    for (int t = 0; t < GCH; ++t) {
        if (t + 1 < GCH) cpa_wait<1>(); else cpa_wait<0>();
        __syncthreads();
        if (t + 2 < GCH) issue(t + 2);
        compute(t % 3);
    }

    const int qrow = lane >> 2;
    const int qcol = (lane & 3) * 2;
    #pragma unroll
    for (int mf = 0; mf < 2; ++mf)
        #pragma unroll
        for (int nf = 0; nf < 8; ++nf)
            #pragma unroll
            for (int half = 0; half < 2; ++half) {
                const int m = m0 + wm0 + mf*16 + qrow + half*8;
                const int n = n0 + wn0 + nf*8 + qcol;
                epi(m, n, acc[mf][nf][half*2 + 0], acc[mf][nf][half*2 + 1]);
            }
}

// fused QKV projection: grid.x = 24 (gemm = x>>3), grid.y = 32
__global__ __launch_bounds__(256, 2)
void mma_gemm_qkv(const __nv_bfloat16* __restrict__ Ahi, const __nv_bfloat16* __restrict__ Alo,
                  const __nv_bfloat16* __restrict__ Whi, const __nv_bfloat16* __restrict__ Wlo,
                  __nv_bfloat16* __restrict__ qh, __nv_bfloat16* __restrict__ ql,
                  __nv_bfloat16* __restrict__ kh, __nv_bfloat16* __restrict__ kl,
                  __nv_bfloat16* __restrict__ vh, __nv_bfloat16* __restrict__ vl)
{
    const int g  = blockIdx.x >> 3;
    const int n0 = (blockIdx.x & 7) * 128;
    const int m0 = blockIdx.y * 128;
    const __nv_bfloat16* Bhi = Whi + (size_t)g * DD * DD;
    const __nv_bfloat16* Blo = Wlo + (size_t)g * DD * DD;
    __nv_bfloat16* Yh = (g == 0) ? qh : (g == 1) ? kh : vh;
    __nv_bfloat16* Yl = (g == 0) ? ql : (g == 1) ? kl : vl;

    gemm_core(Ahi, Alo, Bhi, Blo, m0, n0,
        [&](int m, int n, float cx, float cy) {
            const int b = m >> 11, s = m & (SS - 1);
            const int h = n >> 6, hd = n & 63;
            const size_t off = (((size_t)b*HH + h)*SS + s)*HD + hd;
            __nv_bfloat16 hx = __float2bfloat16(cx);
            __nv_bfloat16 hy = __float2bfloat16(cy);
            *(uint32_t*)(Yh + off) = pack2(hx, hy);
            *(uint32_t*)(Yl + off) = pack_bf16x2(
                cx - __bfloat162float(hx), cy - __bfloat162float(hy));
        });
}

// output projection + bias
__global__ __launch_bounds__(256, 2)
void mma_gemm_out(const __nv_bfloat16* __restrict__ Ahi, const __nv_bfloat16* __restrict__ Alo,
                  const __nv_bfloat16* __restrict__ Bhi, const __nv_bfloat16* __restrict__ Blo,
                  float* __restrict__ Yf, const float* __restrict__ bias)
{
    const int n0 = blockIdx.x * 128;
    const int m0 = blockIdx.y * 128;
    gemm_core(Ahi, Alo, Bhi, Blo, m0, n0,
        [&](int m, int n, float cx, float cy) {
            float2* dst = (float2*)(Yf + (size_t)m * DD + n);
            *dst = make_float2(cx + bias[n], cy + bias[n + 1]);
        });
}

// ---------------- HMMA flash attention (2-stage, 3-pass PV) ------------------
#define KST 72
#define STAGE (4*64*KST*2)           // 36864 B
#define ATTN_SMEM (2*STAGE)          // 73728 B
#define LOG2E 1.4426950408889634f
#define SBIAS (16.0f * LOG2E)

__global__ __launch_bounds__(256, 2)
void attn_mma(const __nv_bfloat16* __restrict__ Qh, const __nv_bfloat16* __restrict__ Ql,
              const __nv_bfloat16* __restrict__ Kh, const __nv_bfloat16* __restrict__ Kl,
              const __nv_bfloat16* __restrict__ Vh, const __nv_bfloat16* __restrict__ Vl,
              __nv_bfloat16* __restrict__ Chi, __nv_bfloat16* __restrict__ Clo)
{
    extern __shared__ __align__(16) char dynsm[];
    __nv_bfloat16* sm = (__nv_bfloat16*)dynsm;

    const int bh  = blockIdx.y;
    const int tid = threadIdx.x;
    const int wid = tid >> 5;
    const int lane = tid & 31;
    const int wrow0 = wid * 16;

    const size_t hbase = (size_t)bh * SS * HD;
    const uint4* Kh4 = (const uint4*)(Kh + hbase);
    const uint4* Kl4 = (const uint4*)(Kl + hbase);
    const uint4* Vh4 = (const uint4*)(Vh + hbase);
    const uint4* Vl4 = (const uint4*)(Vl + hbase);

    const uint32_t sbase = smem_u32(sm);

    uint32_t kbase[4];
    #pragma unroll
    for (int ng = 0; ng < 4; ++ng) {
        int krow = ng*16 + ((lane >> 4) & 1)*8 + (lane & 7);
        kbase[ng] = (krow * KST + ((lane >> 3) & 1) * 8) * 2;
    }
    const uint32_t vrowoff = ((((lane >> 3) & 1)*8 + (lane & 7)) * KST) * 2;
    uint32_t vcol[4];
    #pragma unroll
    for (int ng = 0; ng < 4; ++ng)
        vcol[ng] = (ng*16 + (lane >> 4) * 8) * 2;

    uint32_t cpa_dst[8];
    int cpa_src[8];
    #pragma unroll
    for (int i = 0; i < 8; ++i) {
        int idx = tid + i * 256;
        int tile = idx >> 9;
        int within = idx & 511;
        int row = within >> 3, c = within & 7;
        cpa_dst[i] = sbase + ((tile*64 + row)*KST + c*8) * 2;
        cpa_src[i] = within;
    }

    auto issue = [&](int kt) {
        const uint4* srcs[4] = {Kh4 + kt*512, Kl4 + kt*512, Vh4 + kt*512, Vl4 + kt*512};
        const uint32_t soff = (kt & 1) * STAGE;
        #pragma unroll
        for (int i = 0; i < 8; ++i) {
            int tile = (tid + i*256) >> 9;
            cpa16(cpa_dst[i] + soff, srcs[tile] + cpa_src[i]);
        }
        cpa_commit();
    };

    #pragma unroll 1
    for (int half = 0; half < 2; ++half) {
        const int qi = half ? (15 - blockIdx.x) : blockIdx.x;

        __syncthreads();
        {
            const uint4* Qh4 = (const uint4*)(Qh + hbase + (size_t)qi*128*HD);
            const uint4* Ql4 = (const uint4*)(Ql + hbase + (size_t)qi*128*HD);
            const uint4* bufs[2] = {Qh4, Ql4};
            #pragma unroll
            for (int i = 0; i < 8; ++i) {
                int idx = tid + i * 256;
                int buf = idx >> 10;
                int within = idx & 1023;
                int row = within >> 3, c = within & 7;
                uint4 v = bufs[buf][within];
                *(uint4*)&sm[(buf*128 + row)*KST + c*8] = v;
            }
        }
        __syncthreads();

        uint32_t qhf[4][4], qlf[4][4];
        {
            const uint32_t roff = ((wrow0 + (lane & 15)) * KST + (lane >> 4) * 8) * 2;
            #pragma unroll
            for (int ks = 0; ks < 4; ++ks) {
                ldmx4(qhf[ks], sbase + roff + ks * 32);
                ldmx4(qlf[ks], sbase + roff + 128*KST*2 + ks * 32);
            }
        }
        __syncthreads();

        float lrow[2] = {0.0f, 0.0f};
        float o[8][4] = {};

        const int wmax = qi*128 + wrow0 + 15;
        const int nsteps = 2*qi + 2;

        issue(0);
        for (int kt = 0; kt < nsteps; ++kt) {
            if (kt + 1 < nsteps) { issue(kt + 1); cpa_wait<1>(); }
            else                 { cpa_wait<0>(); }
            __syncthreads();

            const uint32_t st = sbase + (kt & 1) * STAGE;
            const uint32_t sKh = st;
            const uint32_t sKl = st + 64*KST*2;
            const uint32_t sVh = st + 128*KST*2;
            const uint32_t sVl = st + 192*KST*2;

            if (kt*64 <= wmax) {
                float s[8][4] = {};
                #pragma unroll
                for (int ks = 0; ks < 4; ++ks) {
                    #pragma unroll
                    for (int ng = 0; ng < 4; ++ng) {
                        uint32_t khb[4], klb[4];
                        ldmx4(khb, sKh + kbase[ng] + ks*32);
                        ldmx4(klb, sKl + kbase[ng] + ks*32);
                        mma_bf16(s[2*ng+0], qhf[ks], khb[0], khb[1]);
                        mma_bf16(s[2*ng+1], qhf[ks], khb[2], khb[3]);
                        mma_bf16(s[2*ng+0], qhf[ks], klb[0], klb[1]);
                        mma_bf16(s[2*ng+1], qhf[ks], klb[2], klb[3]);
                        mma_bf16(s[2*ng+0], qlf[ks], khb[0], khb[1]);
                        mma_bf16(s[2*ng+1], qlf[ks], khb[2], khb[3]);
                    }
                }

                // ---- fixed-max softmax: p = exp2(s*SC - SBIAS) ----
                const float SC = 0.125f * LOG2E;
                const int r0g = qi*128 + wrow0 + (lane >> 2);
                const bool needmask = (kt*64 + 63 > qi*128 + wrow0);
                #pragma unroll
                for (int nf = 0; nf < 8; ++nf)
                    #pragma unroll
                    for (int ri = 0; ri < 4; ++ri) {
                        float v = s[nf][ri] * SC - SBIAS;
                        if (needmask) {
                            int col = kt*64 + nf*8 + (lane & 3)*2 + (ri & 1);
                            int rg  = r0g + ((ri >> 1) ? 8 : 0);
                            if (col > rg) v = -1e30f;
                        }
                        float p = ex2f(v);
                        s[nf][ri] = p;
                        lrow[ri >> 1] += p;
                    }

                uint32_t pah[4][4], pal[4][4];
                #pragma unroll
                for (int ks = 0; ks < 4; ++ks) {
                    float a0 = s[2*ks][0],   a1 = s[2*ks][1];
                    float b0 = s[2*ks][2],   b1 = s[2*ks][3];
                    float c0 = s[2*ks+1][0], c1 = s[2*ks+1][1];
                    float d0 = s[2*ks+1][2], d1 = s[2*ks+1][3];
                    __nv_bfloat16 ha0 = __float2bfloat16(a0), ha1 = __float2bfloat16(a1);
                    __nv_bfloat16 hb0 = __float2bfloat16(b0), hb1 = __float2bfloat16(b1);
                    __nv_bfloat16 hc0 = __float2bfloat16(c0), hc1 = __float2bfloat16(c1);
                    __nv_bfloat16 hd0 = __float2bfloat16(d0), hd1 = __float2bfloat16(d1);
                    pah[ks][0] = pack2(ha0, ha1);
                    pah[ks][1] = pack2(hb0, hb1);
                    pah[ks][2] = pack2(hc0, hc1);
                    pah[ks][3] = pack2(hd0, hd1);
                    pal[ks][0] = pack_bf16x2(a0 - __bfloat162float(ha0), a1 - __bfloat162float(ha1));
                    pal[ks][1] = pack_bf16x2(b0 - __bfloat162float(hb0), b1 - __bfloat162float(hb1));
                    pal[ks][2] = pack_bf16x2(c0 - __bfloat162float(hc0), c1 - __bfloat162float(hc1));
                    pal[ks][3] = pack_bf16x2(d0 - __bfloat162float(hd0), d1 - __bfloat162float(hd1));
                }

                #pragma unroll
                for (int ks = 0; ks < 4; ++ks) {
                    const uint32_t vrb = vrowoff + ks*16*KST*2;
                    #pragma unroll
                    for (int ng = 0; ng < 4; ++ng) {
                        uint32_t vhb[4], vlb[4];
                        ldmx4t(vhb, sVh + vrb + vcol[ng]);
                        ldmx4t(vlb, sVl + vrb + vcol[ng]);
                        mma_bf16(o[2*ng+0], pah[ks], vhb[0], vhb[1]);
                        mma_bf16(o[2*ng+1], pah[ks], vhb[2], vhb[3]);
                        mma_bf16(o[2*ng+0], pah[ks], vlb[0], vlb[1]);
                        mma_bf16(o[2*ng+1], pah[ks], vlb[2], vlb[3]);
                        mma_bf16(o[2*ng+0], pal[ks], vhb[0], vhb[1]);
                        mma_bf16(o[2*ng+1], pal[ks], vhb[2], vhb[3]);
                    }
                }
            }
            __syncthreads();
        }

        // ---- epilogue: reduce l, write ctx as bf16 hi/lo (row-major [M][D]) ----
        float l0 = lrow[0], l1 = lrow[1];
        l0 += __shfl_xor_sync(0xffffffffu, l0, 1);
        l0 += __shfl_xor_sync(0xffffffffu, l0, 2);
        l1 += __shfl_xor_sync(0xffffffffu, l1, 1);
        l1 += __shfl_xor_sync(0xffffffffu, l1, 2);
        const float inv0 = 1.0f / l0;
        const float inv1 = 1.0f / l1;
        const int b = bh >> 4, h = bh & 15;
        const int r0 = qi*128 + wrow0 + (lane >> 2);
        #pragma unroll
        for (int nf = 0; nf < 8; ++nf) {
            const int col = h*HD + nf*8 + (lane & 3)*2;
            const size_t off0 = ((size_t)b*SS + r0)*DD + col;
            const size_t off1 = ((size_t)b*SS + r0 + 8)*DD + col;
            float x0 = o[nf][0]*inv0, y0 = o[nf][1]*inv0;
            float x1 = o[nf][2]*inv1, y1 = o[nf][3]*inv1;
            __nv_bfloat16 hx0 = __float2bfloat16(x0), hy0 = __float2bfloat16(y0);
            __nv_bfloat16 hx1 = __float2bfloat16(x1), hy1 = __float2bfloat16(y1);
            *(uint32_t*)(Chi + off0) = pack2(hx0, hy0);
            *(uint32_t*)(Chi + off1) = pack2(hx1, hy1);
            *(uint32_t*)(Clo + off0) = pack_bf16x2(x0 - __bfloat162float(hx0),
                                                   y0 - __bfloat162float(hy0));
            *(uint32_t*)(Clo + off1) = pack_bf16x2(x1 - __bfloat162float(hx1),
                                                   y1 - __bfloat162float(hy1));
        }
    }
}

// ---------------------------------------------------------------------------

extern "C" void kernel_launch(void* const* d_in, const int* in_sizes, int n_in,
                              void* d_out, int out_size)
{
    const float* x  = (const float*)d_in[0];
    const float* Wq = (const float*)d_in[1];
    const float* Wk = (const float*)d_in[2];
    const float* Wv = (const float*)d_in[3];
    const float* Wo = (const float*)d_in[4];
    const float* bo = (const float*)d_in[5];
    float* out = (float*)d_out;

    __nv_bfloat16 *ahi, *alo, *wthi, *wtlo, *qh, *ql, *kh, *kl, *vh, *vl;
    cudaGetSymbolAddress((void**)&ahi,  g_ahi);
    cudaGetSymbolAddress((void**)&alo,  g_alo);
    cudaGetSymbolAddress((void**)&wthi, g_wthi);
    cudaGetSymbolAddress((void**)&wtlo, g_wtlo);
    cudaGetSymbolAddress((void**)&qh,   g_qh);
    cudaGetSymbolAddress((void**)&ql,   g_ql);
    cudaGetSymbolAddress((void**)&kh,   g_kh);
    cudaGetSymbolAddress((void**)&kl,   g_kl);
    cudaGetSymbolAddress((void**)&vh,   g_vh);
    cudaGetSymbolAddress((void**)&vl,   g_vl);

    cudaFuncSetAttribute(attn_mma, cudaFuncAttributeMaxDynamicSharedMemorySize, ATTN_SMEM);
    cudaFuncSetAttribute(mma_gemm_qkv, cudaFuncAttributeMaxDynamicSharedMemorySize, GEMM_SMEM);
    cudaFuncSetAttribute(mma_gemm_out, cudaFuncAttributeMaxDynamicSharedMemorySize, GEMM_SMEM);

    // 1. split X into bf16 hi/lo
    split_kernel<<<1024, 256>>>((const float4*)x, ahi, alo, MM*DD/4);

    // 2. transpose+split all 4 weights (one launch)
    transpose_split_kernel<<<dim3(32,32,4), dim3(32,8)>>>(Wq, Wk, Wv, Wo, wthi, wtlo);

    // 3. fused Q/K/V projections (HMMA, load-once 3-pass, 3-stage cp.async)
    mma_gemm_qkv<<<dim3(24, 32), 256, GEMM_SMEM>>>(ahi, alo, wthi, wtlo, qh, ql, kh, kl, vh, vl);

    // 4. attention (HMMA flash, balanced pairs, 2-stage cp.async, 3-pass PV)
    attn_mma<<<dim3(8, BB*HH), 256, ATTN_SMEM>>>(qh, ql, kh, kl, vh, vl, ahi, alo);

    // 5. output projection + bias
    mma_gemm_out<<<dim3(8, 32), 256, GEMM_SMEM>>>(ahi, alo, wthi + 3*(size_t)DD*DD, wtlo + 3*(size_t)DD*DD, out, bo);
}

// round 14
// speedup vs baseline: 4.5142x; 1.1858x over previous
#include <cuda_runtime.h>
#include <cuda_fp16.h>
#include <cstdint>

#define BB 2
#define SS 2048
#define DD 1024
#define HH 16
#define HD 64
#define MM (BB*SS)     // 4096

// ---------------- device scratch (no allocation allowed) -------------------
__device__ __half g_ahi[MM*DD];
__device__ __half g_alo[MM*DD];
__device__ __half g_wthi[4][DD*DD];
__device__ __half g_wtlo[4][DD*DD];
__device__ __half g_qh[BB*HH*SS*HD];
__device__ __half g_kh[BB*HH*SS*HD];
__device__ __half g_kl[BB*HH*SS*HD];
__device__ __half g_vh[BB*HH*SS*HD];
__device__ __half g_vl[BB*HH*SS*HD];

// ---------------- prepass: fp32 -> fp16 hi/lo split -------------------------
__global__ __launch_bounds__(256)
void split_kernel(const float4* __restrict__ X, __half* __restrict__ Hi,
                  __half* __restrict__ Lo, int n4)
{
    union U { __half b[4]; uint64_t u; };
    for (int i = blockIdx.x * blockDim.x + threadIdx.x; i < n4;
         i += gridDim.x * blockDim.x) {
        float4 f = X[i];
        U h, l;
        float vf[4] = {f.x, f.y, f.z, f.w};
        #pragma unroll
        for (int j = 0; j < 4; ++j) {
            __half hb = __float2half(vf[j]);
            h.b[j] = hb;
            l.b[j] = __float2half(vf[j] - __half2float(hb));
        }
        ((uint64_t*)Hi)[i] = h.u;
        ((uint64_t*)Lo)[i] = l.u;
    }
}

// ---------------- prepass: 4x W[k][n] -> Wt[n][k] fp16 hi/lo split -----------
__global__ __launch_bounds__(256)
void transpose_split_kernel(const float* __restrict__ W0, const float* __restrict__ W1,
                            const float* __restrict__ W2, const float* __restrict__ W3,
                            __half* __restrict__ Th, __half* __restrict__ Tl)
{
    __shared__ float tile[32][33];
    const float* Ws[4] = {W0, W1, W2, W3};
    const float* W = Ws[blockIdx.z];
    __half* th = Th + (size_t)blockIdx.z * DD * DD;
    __half* tl = Tl + (size_t)blockIdx.z * DD * DD;
    int tx = threadIdx.x, ty = threadIdx.y;
    int x = blockIdx.x * 32 + tx;
    #pragma unroll
    for (int i = 0; i < 4; ++i) {
        int y = blockIdx.y * 32 + ty + i * 8;
        tile[ty + i * 8][tx] = W[(size_t)y * DD + x];
    }
    __syncthreads();
    int xo = blockIdx.y * 32 + tx;
    #pragma unroll
    for (int i = 0; i < 4; ++i) {
        int yo = blockIdx.x * 32 + ty + i * 8;
        float v = tile[tx][ty + i * 8];
        __half hb = __float2half(v);
        th[(size_t)yo * DD + xo] = hb;
        tl[(size_t)yo * DD + xo] = __float2half(v - __half2float(hb));
    }
}

// ---------------- mma.sync / cp.async helpers --------------------------------
__device__ __forceinline__ uint32_t smem_u32(const void* p) {
    uint32_t a;
    asm("{ .reg .u64 t; cvta.to.shared.u64 t, %1; cvt.u32.u64 %0, t; }"
        : "=r"(a) : "l"(p));
    return a;
}
__device__ __forceinline__ void ldmx4(uint32_t* r, uint32_t addr) {
    asm volatile("ldmatrix.sync.aligned.m8n8.x4.shared.b16 {%0,%1,%2,%3}, [%4];"
                 : "=r"(r[0]), "=r"(r[1]), "=r"(r[2]), "=r"(r[3]) : "r"(addr));
}
__device__ __forceinline__ void ldmx4t(uint32_t* r, uint32_t addr) {
    asm volatile("ldmatrix.sync.aligned.m8n8.x4.trans.shared.b16 {%0,%1,%2,%3}, [%4];"
                 : "=r"(r[0]), "=r"(r[1]), "=r"(r[2]), "=r"(r[3]) : "r"(addr));
}
__device__ __forceinline__ void mma_f16(float* c, const uint32_t* a,
                                        uint32_t b0, uint32_t b1) {
    asm volatile(
        "mma.sync.aligned.m16n8k16.row.col.f32.f16.f16.f32 "
        "{%0,%1,%2,%3}, {%4,%5,%6,%7}, {%8,%9}, {%0,%1,%2,%3};"
        : "+f"(c[0]), "+f"(c[1]), "+f"(c[2]), "+f"(c[3])
        : "r"(a[0]), "r"(a[1]), "r"(a[2]), "r"(a[3]), "r"(b0), "r"(b1));
}
__device__ __forceinline__ float ex2f(float x) {
    float y; asm("ex2.approx.f32 %0, %1;" : "=f"(y) : "f"(x)); return y;
}
__device__ __forceinline__ uint32_t pack2(__half a, __half b) {
    __half2 t = __halves2half2(a, b);
    return *(uint32_t*)&t;
}
__device__ __forceinline__ uint32_t pack_f16x2(float a, float b) {
    __half2 t = __floats2half2_rn(a, b);
    return *(uint32_t*)&t;
}
__device__ __forceinline__ void cpa16(uint32_t dst, const void* src) {
    asm volatile("cp.async.cg.shared.global [%0], [%1], 16;" :: "r"(dst), "l"(src));
}
__device__ __forceinline__ void cpa_commit() {
    asm volatile("cp.async.commit_group;" ::: "memory");
}
template<int N> __device__ __forceinline__ void cpa_wait() {
    asm volatile("cp.async.wait_group %0;" :: "n"(N) : "memory");
}

// ---------------- HMMA GEMM core (swizzled 64B rows, 3-stage) ----------------
// ALO=true : 3 passes (Ahi*Bhi + Ahi*Blo + Alo*Bhi)
// ALO=false: 2 passes (Ahi*Bhi + Ahi*Blo)
#define GCH 32
#define GOP 8192                     // 128 rows * 64 B
#define GSTG (4*GOP)                 // 32768 B per stage
#define GEMM_SMEM (3*GSTG)           // 98304 B

__device__ __forceinline__ uint32_t sw64(uint32_t off) {
    return off ^ (((off >> 7) & 3u) << 4);
}

template<bool ALO, typename EPI>
__device__ __forceinline__ void gemm_core(
    const __half* Ahi, const __half* Alo,
    const __half* Bhi, const __half* Blo,
    int m0, int n0, EPI epi)
{
    extern __shared__ __align__(16) char gsm[];
    const uint32_t base = smem_u32(gsm);

    const int tid  = threadIdx.x;
    const int wid  = tid >> 5;
    const int lane = tid & 31;
    const int wm0 = (wid & 3) * 32;
    const int wn0 = (wid >> 2) * 64;

    const uint4* srcs[4] = {(const uint4*)Ahi, (const uint4*)Alo,
                            (const uint4*)Bhi, (const uint4*)Blo};

    int cmat[8], crow[8], cc4[8];
    uint32_t cdst[8];
    #pragma unroll
    for (int i = 0; i < 8; ++i) {
        int idx = tid + i * 256;
        cmat[i] = idx >> 9;
        int w = idx & 511;
        crow[i] = w >> 2;
        cc4[i]  = w & 3;
        cdst[i] = base + cmat[i]*GOP + sw64(crow[i]*64 + cc4[i]*16);
    }

    auto issue = [&](int t) {
        const uint32_t so = (t % 3) * GSTG;
        #pragma unroll
        for (int i = 0; i < 8; ++i) {
            if (!ALO && cmat[i] == 1) continue;
            const int r0 = (cmat[i] < 2) ? m0 : n0;
            cpa16(cdst[i] + so, srcs[cmat[i]] + (size_t)(r0 + crow[i])*128 + t*4 + cc4[i]);
        }
        cpa_commit();
    };

    uint32_t aoffb[2], axor[2], boffb[4], bxor[4];
    #pragma unroll
    for (int mf = 0; mf < 2; ++mf) {
        int row = wm0 + mf*16 + (lane & 15);
        aoffb[mf] = row*64 + (lane >> 4)*16;
        axor[mf]  = ((row >> 1) & 3u) << 4;
    }
    #pragma unroll
    for (int np = 0; np < 4; ++np) {
        int row = wn0 + np*16 + ((lane >> 4) & 1)*8 + (lane & 7);
        boffb[np] = row*64 + ((lane >> 3) & 1)*16;
        bxor[np]  = ((row >> 1) & 3u) << 4;
    }

    float acc[2][8][4] = {};

    auto compute = [&](int stg) {
        const uint32_t sb = base + stg * GSTG;
        #pragma unroll
        for (int ks2 = 0; ks2 < 64; ks2 += 32) {
            uint32_t afh[2][4], afl[2][4], bfh[4][4], bfl[4][4];
            #pragma unroll
            for (int mf = 0; mf < 2; ++mf) {
                uint32_t o = (aoffb[mf] + ks2) ^ axor[mf];
                ldmx4(afh[mf], sb + o);
                if (ALO) ldmx4(afl[mf], sb + GOP + o);
            }
            #pragma unroll
            for (int np = 0; np < 4; ++np) {
                uint32_t o = (boffb[np] + ks2) ^ bxor[np];
                ldmx4(bfh[np], sb + 2*GOP + o);
                ldmx4(bfl[np], sb + 3*GOP + o);
            }
            #pragma unroll
            for (int mf = 0; mf < 2; ++mf)
                #pragma unroll
                for (int np = 0; np < 4; ++np) {
                    mma_f16(acc[mf][np*2+0], afh[mf], bfh[np][0], bfh[np][1]);
                    mma_f16(acc[mf][np*2+1], afh[mf], bfh[np][2], bfh[np][3]);
                    mma_f16(acc[mf][np*2+0], afh[mf], bfl[np][0], bfl[np][1]);
                    mma_f16(acc[mf][np*2+1], afh[mf], bfl[np][2], bfl[np][3]);
                    if (ALO) {
                        mma_f16(acc[mf][np*2+0], afl[mf], bfh[np][0], bfh[np][1]);
                        mma_f16(acc[mf][np*2+1], afl[mf], bfh[np][2], bfh[np][3]);
                    }
                }
        }
    };

    issue(0); issue(1);
    for (int t = 0; t < GCH; ++t) {
        if (t + 1 < GCH) cpa_wait<1>(); else cpa_wait<0>();
        __syncthreads();
        if (t + 2 < GCH) issue(t + 2);
        compute(t % 3);
    }

    const int qrow = lane >> 2;
    const int qcol = (lane & 3) * 2;
    #pragma unroll
    for (int mf = 0; mf < 2; ++mf)
        #pragma unroll
        for (int nf = 0; nf < 8; ++nf)
            #pragma unroll
            for (int half = 0; half < 2; ++half) {
                const int m = m0 + wm0 + mf*16 + qrow + half*8;
                const int n = n0 + wn0 + nf*8 + qcol;
                epi(m, n, acc[mf][nf][half*2 + 0], acc[mf][nf][half*2 + 1]);
            }
}

// fused QKV projection: Q writes hi only; K,V write hi+lo.
__global__ __launch_bounds__(256, 2)
void mma_gemm_qkv(const __half* __restrict__ Ahi, const __half* __restrict__ Alo,
                  const __half* __restrict__ Whi, const __half* __restrict__ Wlo,
                  __half* __restrict__ qh,
                  __half* __restrict__ kh, __half* __restrict__ kl,
                  __half* __restrict__ vh, __half* __restrict__ vl)
{
    const int g  = blockIdx.x >> 3;
    const int n0 = (blockIdx.x & 7) * 128;
    const int m0 = blockIdx.y * 128;
    const __half* Bhi = Whi + (size_t)g * DD * DD;
    const __half* Blo = Wlo + (size_t)g * DD * DD;
    __half* Yh = (g == 0) ? qh : (g == 1) ? kh : vh;
    __half* Yl = (g == 1) ? kl : vl;
    const bool wantlo = (g != 0);

    gemm_core<true>(Ahi, Alo, Bhi, Blo, m0, n0,
        [&](int m, int n, float cx, float cy) {
            const int b = m >> 11, s = m & (SS - 1);
            const int h = n >> 6, hd = n & 63;
            const size_t off = (((size_t)b*HH + h)*SS + s)*HD + hd;
            __half hx = __float2half(cx);
            __half hy = __float2half(cy);
            *(uint32_t*)(Yh + off) = pack2(hx, hy);
            if (wantlo)
                *(uint32_t*)(Yl + off) = pack_f16x2(
                    cx - __half2float(hx), cy - __half2float(hy));
        });
}

// output projection + bias (2-pass: ctx is hi-only)
__global__ __launch_bounds__(256, 2)
void mma_gemm_out(const __half* __restrict__ Ahi,
                  const __half* __restrict__ Bhi, const __half* __restrict__ Blo,
                  float* __restrict__ Yf, const float* __restrict__ bias)
{
    const int n0 = blockIdx.x * 128;
    const int m0 = blockIdx.y * 128;
    gemm_core<false>(Ahi, Ahi, Bhi, Blo, m0, n0,
        [&](int m, int n, float cx, float cy) {
            float2* dst = (float2*)(Yf + (size_t)m * DD + n);
            *dst = make_float2(cx + bias[n], cy + bias[n + 1]);
        });
}

// ---------------- HMMA flash attention (fp16, online softmax) ----------------
#define KST 72
#define STAGE (4*64*KST*2)           // 36864 B
#define ATTN_SMEM (2*STAGE)          // 73728 B
#define LOG2E 1.4426950408889634f

__global__ __launch_bounds__(256, 2)
void attn_mma(const __half* __restrict__ Qh,
              const __half* __restrict__ Kh, const __half* __restrict__ Kl,
              const __half* __restrict__ Vh, const __half* __restrict__ Vl,
              __half* __restrict__ Chi)
{
    extern __shared__ __align__(16) char dynsm[];
    __half* sm = (__half*)dynsm;

    const int bh  = blockIdx.y;
    const int tid = threadIdx.x;
    const int wid = tid >> 5;
    const int lane = tid & 31;
    const int wrow0 = wid * 16;

    const size_t hbase = (size_t)bh * SS * HD;
    const uint4* Kh4 = (const uint4*)(Kh + hbase);
    const uint4* Kl4 = (const uint4*)(Kl + hbase);
    const uint4* Vh4 = (const uint4*)(Vh + hbase);
    const uint4* Vl4 = (const uint4*)(Vl + hbase);

    const uint32_t sbase = smem_u32(sm);

    uint32_t kbase[4];
    #pragma unroll
    for (int ng = 0; ng < 4; ++ng) {
        int krow = ng*16 + ((lane >> 4) & 1)*8 + (lane & 7);
        kbase[ng] = (krow * KST + ((lane >> 3) & 1) * 8) * 2;
    }
    const uint32_t vrowoff = ((((lane >> 3) & 1)*8 + (lane & 7)) * KST) * 2;
    uint32_t vcol[4];
    #pragma unroll
    for (int ng = 0; ng < 4; ++ng)
        vcol[ng] = (ng*16 + (lane >> 4) * 8) * 2;

    uint32_t cpa_dst[8];
    int cpa_src[8];
    #pragma unroll
    for (int i = 0; i < 8; ++i) {
        int idx = tid + i * 256;
        int tile = idx >> 9;
        int within = idx & 511;
        int row = within >> 3, c = within & 7;
        cpa_dst[i] = sbase + ((tile*64 + row)*KST + c*8) * 2;
        cpa_src[i] = within;
    }

    auto issue = [&](int kt) {
        const uint4* srcs[4] = {Kh4 + kt*512, Kl4 + kt*512, Vh4 + kt*512, Vl4 + kt*512};
        const uint32_t soff = (kt & 1) * STAGE;
        #pragma unroll
        for (int i = 0; i < 8; ++i) {
            int tile = (tid + i*256) >> 9;
            cpa16(cpa_dst[i] + soff, srcs[tile] + cpa_src[i]);
        }
        cpa_commit();
    };

    #pragma unroll 1
    for (int half = 0; half < 2; ++half) {
        const int qi = half ? (15 - blockIdx.x) : blockIdx.x;

        __syncthreads();
        // ---- stage Qh (128x64 fp16) into stage-0 smem ----
        {
            const uint4* Qh4 = (const uint4*)(Qh + hbase + (size_t)qi*128*HD);
            #pragma unroll
            for (int i = 0; i < 4; ++i) {
                int idx = tid + i * 256;
                int row = idx >> 3, c = idx & 7;
                uint4 v = Qh4[idx];
                *(uint4*)&sm[row*KST + c*8] = v;
            }
        }
        __syncthreads();

        uint32_t qhf[4][4];
        {
            const uint32_t roff = ((wrow0 + (lane & 15)) * KST + (lane >> 4) * 8) * 2;
            #pragma unroll
            for (int ks = 0; ks < 4; ++ks)
                ldmx4(qhf[ks], sbase + roff + ks * 32);
        }
        __syncthreads();

        float mrow[2] = {-1e30f, -1e30f};
        float lrow[2] = {0.0f, 0.0f};
        float o[8][4] = {};

        const int wmax = qi*128 + wrow0 + 15;
        const int nsteps = 2*qi + 2;

        issue(0);
        for (int kt = 0; kt < nsteps; ++kt) {
            if (kt + 1 < nsteps) { issue(kt + 1); cpa_wait<1>(); }
            else                 { cpa_wait<0>(); }
            __syncthreads();

            const uint32_t st = sbase + (kt & 1) * STAGE;
            const uint32_t sKh = st;
            const uint32_t sKl = st + 64*KST*2;
            const uint32_t sVh = st + 128*KST*2;
            const uint32_t sVl = st + 192*KST*2;

            if (kt*64 <= wmax) {
                // ---- scores: Qh*Kh + Qh*Kl (2 passes) ----
                float s[8][4] = {};
                #pragma unroll
                for (int ks = 0; ks < 4; ++ks) {
                    #pragma unroll
                    for (int ng = 0; ng < 4; ++ng) {
                        uint32_t khb[4], klb[4];
                        ldmx4(khb, sKh + kbase[ng] + ks*32);
                        ldmx4(klb, sKl + kbase[ng] + ks*32);
                        mma_f16(s[2*ng+0], qhf[ks], khb[0], khb[1]);
                        mma_f16(s[2*ng+1], qhf[ks], khb[2], khb[3]);
                        mma_f16(s[2*ng+0], qhf[ks], klb[0], klb[1]);
                        mma_f16(s[2*ng+1], qhf[ks], klb[2], klb[3]);
                    }
                }

                // ---- scale + causal mask (log2 units) ----
                const float SC = 0.125f * LOG2E;
                const int r0g = qi*128 + wrow0 + (lane >> 2);
                const bool needmask = (kt*64 + 63 > qi*128 + wrow0);
                #pragma unroll
                for (int nf = 0; nf < 8; ++nf)
                    #pragma unroll
                    for (int ri = 0; ri < 4; ++ri) {
                        float v = s[nf][ri] * SC;
                        if (needmask) {
                            int col = kt*64 + nf*8 + (lane & 3)*2 + (ri & 1);
                            int rg  = r0g + ((ri >> 1) ? 8 : 0);
                            if (col > rg) v = -1e30f;
                        }
                        s[nf][ri] = v;
                    }

                // ---- online softmax (p in (0,1], fp16-safe) ----
                float alpha[2];
                #pragma unroll
                for (int h = 0; h < 2; ++h) {
                    float t = -1e30f;
                    #pragma unroll
                    for (int nf = 0; nf < 8; ++nf)
                        t = fmaxf(t, fmaxf(s[nf][h*2], s[nf][h*2+1]));
                    t = fmaxf(t, __shfl_xor_sync(0xffffffffu, t, 1));
                    t = fmaxf(t, __shfl_xor_sync(0xffffffffu, t, 2));
                    float nm = fmaxf(mrow[h], t);
                    alpha[h] = ex2f(mrow[h] - nm);
                    mrow[h] = nm;
                }
                float rs[2] = {0.0f, 0.0f};
                #pragma unroll
                for (int nf = 0; nf < 8; ++nf)
                    #pragma unroll
                    for (int ri = 0; ri < 4; ++ri) {
                        int h = ri >> 1;
                        float p = ex2f(s[nf][ri] - mrow[h]);
                        s[nf][ri] = p;
                        rs[h] += p;
                    }
                #pragma unroll
                for (int h = 0; h < 2; ++h) {
                    rs[h] += __shfl_xor_sync(0xffffffffu, rs[h], 1);
                    rs[h] += __shfl_xor_sync(0xffffffffu, rs[h], 2);
                    lrow[h] = lrow[h] * alpha[h] + rs[h];
                }
                #pragma unroll
                for (int nf = 0; nf < 8; ++nf) {
                    o[nf][0] *= alpha[0]; o[nf][1] *= alpha[0];
                    o[nf][2] *= alpha[1]; o[nf][3] *= alpha[1];
                }

                // ---- P frags (fp16 hi) ----
                uint32_t pah[4][4];
                #pragma unroll
                for (int ks = 0; ks < 4; ++ks) {
                    pah[ks][0] = pack_f16x2(s[2*ks][0],   s[2*ks][1]);
                    pah[ks][1] = pack_f16x2(s[2*ks][2],   s[2*ks][3]);
                    pah[ks][2] = pack_f16x2(s[2*ks+1][0], s[2*ks+1][1]);
                    pah[ks][3] = pack_f16x2(s[2*ks+1][2], s[2*ks+1][3]);
                }

                // ---- P@V: Ph*Vh + Ph*Vl (2 passes) ----
                #pragma unroll
                for (int ks = 0; ks < 4; ++ks) {
                    const uint32_t vrb = vrowoff + ks*16*KST*2;
                    #pragma unroll
                    for (int ng = 0; ng < 4; ++ng) {
                        uint32_t vhb[4], vlb[4];
                        ldmx4t(vhb, sVh + vrb + vcol[ng]);
                        ldmx4t(vlb, sVl + vrb + vcol[ng]);
                        mma_f16(o[2*ng+0], pah[ks], vhb[0], vhb[1]);
                        mma_f16(o[2*ng+1], pah[ks], vhb[2], vhb[3]);
                        mma_f16(o[2*ng+0], pah[ks], vlb[0], vlb[1]);
                        mma_f16(o[2*ng+1], pah[ks], vlb[2], vlb[3]);
                    }
                }
            }
            __syncthreads();
        }

        // ---- epilogue: write ctx hi (fp16, row-major [M][D]) ----
        const float inv0 = 1.0f / lrow[0];
        const float inv1 = 1.0f / lrow[1];
        const int b = bh >> 4, h = bh & 15;
        const int r0 = qi*128 + wrow0 + (lane >> 2);
        #pragma unroll
        for (int nf = 0; nf < 8; ++nf) {
            const int col = h*HD + nf*8 + (lane & 3)*2;
            const size_t off0 = ((size_t)b*SS + r0)*DD + col;
            const size_t off1 = ((size_t)b*SS + r0 + 8)*DD + col;
            *(uint32_t*)(Chi + off0) = pack_f16x2(o[nf][0]*inv0, o[nf][1]*inv0);
            *(uint32_t*)(Chi + off1) = pack_f16x2(o[nf][2]*inv1, o[nf][3]*inv1);
        }
    }
}

// ---------------------------------------------------------------------------

extern "C" void kernel_launch(void* const* d_in, const int* in_sizes, int n_in,
                              void* d_out, int out_size)
{
    const float* x  = (const float*)d_in[0];
    const float* Wq = (const float*)d_in[1];
    const float* Wk = (const float*)d_in[2];
    const float* Wv = (const float*)d_in[3];
    const float* Wo = (const float*)d_in[4];
    const float* bo = (const float*)d_in[5];
    float* out = (float*)d_out;

    __half *ahi, *alo, *wthi, *wtlo, *qh, *kh, *kl, *vh, *vl;
    cudaGetSymbolAddress((void**)&ahi,  g_ahi);
    cudaGetSymbolAddress((void**)&alo,  g_alo);
    cudaGetSymbolAddress((void**)&wthi, g_wthi);
    cudaGetSymbolAddress((void**)&wtlo, g_wtlo);
    cudaGetSymbolAddress((void**)&qh,   g_qh);
    cudaGetSymbolAddress((void**)&kh,   g_kh);
    cudaGetSymbolAddress((void**)&kl,   g_kl);
    cudaGetSymbolAddress((void**)&vh,   g_vh);
    cudaGetSymbolAddress((void**)&vl,   g_vl);

    cudaFuncSetAttribute(attn_mma, cudaFuncAttributeMaxDynamicSharedMemorySize, ATTN_SMEM);
    cudaFuncSetAttribute(mma_gemm_qkv, cudaFuncAttributeMaxDynamicSharedMemorySize, GEMM_SMEM);
    cudaFuncSetAttribute(mma_gemm_out, cudaFuncAttributeMaxDynamicSharedMemorySize, GEMM_SMEM);

    // 1. split X into fp16 hi/lo
    split_kernel<<<1024, 256>>>((const float4*)x, ahi, alo, MM*DD/4);

    // 2. transpose+split all 4 weights (one launch)
    transpose_split_kernel<<<dim3(32,32,4), dim3(32,8)>>>(Wq, Wk, Wv, Wo, wthi, wtlo);

    // 3. fused Q/K/V projections (fp16 3-pass; Q hi-only output)
    mma_gemm_qkv<<<dim3(24, 32), 256, GEMM_SMEM>>>(ahi, alo, wthi, wtlo, qh, kh, kl, vh, vl);

    // 4. attention (fp16 2-pass QK and PV, ONLINE softmax, balanced pairs)
    attn_mma<<<dim3(8, BB*HH), 256, ATTN_SMEM>>>(qh, kh, kl, vh, vl, ahi);

    // 5. output projection + bias (2-pass, ctx hi-only)
    mma_gemm_out<<<dim3(8, 32), 256, GEMM_SMEM>>>(ahi, wthi + 3*(size_t)DD*DD, wtlo + 3*(size_t)DD*DD, out, bo);
}

// round 15
// speedup vs baseline: 5.5053x; 1.2196x over previous
#include <cuda_runtime.h>
#include <cuda_fp16.h>
#include <cstdint>

#define BB 2
#define SS 2048
#define DD 1024
#define HH 16
#define HD 64
#define MM (BB*SS)     // 4096

// ---------------- device scratch (no allocation allowed) -------------------
__device__ __half g_ahi[MM*DD];
__device__ __half g_wthi[4][DD*DD];
__device__ __half g_wtlo[4][DD*DD];
__device__ __half g_qh[BB*HH*SS*HD];
__device__ __half g_kh[BB*HH*SS*HD];
__device__ __half g_kl[BB*HH*SS*HD];
__device__ __half g_vh[BB*HH*SS*HD];
__device__ __half g_vl[BB*HH*SS*HD];

// ---------------- prepass: fp32 -> fp16 convert (hi only) -------------------
__global__ __launch_bounds__(256)
void split_kernel(const float4* __restrict__ X, __half* __restrict__ Hi, int n4)
{
    union U { __half b[4]; uint64_t u; };
    for (int i = blockIdx.x * blockDim.x + threadIdx.x; i < n4;
         i += gridDim.x * blockDim.x) {
        float4 f = X[i];
        U h;
        h.b[0] = __float2half(f.x);
        h.b[1] = __float2half(f.y);
        h.b[2] = __float2half(f.z);
        h.b[3] = __float2half(f.w);
        ((uint64_t*)Hi)[i] = h.u;
    }
}

// ---------------- prepass: 4x W[k][n] -> Wt[n][k] fp16 hi/lo split -----------
__global__ __launch_bounds__(256)
void transpose_split_kernel(const float* __restrict__ W0, const float* __restrict__ W1,
                            const float* __restrict__ W2, const float* __restrict__ W3,
                            __half* __restrict__ Th, __half* __restrict__ Tl)
{
    __shared__ float tile[32][33];
    const float* Ws[4] = {W0, W1, W2, W3};
    const float* W = Ws[blockIdx.z];
    __half* th = Th + (size_t)blockIdx.z * DD * DD;
    __half* tl = Tl + (size_t)blockIdx.z * DD * DD;
    int tx = threadIdx.x, ty = threadIdx.y;
    int x = blockIdx.x * 32 + tx;
    #pragma unroll
    for (int i = 0; i < 4; ++i) {
        int y = blockIdx.y * 32 + ty + i * 8;
        tile[ty + i * 8][tx] = W[(size_t)y * DD + x];
    }
    __syncthreads();
    int xo = blockIdx.y * 32 + tx;
    #pragma unroll
    for (int i = 0; i < 4; ++i) {
        int yo = blockIdx.x * 32 + ty + i * 8;
        float v = tile[tx][ty + i * 8];
        __half hb = __float2half(v);
        th[(size_t)yo * DD + xo] = hb;
        tl[(size_t)yo * DD + xo] = __float2half(v - __half2float(hb));
    }
}

// ---------------- mma.sync / cp.async helpers --------------------------------
__device__ __forceinline__ uint32_t smem_u32(const void* p) {
    uint32_t a;
    asm("{ .reg .u64 t; cvta.to.shared.u64 t, %1; cvt.u32.u64 %0, t; }"
        : "=r"(a) : "l"(p));
    return a;
}
__device__ __forceinline__ void ldmx4(uint32_t* r, uint32_t addr) {
    asm volatile("ldmatrix.sync.aligned.m8n8.x4.shared.b16 {%0,%1,%2,%3}, [%4];"
                 : "=r"(r[0]), "=r"(r[1]), "=r"(r[2]), "=r"(r[3]) : "r"(addr));
}
__device__ __forceinline__ void ldmx4t(uint32_t* r, uint32_t addr) {
    asm volatile("ldmatrix.sync.aligned.m8n8.x4.trans.shared.b16 {%0,%1,%2,%3}, [%4];"
                 : "=r"(r[0]), "=r"(r[1]), "=r"(r[2]), "=r"(r[3]) : "r"(addr));
}
__device__ __forceinline__ void mma_f16(float* c, const uint32_t* a,
                                        uint32_t b0, uint32_t b1) {
    asm volatile(
        "mma.sync.aligned.m16n8k16.row.col.f32.f16.f16.f32 "
        "{%0,%1,%2,%3}, {%4,%5,%6,%7}, {%8,%9}, {%0,%1,%2,%3};"
        : "+f"(c[0]), "+f"(c[1]), "+f"(c[2]), "+f"(c[3])
        : "r"(a[0]), "r"(a[1]), "r"(a[2]), "r"(a[3]), "r"(b0), "r"(b1));
}
__device__ __forceinline__ float ex2f(float x) {
    float y; asm("ex2.approx.f32 %0, %1;" : "=f"(y) : "f"(x)); return y;
}
__device__ __forceinline__ uint32_t pack2(__half a, __half b) {
    __half2 t = __halves2half2(a, b);
    return *(uint32_t*)&t;
}
__device__ __forceinline__ uint32_t pack_f16x2(float a, float b) {
    __half2 t = __floats2half2_rn(a, b);
    return *(uint32_t*)&t;
}
__device__ __forceinline__ void cpa16(uint32_t dst, const void* src) {
    asm volatile("cp.async.cg.shared.global [%0], [%1], 16;" :: "r"(dst), "l"(src));
}
__device__ __forceinline__ void cpa_commit() {
    asm volatile("cp.async.commit_group;" ::: "memory");
}
template<int N> __device__ __forceinline__ void cpa_wait() {
    asm volatile("cp.async.wait_group %0;" :: "n"(N) : "memory");
}

// ---------------- HMMA GEMM core (swizzled 64B rows, 3-stage, 2-pass) --------
// 2 passes: Ahi*Bhi + Ahi*Blo. Operands staged: Ahi | Bhi | Blo.
#define GCH 32
#define GOP 8192                     // 128 rows * 64 B
#define GSTG (3*GOP)                 // 24576 B per stage
#define GEMM_SMEM (3*GSTG)           // 73728 B

__device__ __forceinline__ uint32_t sw64(uint32_t off) {
    return off ^ (((off >> 7) & 3u) << 4);
}

template<typename EPI>
__device__ __forceinline__ void gemm_core(
    const __half* Ahi, const __half* Bhi, const __half* Blo,
    int m0, int n0, EPI epi)
{
    extern __shared__ __align__(16) char gsm[];
    const uint32_t base = smem_u32(gsm);

    const int tid  = threadIdx.x;
    const int wid  = tid >> 5;
    const int lane = tid & 31;
    const int wm0 = (wid & 3) * 32;
    const int wn0 = (wid >> 2) * 64;

    const uint4* srcs[3] = {(const uint4*)Ahi, (const uint4*)Bhi, (const uint4*)Blo};

    // copy mapping: 1536 uint4 per chunk, 6 per thread
    int cmat[6], crow[6], cc4[6];
    uint32_t cdst[6];
    #pragma unroll
    for (int i = 0; i < 6; ++i) {
        int idx = tid + i * 256;
        cmat[i] = idx >> 9;
        int w = idx & 511;
        crow[i] = w >> 2;
        cc4[i]  = w & 3;
        cdst[i] = base + cmat[i]*GOP + sw64(crow[i]*64 + cc4[i]*16);
    }

    auto issue = [&](int t) {
        const uint32_t so = (t % 3) * GSTG;
        #pragma unroll
        for (int i = 0; i < 6; ++i) {
            const int r0 = (cmat[i] == 0) ? m0 : n0;
            cpa16(cdst[i] + so, srcs[cmat[i]] + (size_t)(r0 + crow[i])*128 + t*4 + cc4[i]);
        }
        cpa_commit();
    };

    uint32_t aoffb[2], axor[2], boffb[4], bxor[4];
    #pragma unroll
    for (int mf = 0; mf < 2; ++mf) {
        int row = wm0 + mf*16 + (lane & 15);
        aoffb[mf] = row*64 + (lane >> 4)*16;
        axor[mf]  = ((row >> 1) & 3u) << 4;
    }
    #pragma unroll
    for (int np = 0; np < 4; ++np) {
        int row = wn0 + np*16 + ((lane >> 4) & 1)*8 + (lane & 7);
        boffb[np] = row*64 + ((lane >> 3) & 1)*16;
        bxor[np]  = ((row >> 1) & 3u) << 4;
    }

    float acc[2][8][4] = {};

    auto compute = [&](int stg) {
        const uint32_t sb = base + stg * GSTG;
        #pragma unroll
        for (int ks2 = 0; ks2 < 64; ks2 += 32) {
            uint32_t afh[2][4], bfh[4][4], bfl[4][4];
            #pragma unroll
            for (int mf = 0; mf < 2; ++mf) {
                uint32_t o = (aoffb[mf] + ks2) ^ axor[mf];
                ldmx4(afh[mf], sb + o);
            }
            #pragma unroll
            for (int np = 0; np < 4; ++np) {
                uint32_t o = (boffb[np] + ks2) ^ bxor[np];
                ldmx4(bfh[np], sb + 1*GOP + o);
                ldmx4(bfl[np], sb + 2*GOP + o);
            }
            #pragma unroll
            for (int mf = 0; mf < 2; ++mf)
                #pragma unroll
                for (int np = 0; np < 4; ++np) {
                    mma_f16(acc[mf][np*2+0], afh[mf], bfh[np][0], bfh[np][1]);
                    mma_f16(acc[mf][np*2+1], afh[mf], bfh[np][2], bfh[np][3]);
                    mma_f16(acc[mf][np*2+0], afh[mf], bfl[np][0], bfl[np][1]);
                    mma_f16(acc[mf][np*2+1], afh[mf], bfl[np][2], bfl[np][3]);
                }
        }
    };

    issue(0); issue(1);
    for (int t = 0; t < GCH; ++t) {
        if (t + 1 < GCH) cpa_wait<1>(); else cpa_wait<0>();
        __syncthreads();
        if (t + 2 < GCH) issue(t + 2);
        compute(t % 3);
    }

    const int qrow = lane >> 2;
    const int qcol = (lane & 3) * 2;
    #pragma unroll
    for (int mf = 0; mf < 2; ++mf)
        #pragma unroll
        for (int nf = 0; nf < 8; ++nf)
            #pragma unroll
            for (int half = 0; half < 2; ++half) {
                const int m = m0 + wm0 + mf*16 + qrow + half*8;
                const int n = n0 + wn0 + nf*8 + qcol;
                epi(m, n, acc[mf][nf][half*2 + 0], acc[mf][nf][half*2 + 1]);
            }
}

// fused QKV projection (2-pass): Q writes hi only; K,V write hi+lo.
__global__ __launch_bounds__(256, 2)
void mma_gemm_qkv(const __half* __restrict__ Ahi,
                  const __half* __restrict__ Whi, const __half* __restrict__ Wlo,
                  __half* __restrict__ qh,
                  __half* __restrict__ kh, __half* __restrict__ kl,
                  __half* __restrict__ vh, __half* __restrict__ vl)
{
    const int g  = blockIdx.x >> 3;
    const int n0 = (blockIdx.x & 7) * 128;
    const int m0 = blockIdx.y * 128;
    const __half* Bhi = Whi + (size_t)g * DD * DD;
    const __half* Blo = Wlo + (size_t)g * DD * DD;
    __half* Yh = (g == 0) ? qh : (g == 1) ? kh : vh;
    __half* Yl = (g == 1) ? kl : vl;
    const bool wantlo = (g != 0);

    gemm_core(Ahi, Bhi, Blo, m0, n0,
        [&](int m, int n, float cx, float cy) {
            const int b = m >> 11, s = m & (SS - 1);
            const int h = n >> 6, hd = n & 63;
            const size_t off = (((size_t)b*HH + h)*SS + s)*HD + hd;
            __half hx = __float2half(cx);
            __half hy = __float2half(cy);
            *(uint32_t*)(Yh + off) = pack2(hx, hy);
            if (wantlo)
                *(uint32_t*)(Yl + off) = pack_f16x2(
                    cx - __half2float(hx), cy - __half2float(hy));
        });
}

// output projection + bias (2-pass: ctx is hi-only)
__global__ __launch_bounds__(256, 2)
void mma_gemm_out(const __half* __restrict__ Ahi,
                  const __half* __restrict__ Bhi, const __half* __restrict__ Blo,
                  float* __restrict__ Yf, const float* __restrict__ bias)
{
    const int n0 = blockIdx.x * 128;
    const int m0 = blockIdx.y * 128;
    gemm_core(Ahi, Bhi, Blo, m0, n0,
        [&](int m, int n, float cx, float cy) {
            float2* dst = (float2*)(Yf + (size_t)m * DD + n);
            *dst = make_float2(cx + bias[n], cy + bias[n + 1]);
        });
}

// ---------------- HMMA flash attention (fp16, online softmax) ----------------
#define KST 72
#define STAGE (4*64*KST*2)           // 36864 B
#define ATTN_SMEM (2*STAGE)          // 73728 B
#define LOG2E 1.4426950408889634f

__global__ __launch_bounds__(256, 2)
void attn_mma(const __half* __restrict__ Qh,
              const __half* __restrict__ Kh, const __half* __restrict__ Kl,
              const __half* __restrict__ Vh, const __half* __restrict__ Vl,
              __half* __restrict__ Chi)
{
    extern __shared__ __align__(16) char dynsm[];
    __half* sm = (__half*)dynsm;

    const int bh  = blockIdx.y;
    const int tid = threadIdx.x;
    const int wid = tid >> 5;
    const int lane = tid & 31;
    const int wrow0 = wid * 16;

    const size_t hbase = (size_t)bh * SS * HD;
    const uint4* Kh4 = (const uint4*)(Kh + hbase);
    const uint4* Kl4 = (const uint4*)(Kl + hbase);
    const uint4* Vh4 = (const uint4*)(Vh + hbase);
    const uint4* Vl4 = (const uint4*)(Vl + hbase);

    const uint32_t sbase = smem_u32(sm);

    uint32_t kbase[4];
    #pragma unroll
    for (int ng = 0; ng < 4; ++ng) {
        int krow = ng*16 + ((lane >> 4) & 1)*8 + (lane & 7);
        kbase[ng] = (krow * KST + ((lane >> 3) & 1) * 8) * 2;
    }
    const uint32_t vrowoff = ((((lane >> 3) & 1)*8 + (lane & 7)) * KST) * 2;
    uint32_t vcol[4];
    #pragma unroll
    for (int ng = 0; ng < 4; ++ng)
        vcol[ng] = (ng*16 + (lane >> 4) * 8) * 2;

    uint32_t cpa_dst[8];
    int cpa_src[8];
    #pragma unroll
    for (int i = 0; i < 8; ++i) {
        int idx = tid + i * 256;
        int tile = idx >> 9;
        int within = idx & 511;
        int row = within >> 3, c = within & 7;
        cpa_dst[i] = sbase + ((tile*64 + row)*KST + c*8) * 2;
        cpa_src[i] = within;
    }

    auto issue = [&](int kt) {
        const uint4* srcs[4] = {Kh4 + kt*512, Kl4 + kt*512, Vh4 + kt*512, Vl4 + kt*512};
        const uint32_t soff = (kt & 1) * STAGE;
        #pragma unroll
        for (int i = 0; i < 8; ++i) {
            int tile = (tid + i*256) >> 9;
            cpa16(cpa_dst[i] + soff, srcs[tile] + cpa_src[i]);
        }
        cpa_commit();
    };

    #pragma unroll 1
    for (int half = 0; half < 2; ++half) {
        const int qi = half ? (15 - blockIdx.x) : blockIdx.x;

        __syncthreads();
        // ---- stage Qh (128x64 fp16) into stage-0 smem ----
        {
            const uint4* Qh4 = (const uint4*)(Qh + hbase + (size_t)qi*128*HD);
            #pragma unroll
            for (int i = 0; i < 4; ++i) {
                int idx = tid + i * 256;
                int row = idx >> 3, c = idx & 7;
                uint4 v = Qh4[idx];
                *(uint4*)&sm[row*KST + c*8] = v;
            }
        }
        __syncthreads();

        uint32_t qhf[4][4];
        {
            const uint32_t roff = ((wrow0 + (lane & 15)) * KST + (lane >> 4) * 8) * 2;
            #pragma unroll
            for (int ks = 0; ks < 4; ++ks)
                ldmx4(qhf[ks], sbase + roff + ks * 32);
        }
        __syncthreads();

        float mrow[2] = {-1e30f, -1e30f};
        float lrow[2] = {0.0f, 0.0f};
        float o[8][4] = {};

        const int wmax = qi*128 + wrow0 + 15;
        const int nsteps = 2*qi + 2;

        issue(0);
        for (int kt = 0; kt < nsteps; ++kt) {
            if (kt + 1 < nsteps) { issue(kt + 1); cpa_wait<1>(); }
            else                 { cpa_wait<0>(); }
            __syncthreads();

            const uint32_t st = sbase + (kt & 1) * STAGE;
            const uint32_t sKh = st;
            const uint32_t sKl = st + 64*KST*2;
            const uint32_t sVh = st + 128*KST*2;
            const uint32_t sVl = st + 192*KST*2;

            if (kt*64 <= wmax) {
                // ---- scores: Qh*Kh + Qh*Kl (2 passes) ----
                float s[8][4] = {};
                #pragma unroll
                for (int ks = 0; ks < 4; ++ks) {
                    #pragma unroll
                    for (int ng = 0; ng < 4; ++ng) {
                        uint32_t khb[4], klb[4];
                        ldmx4(khb, sKh + kbase[ng] + ks*32);
                        ldmx4(klb, sKl + kbase[ng] + ks*32);
                        mma_f16(s[2*ng+0], qhf[ks], khb[0], khb[1]);
                        mma_f16(s[2*ng+1], qhf[ks], khb[2], khb[3]);
                        mma_f16(s[2*ng+0], qhf[ks], klb[0], klb[1]);
                        mma_f16(s[2*ng+1], qhf[ks], klb[2], klb[3]);
                    }
                }

                // ---- scale + causal mask (log2 units) ----
                const float SC = 0.125f * LOG2E;
                const int r0g = qi*128 + wrow0 + (lane >> 2);
                const bool needmask = (kt*64 + 63 > qi*128 + wrow0);
                #pragma unroll
                for (int nf = 0; nf < 8; ++nf)
                    #pragma unroll
                    for (int ri = 0; ri < 4; ++ri) {
                        float v = s[nf][ri] * SC;
                        if (needmask) {
                            int col = kt*64 + nf*8 + (lane & 3)*2 + (ri & 1);
                            int rg  = r0g + ((ri >> 1) ? 8 : 0);
                            if (col > rg) v = -1e30f;
                        }
                        s[nf][ri] = v;
                    }

                // ---- online softmax (p in (0,1], fp16-safe) ----
                float alpha[2];
                #pragma unroll
                for (int h = 0; h < 2; ++h) {
                    float t = -1e30f;
                    #pragma unroll
                    for (int nf = 0; nf < 8; ++nf)
                        t = fmaxf(t, fmaxf(s[nf][h*2], s[nf][h*2+1]));
                    t = fmaxf(t, __shfl_xor_sync(0xffffffffu, t, 1));
                    t = fmaxf(t, __shfl_xor_sync(0xffffffffu, t, 2));
                    float nm = fmaxf(mrow[h], t);
                    alpha[h] = ex2f(mrow[h] - nm);
                    mrow[h] = nm;
                }
                float rs[2] = {0.0f, 0.0f};
                #pragma unroll
                for (int nf = 0; nf < 8; ++nf)
                    #pragma unroll
                    for (int ri = 0; ri < 4; ++ri) {
                        int h = ri >> 1;
                        float p = ex2f(s[nf][ri] - mrow[h]);
                        s[nf][ri] = p;
                        rs[h] += p;
                    }
                #pragma unroll
                for (int h = 0; h < 2; ++h) {
                    rs[h] += __shfl_xor_sync(0xffffffffu, rs[h], 1);
                    rs[h] += __shfl_xor_sync(0xffffffffu, rs[h], 2);
                    lrow[h] = lrow[h] * alpha[h] + rs[h];
                }
                #pragma unroll
                for (int nf = 0; nf < 8; ++nf) {
                    o[nf][0] *= alpha[0]; o[nf][1] *= alpha[0];
                    o[nf][2] *= alpha[1]; o[nf][3] *= alpha[1];
                }

                // ---- P frags (fp16 hi) ----
                uint32_t pah[4][4];
                #pragma unroll
                for (int ks = 0; ks < 4; ++ks) {
                    pah[ks][0] = pack_f16x2(s[2*ks][0],   s[2*ks][1]);
                    pah[ks][1] = pack_f16x2(s[2*ks][2],   s[2*ks][3]);
                    pah[ks][2] = pack_f16x2(s[2*ks+1][0], s[2*ks+1][1]);
                    pah[ks][3] = pack_f16x2(s[2*ks+1][2], s[2*ks+1][3]);
                }

                // ---- P@V: Ph*Vh + Ph*Vl (2 passes) ----
                #pragma unroll
                for (int ks = 0; ks < 4; ++ks) {
                    const uint32_t vrb = vrowoff + ks*16*KST*2;
                    #pragma unroll
                    for (int ng = 0; ng < 4; ++ng) {
                        uint32_t vhb[4], vlb[4];
                        ldmx4t(vhb, sVh + vrb + vcol[ng]);
                        ldmx4t(vlb, sVl + vrb + vcol[ng]);
                        mma_f16(o[2*ng+0], pah[ks], vhb[0], vhb[1]);
                        mma_f16(o[2*ng+1], pah[ks], vhb[2], vhb[3]);
                        mma_f16(o[2*ng+0], pah[ks], vlb[0], vlb[1]);
                        mma_f16(o[2*ng+1], pah[ks], vlb[2], vlb[3]);
                    }
                }
            }
            __syncthreads();
        }

        // ---- epilogue: write ctx hi (fp16, row-major [M][D]) ----
        const float inv0 = 1.0f / lrow[0];
        const float inv1 = 1.0f / lrow[1];
        const int b = bh >> 4, h = bh & 15;
        const int r0 = qi*128 + wrow0 + (lane >> 2);
        #pragma unroll
        for (int nf = 0; nf < 8; ++nf) {
            const int col = h*HD + nf*8 + (lane & 3)*2;
            const size_t off0 = ((size_t)b*SS + r0)*DD + col;
            const size_t off1 = ((size_t)b*SS + r0 + 8)*DD + col;
            *(uint32_t*)(Chi + off0) = pack_f16x2(o[nf][0]*inv0, o[nf][1]*inv0);
            *(uint32_t*)(Chi + off1) = pack_f16x2(o[nf][2]*inv1, o[nf][3]*inv1);
        }
    }
}

// ---------------------------------------------------------------------------

extern "C" void kernel_launch(void* const* d_in, const int* in_sizes, int n_in,
                              void* d_out, int out_size)
{
    const float* x  = (const float*)d_in[0];
    const float* Wq = (const float*)d_in[1];
    const float* Wk = (const float*)d_in[2];
    const float* Wv = (const float*)d_in[3];
    const float* Wo = (const float*)d_in[4];
    const float* bo = (const float*)d_in[5];
    float* out = (float*)d_out;

    __half *ahi, *wthi, *wtlo, *qh, *kh, *kl, *vh, *vl;
    cudaGetSymbolAddress((void**)&ahi,  g_ahi);
    cudaGetSymbolAddress((void**)&wthi, g_wthi);
    cudaGetSymbolAddress((void**)&wtlo, g_wtlo);
    cudaGetSymbolAddress((void**)&qh,   g_qh);
    cudaGetSymbolAddress((void**)&kh,   g_kh);
    cudaGetSymbolAddress((void**)&kl,   g_kl);
    cudaGetSymbolAddress((void**)&vh,   g_vh);
    cudaGetSymbolAddress((void**)&vl,   g_vl);

    cudaFuncSetAttribute(attn_mma, cudaFuncAttributeMaxDynamicSharedMemorySize, ATTN_SMEM);
    cudaFuncSetAttribute(mma_gemm_qkv, cudaFuncAttributeMaxDynamicSharedMemorySize, GEMM_SMEM);
    cudaFuncSetAttribute(mma_gemm_out, cudaFuncAttributeMaxDynamicSharedMemorySize, GEMM_SMEM);

    // 1. convert X to fp16 (hi only — residual pass dropped)
    split_kernel<<<1024, 256>>>((const float4*)x, ahi, MM*DD/4);

    // 2. transpose+split all 4 weights (one launch)
    transpose_split_kernel<<<dim3(32,32,4), dim3(32,8)>>>(Wq, Wk, Wv, Wo, wthi, wtlo);

    // 3. fused Q/K/V projections (fp16 2-pass; Q hi-only output)
    mma_gemm_qkv<<<dim3(24, 32), 256, GEMM_SMEM>>>(ahi, wthi, wtlo, qh, kh, kl, vh, vl);

    // 4. attention (fp16 2-pass QK and PV, online softmax, balanced pairs)
    attn_mma<<<dim3(8, BB*HH), 256, ATTN_SMEM>>>(qh, kh, kl, vh, vl, ahi);

    // 5. output projection + bias (2-pass, ctx hi-only)
    mma_gemm_out<<<dim3(8, 32), 256, GEMM_SMEM>>>(ahi, wthi + 3*(size_t)DD*DD, wtlo + 3*(size_t)DD*DD, out, bo);
}

// round 16
// speedup vs baseline: 6.4822x; 1.1774x over previous
#include <cuda_runtime.h>
#include <cuda_fp16.h>
#include <cstdint>

#define BB 2
#define SS 2048
#define DD 1024
#define HH 16
#define HD 64
#define MM (BB*SS)     // 4096

// ---------------- device scratch (no allocation allowed) -------------------
__device__ __half g_ahi[MM*DD];
__device__ __half g_wthi[4][DD*DD];
__device__ __half g_wtlo[4][DD*DD];
__device__ __half g_qh[BB*HH*SS*HD];
__device__ __half g_kh[BB*HH*SS*HD];
__device__ __half g_vh[BB*HH*SS*HD];

// ---------------- prepass: fp32 -> fp16 convert (hi only) -------------------
__global__ __launch_bounds__(256)
void split_kernel(const float4* __restrict__ X, __half* __restrict__ Hi, int n4)
{
    union U { __half b[4]; uint64_t u; };
    for (int i = blockIdx.x * blockDim.x + threadIdx.x; i < n4;
         i += gridDim.x * blockDim.x) {
        float4 f = X[i];
        U h;
        h.b[0] = __float2half(f.x);
        h.b[1] = __float2half(f.y);
        h.b[2] = __float2half(f.z);
        h.b[3] = __float2half(f.w);
        ((uint64_t*)Hi)[i] = h.u;
    }
}

// ---------------- prepass: 4x W[k][n] -> Wt[n][k] fp16 hi/lo split -----------
__global__ __launch_bounds__(256)
void transpose_split_kernel(const float* __restrict__ W0, const float* __restrict__ W1,
                            const float* __restrict__ W2, const float* __restrict__ W3,
                            __half* __restrict__ Th, __half* __restrict__ Tl)
{
    __shared__ float tile[32][33];
    const float* Ws[4] = {W0, W1, W2, W3};
    const float* W = Ws[blockIdx.z];
    __half* th = Th + (size_t)blockIdx.z * DD * DD;
    __half* tl = Tl + (size_t)blockIdx.z * DD * DD;
    int tx = threadIdx.x, ty = threadIdx.y;
    int x = blockIdx.x * 32 + tx;
    #pragma unroll
    for (int i = 0; i < 4; ++i) {
        int y = blockIdx.y * 32 + ty + i * 8;
        tile[ty + i * 8][tx] = W[(size_t)y * DD + x];
    }
    __syncthreads();
    int xo = blockIdx.y * 32 + tx;
    #pragma unroll
    for (int i = 0; i < 4; ++i) {
        int yo = blockIdx.x * 32 + ty + i * 8;
        float v = tile[tx][ty + i * 8];
        __half hb = __float2half(v);
        th[(size_t)yo * DD + xo] = hb;
        tl[(size_t)yo * DD + xo] = __float2half(v - __half2float(hb));
    }
}

// ---------------- mma.sync / cp.async helpers --------------------------------
__device__ __forceinline__ uint32_t smem_u32(const void* p) {
    uint32_t a;
    asm("{ .reg .u64 t; cvta.to.shared.u64 t, %1; cvt.u32.u64 %0, t; }"
        : "=r"(a) : "l"(p));
    return a;
}
__device__ __forceinline__ void ldmx4(uint32_t* r, uint32_t addr) {
    asm volatile("ldmatrix.sync.aligned.m8n8.x4.shared.b16 {%0,%1,%2,%3}, [%4];"
                 : "=r"(r[0]), "=r"(r[1]), "=r"(r[2]), "=r"(r[3]) : "r"(addr));
}
__device__ __forceinline__ void ldmx4t(uint32_t* r, uint32_t addr) {
    asm volatile("ldmatrix.sync.aligned.m8n8.x4.trans.shared.b16 {%0,%1,%2,%3}, [%4];"
                 : "=r"(r[0]), "=r"(r[1]), "=r"(r[2]), "=r"(r[3]) : "r"(addr));
}
__device__ __forceinline__ void mma_f16(float* c, const uint32_t* a,
                                        uint32_t b0, uint32_t b1) {
    asm volatile(
        "mma.sync.aligned.m16n8k16.row.col.f32.f16.f16.f32 "
        "{%0,%1,%2,%3}, {%4,%5,%6,%7}, {%8,%9}, {%0,%1,%2,%3};"
        : "+f"(c[0]), "+f"(c[1]), "+f"(c[2]), "+f"(c[3])
        : "r"(a[0]), "r"(a[1]), "r"(a[2]), "r"(a[3]), "r"(b0), "r"(b1));
}
__device__ __forceinline__ float ex2f(float x) {
    float y; asm("ex2.approx.f32 %0, %1;" : "=f"(y) : "f"(x)); return y;
}
__device__ __forceinline__ uint32_t pack2(__half a, __half b) {
    __half2 t = __halves2half2(a, b);
    return *(uint32_t*)&t;
}
__device__ __forceinline__ uint32_t pack_f16x2(float a, float b) {
    __half2 t = __floats2half2_rn(a, b);
    return *(uint32_t*)&t;
}
__device__ __forceinline__ void cpa16(uint32_t dst, const void* src) {
    asm volatile("cp.async.cg.shared.global [%0], [%1], 16;" :: "r"(dst), "l"(src));
}
__device__ __forceinline__ void cpa_commit() {
    asm volatile("cp.async.commit_group;" ::: "memory");
}
template<int N> __device__ __forceinline__ void cpa_wait() {
    asm volatile("cp.async.wait_group %0;" :: "n"(N) : "memory");
}

// ---------------- HMMA GEMM core (swizzled 64B rows, 3-stage, 2-pass) --------
// 2 passes: Ahi*Bhi + Ahi*Blo. Operands staged: Ahi | Bhi | Blo.
#define GCH 32
#define GOP 8192                     // 128 rows * 64 B
#define GSTG (3*GOP)                 // 24576 B per stage
#define GEMM_SMEM (3*GSTG)           // 73728 B

__device__ __forceinline__ uint32_t sw64(uint32_t off) {
    return off ^ (((off >> 7) & 3u) << 4);
}

template<typename EPI>
__device__ __forceinline__ void gemm_core(
    const __half* Ahi, const __half* Bhi, const __half* Blo,
    int m0, int n0, EPI epi)
{
    extern __shared__ __align__(16) char gsm[];
    const uint32_t base = smem_u32(gsm);

    const int tid  = threadIdx.x;
    const int wid  = tid >> 5;
    const int lane = tid & 31;
    const int wm0 = (wid & 3) * 32;
    const int wn0 = (wid >> 2) * 64;

    const uint4* srcs[3] = {(const uint4*)Ahi, (const uint4*)Bhi, (const uint4*)Blo};

    int cmat[6], crow[6], cc4[6];
    uint32_t cdst[6];
    #pragma unroll
    for (int i = 0; i < 6; ++i) {
        int idx = tid + i * 256;
        cmat[i] = idx >> 9;
        int w = idx & 511;
        crow[i] = w >> 2;
        cc4[i]  = w & 3;
        cdst[i] = base + cmat[i]*GOP + sw64(crow[i]*64 + cc4[i]*16);
    }

    auto issue = [&](int t) {
        const uint32_t so = (t % 3) * GSTG;
        #pragma unroll
        for (int i = 0; i < 6; ++i) {
            const int r0 = (cmat[i] == 0) ? m0 : n0;
            cpa16(cdst[i] + so, srcs[cmat[i]] + (size_t)(r0 + crow[i])*128 + t*4 + cc4[i]);
        }
        cpa_commit();
    };

    uint32_t aoffb[2], axor[2], boffb[4], bxor[4];
    #pragma unroll
    for (int mf = 0; mf < 2; ++mf) {
        int row = wm0 + mf*16 + (lane & 15);
        aoffb[mf] = row*64 + (lane >> 4)*16;
        axor[mf]  = ((row >> 1) & 3u) << 4;
    }
    #pragma unroll
    for (int np = 0; np < 4; ++np) {
        int row = wn0 + np*16 + ((lane >> 4) & 1)*8 + (lane & 7);
        boffb[np] = row*64 + ((lane >> 3) & 1)*16;
        bxor[np]  = ((row >> 1) & 3u) << 4;
    }

    float acc[2][8][4] = {};

    auto compute = [&](int stg) {
        const uint32_t sb = base + stg * GSTG;
        #pragma unroll
        for (int ks2 = 0; ks2 < 64; ks2 += 32) {
            uint32_t afh[2][4], bfh[4][4], bfl[4][4];
            #pragma unroll
            for (int mf = 0; mf < 2; ++mf) {
                uint32_t o = (aoffb[mf] + ks2) ^ axor[mf];
                ldmx4(afh[mf], sb + o);
            }
            #pragma unroll
            for (int np = 0; np < 4; ++np) {
                uint32_t o = (boffb[np] + ks2) ^ bxor[np];
                ldmx4(bfh[np], sb + 1*GOP + o);
                ldmx4(bfl[np], sb + 2*GOP + o);
            }
            #pragma unroll
            for (int mf = 0; mf < 2; ++mf)
                #pragma unroll
                for (int np = 0; np < 4; ++np) {
                    mma_f16(acc[mf][np*2+0], afh[mf], bfh[np][0], bfh[np][1]);
                    mma_f16(acc[mf][np*2+1], afh[mf], bfh[np][2], bfh[np][3]);
                    mma_f16(acc[mf][np*2+0], afh[mf], bfl[np][0], bfl[np][1]);
                    mma_f16(acc[mf][np*2+1], afh[mf], bfl[np][2], bfl[np][3]);
                }
        }
    };

    issue(0); issue(1);
    for (int t = 0; t < GCH; ++t) {
        if (t + 1 < GCH) cpa_wait<1>(); else cpa_wait<0>();
        __syncthreads();
        if (t + 2 < GCH) issue(t + 2);
        compute(t % 3);
    }

    const int qrow = lane >> 2;
    const int qcol = (lane & 3) * 2;
    #pragma unroll
    for (int mf = 0; mf < 2; ++mf)
        #pragma unroll
        for (int nf = 0; nf < 8; ++nf)
            #pragma unroll
            for (int half = 0; half < 2; ++half) {
                const int m = m0 + wm0 + mf*16 + qrow + half*8;
                const int n = n0 + wn0 + nf*8 + qcol;
                epi(m, n, acc[mf][nf][half*2 + 0], acc[mf][nf][half*2 + 1]);
            }
}

// fused QKV projection (2-pass): all outputs hi-only
__global__ __launch_bounds__(256, 2)
void mma_gemm_qkv(const __half* __restrict__ Ahi,
                  const __half* __restrict__ Whi, const __half* __restrict__ Wlo,
                  __half* __restrict__ qh, __half* __restrict__ kh,
                  __half* __restrict__ vh)
{
    const int g  = blockIdx.x >> 3;
    const int n0 = (blockIdx.x & 7) * 128;
    const int m0 = blockIdx.y * 128;
    const __half* Bhi = Whi + (size_t)g * DD * DD;
    const __half* Blo = Wlo + (size_t)g * DD * DD;
    __half* Yh = (g == 0) ? qh : (g == 1) ? kh : vh;

    gemm_core(Ahi, Bhi, Blo, m0, n0,
        [&](int m, int n, float cx, float cy) {
            const int b = m >> 11, s = m & (SS - 1);
            const int h = n >> 6, hd = n & 63;
            const size_t off = (((size_t)b*HH + h)*SS + s)*HD + hd;
            *(uint32_t*)(Yh + off) = pack_f16x2(cx, cy);
        });
}

// output projection + bias (2-pass: ctx is hi-only)
__global__ __launch_bounds__(256, 2)
void mma_gemm_out(const __half* __restrict__ Ahi,
                  const __half* __restrict__ Bhi, const __half* __restrict__ Blo,
                  float* __restrict__ Yf, const float* __restrict__ bias)
{
    const int n0 = blockIdx.x * 128;
    const int m0 = blockIdx.y * 128;
    gemm_core(Ahi, Bhi, Blo, m0, n0,
        [&](int m, int n, float cx, float cy) {
            float2* dst = (float2*)(Yf + (size_t)m * DD + n);
            *dst = make_float2(cx + bias[n], cy + bias[n + 1]);
        });
}

// ---------------- HMMA flash attention (fp16 hi-only, online softmax) --------
#define KST 72
#define STAGE (2*64*KST*2)           // 18432 B (Kh | Vh)
#define ATTN_SMEM (2*STAGE)          // 36864 B
#define LOG2E 1.4426950408889634f

__global__ __launch_bounds__(256, 2)
void attn_mma(const __half* __restrict__ Qh,
              const __half* __restrict__ Kh, const __half* __restrict__ Vh,
              __half* __restrict__ Chi)
{
    extern __shared__ __align__(16) char dynsm[];
    __half* sm = (__half*)dynsm;

    const int bh  = blockIdx.y;
    const int tid = threadIdx.x;
    const int wid = tid >> 5;
    const int lane = tid & 31;
    const int wrow0 = wid * 16;

    const size_t hbase = (size_t)bh * SS * HD;
    const uint4* Kh4 = (const uint4*)(Kh + hbase);
    const uint4* Vh4 = (const uint4*)(Vh + hbase);

    const uint32_t sbase = smem_u32(sm);

    uint32_t kbase[4];
    #pragma unroll
    for (int ng = 0; ng < 4; ++ng) {
        int krow = ng*16 + ((lane >> 4) & 1)*8 + (lane & 7);
        kbase[ng] = (krow * KST + ((lane >> 3) & 1) * 8) * 2;
    }
    const uint32_t vrowoff = ((((lane >> 3) & 1)*8 + (lane & 7)) * KST) * 2;
    uint32_t vcol[4];
    #pragma unroll
    for (int ng = 0; ng < 4; ++ng)
        vcol[ng] = (ng*16 + (lane >> 4) * 8) * 2;

    // per-thread cp.async slots: 1024 uint4 per step, 4 per thread
    uint32_t cpa_dst[4];
    int cpa_src[4];
    #pragma unroll
    for (int i = 0; i < 4; ++i) {
        int idx = tid + i * 256;
        int tile = idx >> 9;             // 0 = Kh, 1 = Vh
        int within = idx & 511;
        int row = within >> 3, c = within & 7;
        cpa_dst[i] = sbase + ((tile*64 + row)*KST + c*8) * 2;
        cpa_src[i] = within;
    }

    auto issue = [&](int kt) {
        const uint4* srcs[2] = {Kh4 + kt*512, Vh4 + kt*512};
        const uint32_t soff = (kt & 1) * STAGE;
        #pragma unroll
        for (int i = 0; i < 4; ++i) {
            int tile = (tid + i*256) >> 9;
            cpa16(cpa_dst[i] + soff, srcs[tile] + cpa_src[i]);
        }
        cpa_commit();
    };

    #pragma unroll 1
    for (int half = 0; half < 2; ++half) {
        const int qi = half ? (15 - blockIdx.x) : blockIdx.x;

        __syncthreads();
        // ---- stage Qh (128x64 fp16) into stage-0 smem ----
        {
            const uint4* Qh4 = (const uint4*)(Qh + hbase + (size_t)qi*128*HD);
            #pragma unroll
            for (int i = 0; i < 4; ++i) {
                int idx = tid + i * 256;
                int row = idx >> 3, c = idx & 7;
                uint4 v = Qh4[idx];
                *(uint4*)&sm[row*KST + c*8] = v;
            }
        }
        __syncthreads();

        uint32_t qhf[4][4];
        {
            const uint32_t roff = ((wrow0 + (lane & 15)) * KST + (lane >> 4) * 8) * 2;
            #pragma unroll
            for (int ks = 0; ks < 4; ++ks)
                ldmx4(qhf[ks], sbase + roff + ks * 32);
        }
        __syncthreads();

        float mrow[2] = {-1e30f, -1e30f};
        float lrow[2] = {0.0f, 0.0f};
        float o[8][4] = {};

        const int wmax = qi*128 + wrow0 + 15;
        const int nsteps = 2*qi + 2;

        issue(0);
        for (int kt = 0; kt < nsteps; ++kt) {
            if (kt + 1 < nsteps) { issue(kt + 1); cpa_wait<1>(); }
            else                 { cpa_wait<0>(); }
            __syncthreads();

            const uint32_t st = sbase + (kt & 1) * STAGE;
            const uint32_t sKh = st;
            const uint32_t sVh = st + 64*KST*2;

            if (kt*64 <= wmax) {
                // ---- scores: Qh*Kh (1 pass) ----
                float s[8][4] = {};
                #pragma unroll
                for (int ks = 0; ks < 4; ++ks) {
                    #pragma unroll
                    for (int ng = 0; ng < 4; ++ng) {
                        uint32_t khb[4];
                        ldmx4(khb, sKh + kbase[ng] + ks*32);
                        mma_f16(s[2*ng+0], qhf[ks], khb[0], khb[1]);
                        mma_f16(s[2*ng+1], qhf[ks], khb[2], khb[3]);
                    }
                }

                // ---- scale + causal mask (log2 units) ----
                const float SC = 0.125f * LOG2E;
                const int r0g = qi*128 + wrow0 + (lane >> 2);
                const bool needmask = (kt*64 + 63 > qi*128 + wrow0);
                #pragma unroll
                for (int nf = 0; nf < 8; ++nf)
                    #pragma unroll
                    for (int ri = 0; ri < 4; ++ri) {
                        float v = s[nf][ri] * SC;
                        if (needmask) {
                            int col = kt*64 + nf*8 + (lane & 3)*2 + (ri & 1);
                            int rg  = r0g + ((ri >> 1) ? 8 : 0);
                            if (col > rg) v = -1e30f;
                        }
                        s[nf][ri] = v;
                    }

                // ---- online softmax (p in (0,1], fp16-safe) ----
                float alpha[2];
                #pragma unroll
                for (int h = 0; h < 2; ++h) {
                    float t = -1e30f;
                    #pragma unroll
                    for (int nf = 0; nf < 8; ++nf)
                        t = fmaxf(t, fmaxf(s[nf][h*2], s[nf][h*2+1]));
                    t = fmaxf(t, __shfl_xor_sync(0xffffffffu, t, 1));
                    t = fmaxf(t, __shfl_xor_sync(0xffffffffu, t, 2));
                    float nm = fmaxf(mrow[h], t);
                    alpha[h] = ex2f(mrow[h] - nm);
                    mrow[h] = nm;
                }
                float rs[2] = {0.0f, 0.0f};
                #pragma unroll
                for (int nf = 0; nf < 8; ++nf)
                    #pragma unroll
                    for (int ri = 0; ri < 4; ++ri) {
                        int h = ri >> 1;
                        float p = ex2f(s[nf][ri] - mrow[h]);
                        s[nf][ri] = p;
                        rs[h] += p;
                    }
                #pragma unroll
                for (int h = 0; h < 2; ++h) {
                    rs[h] += __shfl_xor_sync(0xffffffffu, rs[h], 1);
                    rs[h] += __shfl_xor_sync(0xffffffffu, rs[h], 2);
                    lrow[h] = lrow[h] * alpha[h] + rs[h];
                }
                #pragma unroll
                for (int nf = 0; nf < 8; ++nf) {
                    o[nf][0] *= alpha[0]; o[nf][1] *= alpha[0];
                    o[nf][2] *= alpha[1]; o[nf][3] *= alpha[1];
                }

                // ---- P frags (fp16) ----
                uint32_t pah[4][4];
                #pragma unroll
                for (int ks = 0; ks < 4; ++ks) {
                    pah[ks][0] = pack_f16x2(s[2*ks][0],   s[2*ks][1]);
                    pah[ks][1] = pack_f16x2(s[2*ks][2],   s[2*ks][3]);
                    pah[ks][2] = pack_f16x2(s[2*ks+1][0], s[2*ks+1][1]);
                    pah[ks][3] = pack_f16x2(s[2*ks+1][2], s[2*ks+1][3]);
                }

                // ---- P@V: Ph*Vh (1 pass) ----
                #pragma unroll
                for (int ks = 0; ks < 4; ++ks) {
                    const uint32_t vrb = vrowoff + ks*16*KST*2;
                    #pragma unroll
                    for (int ng = 0; ng < 4; ++ng) {
                        uint32_t vhb[4];
                        ldmx4t(vhb, sVh + vrb + vcol[ng]);
                        mma_f16(o[2*ng+0], pah[ks], vhb[0], vhb[1]);
                        mma_f16(o[2*ng+1], pah[ks], vhb[2], vhb[3]);
                    }
                }
            }
            __syncthreads();
        }

        // ---- epilogue: write ctx hi (fp16, row-major [M][D]) ----
        const float inv0 = 1.0f / lrow[0];
        const float inv1 = 1.0f / lrow[1];
        const int b = bh >> 4, h = bh & 15;
        const int r0 = qi*128 + wrow0 + (lane >> 2);
        #pragma unroll
        for (int nf = 0; nf < 8; ++nf) {
            const int col = h*HD + nf*8 + (lane & 3)*2;
            const size_t off0 = ((size_t)b*SS + r0)*DD + col;
            const size_t off1 = ((size_t)b*SS + r0 + 8)*DD + col;
            *(uint32_t*)(Chi + off0) = pack_f16x2(o[nf][0]*inv0, o[nf][1]*inv0);
            *(uint32_t*)(Chi + off1) = pack_f16x2(o[nf][2]*inv1, o[nf][3]*inv1);
        }
    }
}

// ---------------------------------------------------------------------------

extern "C" void kernel_launch(void* const* d_in, const int* in_sizes, int n_in,
                              void* d_out, int out_size)
{
    const float* x  = (const float*)d_in[0];
    const float* Wq = (const float*)d_in[1];
    const float* Wk = (const float*)d_in[2];
    const float* Wv = (const float*)d_in[3];
    const float* Wo = (const float*)d_in[4];
    const float* bo = (const float*)d_in[5];
    float* out = (float*)d_out;

    __half *ahi, *wthi, *wtlo, *qh, *kh, *vh;
    cudaGetSymbolAddress((void**)&ahi,  g_ahi);
    cudaGetSymbolAddress((void**)&wthi, g_wthi);
    cudaGetSymbolAddress((void**)&wtlo, g_wtlo);
    cudaGetSymbolAddress((void**)&qh,   g_qh);
    cudaGetSymbolAddress((void**)&kh,   g_kh);
    cudaGetSymbolAddress((void**)&vh,   g_vh);

    cudaFuncSetAttribute(attn_mma, cudaFuncAttributeMaxDynamicSharedMemorySize, ATTN_SMEM);
    cudaFuncSetAttribute(mma_gemm_qkv, cudaFuncAttributeMaxDynamicSharedMemorySize, GEMM_SMEM);
    cudaFuncSetAttribute(mma_gemm_out, cudaFuncAttributeMaxDynamicSharedMemorySize, GEMM_SMEM);

    // 1. convert X to fp16
    split_kernel<<<1024, 256>>>((const float4*)x, ahi, MM*DD/4);

    // 2. transpose+split all 4 weights (one launch)
    transpose_split_kernel<<<dim3(32,32,4), dim3(32,8)>>>(Wq, Wk, Wv, Wo, wthi, wtlo);

    // 3. fused Q/K/V projections (fp16 2-pass; hi-only outputs)
    mma_gemm_qkv<<<dim3(24, 32), 256, GEMM_SMEM>>>(ahi, wthi, wtlo, qh, kh, vh);

    // 4. attention (fp16 1-pass QK and PV, online softmax, balanced pairs)
    attn_mma<<<dim3(8, BB*HH), 256, ATTN_SMEM>>>(qh, kh, vh, ahi);

    // 5. output projection + bias (2-pass, ctx hi-only)
    mma_gemm_out<<<dim3(8, 32), 256, GEMM_SMEM>>>(ahi, wthi + 3*(size_t)DD*DD, wtlo + 3*(size_t)DD*DD, out, bo);
}